// round 1
// baseline (speedup 1.0000x reference)
#include <cuda_runtime.h>

// Problem constants (fixed by the dataset)
#define T_DIM   2048
#define B_DIM   4
#define E_DIM   1024
#define H_DIM   16
#define D_HEAD  64
#define MROWS   (T_DIM * B_DIM)      // 8192 rows of the [T*B, E] activations

// Scratch (no cudaMalloc allowed): q, k, v projections and attention output
__device__ float g_q[MROWS * E_DIM];
__device__ float g_k[MROWS * E_DIM];
__device__ float g_v[MROWS * E_DIM];
__device__ float g_attn[MROWS * E_DIM];

// ---------------------------------------------------------------------------
// GEMM: C[m,n] = (sum_k A[m,k] * W[n,k] + bias[n]) * scale
//   A: [M,K] row-major, W: [N,K] row-major (i.e. torch Linear weight, x @ W^T)
// Tile: 128x128, BK=8, 256 threads, 8x8 per-thread microtile.
// ---------------------------------------------------------------------------
__global__ __launch_bounds__(256) void sgemm_bias_kernel(
    const float* __restrict__ A, const float* __restrict__ W,
    const float* __restrict__ bias, float* __restrict__ C,
    int M, int N, int K, float scale)
{
    __shared__ float As[8][128];
    __shared__ float Bs[8][128];

    const int tid = threadIdx.x;
    const int m0 = blockIdx.y * 128;
    const int n0 = blockIdx.x * 128;
    const int ty = tid >> 4;        // 0..15
    const int tx = tid & 15;        // 0..15

    // load mapping: each thread fetches one float4 of A and one of W per BK step
    const int lr = tid >> 1;        // 0..127 (row within tile)
    const int lc = (tid & 1) * 4;   // 0 or 4 (k within tile)
    const float* Ag = A + (m0 + lr) * K + lc;
    const float* Wg = W + (n0 + lr) * K + lc;

    float acc[8][8];
#pragma unroll
    for (int i = 0; i < 8; i++)
#pragma unroll
        for (int j = 0; j < 8; j++) acc[i][j] = 0.0f;

    for (int k0 = 0; k0 < K; k0 += 8) {
        float4 av = *(const float4*)(Ag + k0);
        float4 wv = *(const float4*)(Wg + k0);
        As[lc + 0][lr] = av.x; As[lc + 1][lr] = av.y;
        As[lc + 2][lr] = av.z; As[lc + 3][lr] = av.w;
        Bs[lc + 0][lr] = wv.x; Bs[lc + 1][lr] = wv.y;
        Bs[lc + 2][lr] = wv.z; Bs[lc + 3][lr] = wv.w;
        __syncthreads();

#pragma unroll
        for (int kk = 0; kk < 8; kk++) {
            float ra[8], rb[8];
            *(float4*)(ra)     = *(const float4*)&As[kk][ty * 8];
            *(float4*)(ra + 4) = *(const float4*)&As[kk][ty * 8 + 4];
            *(float4*)(rb)     = *(const float4*)&Bs[kk][tx * 8];
            *(float4*)(rb + 4) = *(const float4*)&Bs[kk][tx * 8 + 4];
#pragma unroll
            for (int i = 0; i < 8; i++)
#pragma unroll
                for (int j = 0; j < 8; j++)
                    acc[i][j] = fmaf(ra[i], rb[j], acc[i][j]);
        }
        __syncthreads();
    }

#pragma unroll
    for (int i = 0; i < 8; i++) {
        int m = m0 + ty * 8 + i;
#pragma unroll
        for (int j = 0; j < 8; j++) {
            int n = n0 + tx * 8 + j;
            C[m * N + n] = (acc[i][j] + bias[n]) * scale;
        }
    }
}

// ---------------------------------------------------------------------------
// Flash attention (fp32, causal), one block = (head n = b*H+h, q-tile of 64)
// 256 threads: tid = qg*16 + sg ; thread owns 4 q-rows (qg*4..) and
//   S-phase: 4 s-cols (sg*4..) ;  O-phase: 4 d-cols (sg*4..)
// smem tiles [64][65] (PAD=65 to break bank conflicts on strided row reads)
// ---------------------------------------------------------------------------
#define BQ  64
#define BS  64
#define PAD 65

__global__ __launch_bounds__(256) void flash_attn_kernel(
    const float* __restrict__ Q, const float* __restrict__ Kb,
    const float* __restrict__ Vb, float* __restrict__ Ob)
{
    extern __shared__ float sm[];
    float* Qs = sm;                   // [BQ][PAD]
    float* Ks = Qs + BQ * PAD;        // [BS][PAD]
    float* Vs = Ks + BS * PAD;        // [BS][PAD]
    float* Ps = Vs + BS * PAD;        // [BQ][PAD]

    const int tid = threadIdx.x;
    const int qg = tid >> 4;          // 0..15
    const int sg = tid & 15;          // 0..15
    const int qtile = blockIdx.x;
    const int n = blockIdx.y;         // b*H + h
    const int b = n / H_DIM;
    const int h = n % H_DIM;
    const int t0 = qtile * BQ;

    // ---- load Q tile (coalesced float4 from gmem, scalar stores to padded smem)
    {
        const int r = tid >> 2;                  // 0..63
        const int c0 = (tid & 3) * 16;           // 0,16,32,48
        const float* src = Q + ((t0 + r) * B_DIM + b) * E_DIM + h * D_HEAD + c0;
        float* dst = &Qs[r * PAD + c0];
#pragma unroll
        for (int u = 0; u < 4; u++) {
            float4 v = *(const float4*)(src + u * 4);
            dst[u * 4 + 0] = v.x; dst[u * 4 + 1] = v.y;
            dst[u * 4 + 2] = v.z; dst[u * 4 + 3] = v.w;
        }
    }

    float m_i[4], l_i[4], o[4][4];
#pragma unroll
    for (int i = 0; i < 4; i++) {
        m_i[i] = -1e30f; l_i[i] = 0.0f;
#pragma unroll
        for (int j = 0; j < 4; j++) o[i][j] = 0.0f;
    }

    const int ntiles = qtile + 1;     // causal: s-tiles 0..qtile
    for (int st = 0; st < ntiles; st++) {
        const int s0 = st * BS;

        // ---- load K, V tiles
        {
            const int r = tid >> 2;
            const int c0 = (tid & 3) * 16;
            const float* ksrc = Kb + ((s0 + r) * B_DIM + b) * E_DIM + h * D_HEAD + c0;
            const float* vsrc = Vb + ((s0 + r) * B_DIM + b) * E_DIM + h * D_HEAD + c0;
            float* kdst = &Ks[r * PAD + c0];
            float* vdst = &Vs[r * PAD + c0];
#pragma unroll
            for (int u = 0; u < 4; u++) {
                float4 kv = *(const float4*)(ksrc + u * 4);
                float4 vv = *(const float4*)(vsrc + u * 4);
                kdst[u * 4 + 0] = kv.x; kdst[u * 4 + 1] = kv.y;
                kdst[u * 4 + 2] = kv.z; kdst[u * 4 + 3] = kv.w;
                vdst[u * 4 + 0] = vv.x; vdst[u * 4 + 1] = vv.y;
                vdst[u * 4 + 2] = vv.z; vdst[u * 4 + 3] = vv.w;
            }
        }
        __syncthreads();

        // ---- S = Q K^T (4x4 per thread), q already carries the 1/sqrt(D) scale
        float sacc[4][4];
#pragma unroll
        for (int i = 0; i < 4; i++)
#pragma unroll
            for (int j = 0; j < 4; j++) sacc[i][j] = 0.0f;

        for (int d = 0; d < D_HEAD; d++) {
            float qv[4], kv[4];
#pragma unroll
            for (int i = 0; i < 4; i++) qv[i] = Qs[(qg * 4 + i) * PAD + d];
#pragma unroll
            for (int j = 0; j < 4; j++) kv[j] = Ks[(sg * 4 + j) * PAD + d];
#pragma unroll
            for (int i = 0; i < 4; i++)
#pragma unroll
                for (int j = 0; j < 4; j++)
                    sacc[i][j] = fmaf(qv[i], kv[j], sacc[i][j]);
        }

        // ---- additive causal mask (only the diagonal tile has masked entries)
        if (st == qtile) {
#pragma unroll
            for (int i = 0; i < 4; i++) {
                int t = t0 + qg * 4 + i;
#pragma unroll
                for (int j = 0; j < 4; j++) {
                    int s = s0 + sg * 4 + j;
                    if (s > t) sacc[i][j] += -1e9f;
                }
            }
        }

        // ---- online softmax (row reductions across the 16 sg-lanes)
        float alpha[4];
#pragma unroll
        for (int i = 0; i < 4; i++) {
            float rmax = sacc[i][0];
#pragma unroll
            for (int j = 1; j < 4; j++) rmax = fmaxf(rmax, sacc[i][j]);
#pragma unroll
            for (int off = 1; off < 16; off <<= 1)
                rmax = fmaxf(rmax, __shfl_xor_sync(0xffffffffu, rmax, off));
            float mnew = fmaxf(m_i[i], rmax);
            float rsum = 0.0f;
#pragma unroll
            for (int j = 0; j < 4; j++) {
                float p = __expf(sacc[i][j] - mnew);
                sacc[i][j] = p;
                rsum += p;
            }
#pragma unroll
            for (int off = 1; off < 16; off <<= 1)
                rsum += __shfl_xor_sync(0xffffffffu, rsum, off);
            alpha[i] = __expf(m_i[i] - mnew);
            l_i[i] = l_i[i] * alpha[i] + rsum;
            m_i[i] = mnew;
        }

        // ---- stage P, rescale running O
#pragma unroll
        for (int i = 0; i < 4; i++) {
#pragma unroll
            for (int j = 0; j < 4; j++)
                Ps[(qg * 4 + i) * PAD + sg * 4 + j] = sacc[i][j];
#pragma unroll
            for (int j = 0; j < 4; j++) o[i][j] *= alpha[i];
        }
        __syncthreads();

        // ---- O += P V (thread owns rows qg*4.., d-cols sg*4..)
        for (int s = 0; s < BS; s++) {
            float pv[4], vv[4];
#pragma unroll
            for (int i = 0; i < 4; i++) pv[i] = Ps[(qg * 4 + i) * PAD + s];
#pragma unroll
            for (int j = 0; j < 4; j++) vv[j] = Vs[s * PAD + sg * 4 + j];
#pragma unroll
            for (int i = 0; i < 4; i++)
#pragma unroll
                for (int j = 0; j < 4; j++)
                    o[i][j] = fmaf(pv[i], vv[j], o[i][j]);
        }
        __syncthreads();
    }

    // ---- normalize and write out
#pragma unroll
    for (int i = 0; i < 4; i++) {
        float inv = 1.0f / l_i[i];
        int t = t0 + qg * 4 + i;
        float* dst = Ob + (t * B_DIM + b) * E_DIM + h * D_HEAD + sg * 4;
#pragma unroll
        for (int j = 0; j < 4; j++) dst[j] = o[i][j] * inv;
    }
}

// ---------------------------------------------------------------------------
extern "C" void kernel_launch(void* const* d_in, const int* in_sizes, int n_in,
                              void* d_out, int out_size)
{
    const float* query = (const float*)d_in[0];
    const float* key   = (const float*)d_in[1];
    const float* value = (const float*)d_in[2];
    // d_in[3] = attn_mask (pure causal; applied analytically in the kernel)
    const float* wq = (const float*)d_in[4];
    const float* bq = (const float*)d_in[5];
    const float* wk = (const float*)d_in[6];
    const float* bk = (const float*)d_in[7];
    const float* wv = (const float*)d_in[8];
    const float* bv = (const float*)d_in[9];
    const float* wo = (const float*)d_in[10];
    const float* bo = (const float*)d_in[11];
    float* out = (float*)d_out;

    float *qp, *kp, *vp, *ap;
    cudaGetSymbolAddress((void**)&qp, g_q);
    cudaGetSymbolAddress((void**)&kp, g_k);
    cudaGetSymbolAddress((void**)&vp, g_v);
    cudaGetSymbolAddress((void**)&ap, g_attn);

    const int M = MROWS, N = E_DIM, K = E_DIM;
    dim3 gGrid(N / 128, M / 128);   // (8, 64)
    const float scaling = 0.125f;   // D^-0.5, D=64

    // projections
    sgemm_bias_kernel<<<gGrid, 256>>>(query, wq, bq, qp, M, N, K, scaling);
    sgemm_bias_kernel<<<gGrid, 256>>>(key,   wk, bk, kp, M, N, K, 1.0f);
    sgemm_bias_kernel<<<gGrid, 256>>>(value, wv, bv, vp, M, N, K, 1.0f);

    // causal flash attention
    const int smemBytes = 4 * BQ * PAD * (int)sizeof(float);   // ~65 KB
    cudaFuncSetAttribute(flash_attn_kernel,
                         cudaFuncAttributeMaxDynamicSharedMemorySize, smemBytes);
    dim3 fGrid(T_DIM / BQ, B_DIM * H_DIM);  // (32, 64)
    flash_attn_kernel<<<fGrid, 256, smemBytes>>>(qp, kp, vp, ap);

    // output projection
    sgemm_bias_kernel<<<gGrid, 256>>>(ap, wo, bo, out, M, N, K, 1.0f);
}

// round 3
// speedup vs baseline: 1.7878x; 1.7878x over previous
#include <cuda_runtime.h>
#include <cuda_bf16.h>
#include <cstdint>

// Problem constants (fixed by the dataset)
#define T_DIM   2048
#define B_DIM   4
#define E_DIM   1024
#define H_DIM   16
#define D_HEAD  64
#define MROWS   (T_DIM * B_DIM)      // 8192 rows of [T*B, E] activations

// Scratch (no cudaMalloc allowed)
__device__ float g_q[MROWS * E_DIM];
__device__ float g_k[MROWS * E_DIM];
__device__ float g_v[MROWS * E_DIM];
__device__ float g_attn[MROWS * E_DIM];

// ============================================================================
// helpers
// ============================================================================
__device__ __forceinline__ uint32_t smem_u32(const void* p) {
    uint32_t a;
    asm("{ .reg .u64 t; cvta.to.shared.u64 t, %1; cvt.u32.u64 %0, t; }"
        : "=r"(a) : "l"(p));
    return a;
}

#define LDSM_X4(r0, r1, r2, r3, addr) \
    asm volatile("ldmatrix.sync.aligned.m8n8.x4.shared.b16 {%0,%1,%2,%3}, [%4];" \
                 : "=r"(r0), "=r"(r1), "=r"(r2), "=r"(r3) : "r"(addr))
#define LDSM_X2(r0, r1, addr) \
    asm volatile("ldmatrix.sync.aligned.m8n8.x2.shared.b16 {%0,%1}, [%2];" \
                 : "=r"(r0), "=r"(r1) : "r"(addr))
#define MMA_BF16(d, a, b) \
    asm volatile("mma.sync.aligned.m16n8k16.row.col.f32.bf16.bf16.f32 " \
                 "{%0,%1,%2,%3}, {%4,%5,%6,%7}, {%8,%9}, {%0,%1,%2,%3};" \
                 : "+f"((d)[0]), "+f"((d)[1]), "+f"((d)[2]), "+f"((d)[3]) \
                 : "r"((a)[0]), "r"((a)[1]), "r"((a)[2]), "r"((a)[3]), \
                   "r"((b)[0]), "r"((b)[1]))

// packed f32x2 helpers (Blackwell)
#define PACK2(d, lo, hi)   asm("mov.b64 %0, {%1, %2};" : "=l"(d) : "f"(lo), "f"(hi))
#define UNPACK2(lo, hi, s) asm("mov.b64 {%0, %1}, %2;" : "=f"(lo), "=f"(hi) : "l"(s))
#define FMA2(d, a, b, c)   asm("fma.rn.f32x2 %0, %1, %2, %3;" : "=l"(d) : "l"(a), "l"(b), "l"(c))
#define MUL2(d, a, b)      asm("mul.rn.f32x2 %0, %1, %2;" : "=l"(d) : "l"(a), "l"(b))

// pack 2 floats -> hi/lo bf16 pairs (split-bf16 representation)
__device__ __forceinline__ void split2(float x, float y, uint32_t& hi, uint32_t& lo) {
    __nv_bfloat16 hx = __float2bfloat16(x);
    __nv_bfloat16 hy = __float2bfloat16(y);
    __nv_bfloat16 lx = __float2bfloat16(x - __bfloat162float(hx));
    __nv_bfloat16 ly = __float2bfloat16(y - __bfloat162float(hy));
    __nv_bfloat162 h2 = __halves2bfloat162(hx, hy);
    __nv_bfloat162 l2 = __halves2bfloat162(lx, ly);
    hi = *reinterpret_cast<uint32_t*>(&h2);
    lo = *reinterpret_cast<uint32_t*>(&l2);
}

// ============================================================================
// Split-bf16 GEMM: C[m,n] = (sum_k A[m,k]*W[n,k] + bias[n]) * scale
// CTA 128x128, 8 warps (2m x 4n, each 64x32), K-chunks of 32, double buffer.
// 3 mma passes (hi*hi + hi*lo + lo*hi) recover ~fp32 precision.
// ============================================================================
#define KC   32
#define SA   40                           // bf16 elems per smem row (pad 8)
#define MAT_ELEMS (128 * SA)              // 5120 bf16 per matrix
#define BUF_ELEMS (4 * MAT_ELEMS)         // Ah, Al, Wh, Wl
#define GSMEM_BYTES (2 * BUF_ELEMS * 2)   // 81920

__global__ __launch_bounds__(256) void bf16x3_gemm_kernel(
    const float* __restrict__ A, const float* __restrict__ W,
    const float* __restrict__ bias, float* __restrict__ C, float scale)
{
    extern __shared__ __nv_bfloat16 gsm[];
    const uint32_t sbase = smem_u32(gsm);

    const int tid  = threadIdx.x;
    const int wid  = tid >> 5;
    const int lane = tid & 31;
    const int m0 = blockIdx.y * 128;
    const int n0 = blockIdx.x * 128;
    const int wm = (wid >> 2) * 64;       // warp m offset (0 or 64)
    const int wn = (wid & 3) * 32;        // warp n offset

    // per-lane ldmatrix row indices
    const int arow  = (lane & 7) + ((lane >> 3) & 1) * 8;   // 0..15
    const int akoff = (lane >> 4) * 8;                      // 0 or 8
    const int brow  = lane & 7;
    const int bkoff = ((lane >> 3) & 1) * 8;

    float acc[4][4][4];
#pragma unroll
    for (int i = 0; i < 4; i++)
#pragma unroll
        for (int j = 0; j < 4; j++)
#pragma unroll
            for (int t = 0; t < 4; t++) acc[i][j][t] = 0.0f;

    // gmem load indices: i = tid + 256*j ; row = i>>3, kf = (i&7)*4
    const int lrow = tid >> 3;
    const int lkf  = (tid & 7) * 4;

    float4 avs[4], wvs[4];

    // ---- prologue: load + convert chunk 0 into buf 0
#pragma unroll
    for (int j = 0; j < 4; j++) {
        avs[j] = *(const float4*)(A + (size_t)(m0 + lrow + j * 32) * E_DIM + lkf);
        wvs[j] = *(const float4*)(W + (size_t)(n0 + lrow + j * 32) * E_DIM + lkf);
    }
    {
        __nv_bfloat16* Ah = gsm;               __nv_bfloat16* Al = gsm + MAT_ELEMS;
        __nv_bfloat16* Wh = gsm + 2*MAT_ELEMS; __nv_bfloat16* Wl = gsm + 3*MAT_ELEMS;
#pragma unroll
        for (int j = 0; j < 4; j++) {
            int r = lrow + j * 32;
            uint32_t h0, l0, h1, l1;
            split2(avs[j].x, avs[j].y, h0, l0);
            split2(avs[j].z, avs[j].w, h1, l1);
            *(uint2*)(Ah + r * SA + lkf) = make_uint2(h0, h1);
            *(uint2*)(Al + r * SA + lkf) = make_uint2(l0, l1);
            split2(wvs[j].x, wvs[j].y, h0, l0);
            split2(wvs[j].z, wvs[j].w, h1, l1);
            *(uint2*)(Wh + r * SA + lkf) = make_uint2(h0, h1);
            *(uint2*)(Wl + r * SA + lkf) = make_uint2(l0, l1);
        }
    }
    __syncthreads();

    const int NC = E_DIM / KC;   // 32
    for (int c = 0; c < NC; c++) {
        // ---- prefetch next chunk into registers
        if (c + 1 < NC) {
            const float* Ab = A + (size_t)m0 * E_DIM + (c + 1) * KC + lkf;
            const float* Wb = W + (size_t)n0 * E_DIM + (c + 1) * KC + lkf;
#pragma unroll
            for (int j = 0; j < 4; j++) {
                avs[j] = *(const float4*)(Ab + (size_t)(lrow + j * 32) * E_DIM);
                wvs[j] = *(const float4*)(Wb + (size_t)(lrow + j * 32) * E_DIM);
            }
        }

        // ---- compute on buf c&1
        {
            const uint32_t bufb = sbase + (uint32_t)(c & 1) * BUF_ELEMS * 2;
            const uint32_t AhB = bufb;
            const uint32_t AlB = bufb + MAT_ELEMS * 2;
            const uint32_t WhB = bufb + 2 * MAT_ELEMS * 2;
            const uint32_t WlB = bufb + 3 * MAT_ELEMS * 2;

#pragma unroll
            for (int kk = 0; kk < 2; kk++) {
                uint32_t ah[4][4], al[4][4];
#pragma unroll
                for (int ma = 0; ma < 4; ma++) {
                    uint32_t off = ((uint32_t)(wm + ma * 16 + arow) * SA
                                    + kk * 16 + akoff) * 2;
                    LDSM_X4(ah[ma][0], ah[ma][1], ah[ma][2], ah[ma][3], AhB + off);
                    LDSM_X4(al[ma][0], al[ma][1], al[ma][2], al[ma][3], AlB + off);
                }
#pragma unroll
                for (int na = 0; na < 4; na++) {
                    uint32_t off = ((uint32_t)(wn + na * 8 + brow) * SA
                                    + kk * 16 + bkoff) * 2;
                    uint32_t bh[2], bl[2];
                    LDSM_X2(bh[0], bh[1], WhB + off);
                    LDSM_X2(bl[0], bl[1], WlB + off);
#pragma unroll
                    for (int ma = 0; ma < 4; ma++) {
                        MMA_BF16(acc[ma][na], ah[ma], bh);
                        MMA_BF16(acc[ma][na], ah[ma], bl);
                        MMA_BF16(acc[ma][na], al[ma], bh);
                    }
                }
            }
        }
        __syncthreads();

        // ---- convert + store next chunk into the other buffer
        if (c + 1 < NC) {
            __nv_bfloat16* base = gsm + (size_t)((c + 1) & 1) * BUF_ELEMS;
            __nv_bfloat16* Ah = base;               __nv_bfloat16* Al = base + MAT_ELEMS;
            __nv_bfloat16* Wh = base + 2*MAT_ELEMS; __nv_bfloat16* Wl = base + 3*MAT_ELEMS;
#pragma unroll
            for (int j = 0; j < 4; j++) {
                int r = lrow + j * 32;
                uint32_t h0, l0, h1, l1;
                split2(avs[j].x, avs[j].y, h0, l0);
                split2(avs[j].z, avs[j].w, h1, l1);
                *(uint2*)(Ah + r * SA + lkf) = make_uint2(h0, h1);
                *(uint2*)(Al + r * SA + lkf) = make_uint2(l0, l1);
                split2(wvs[j].x, wvs[j].y, h0, l0);
                split2(wvs[j].z, wvs[j].w, h1, l1);
                *(uint2*)(Wh + r * SA + lkf) = make_uint2(h0, h1);
                *(uint2*)(Wl + r * SA + lkf) = make_uint2(l0, l1);
            }
            __syncthreads();
        }
    }

    // ---- epilogue: bias + scale, direct fp32 stores
    const int erow = lane >> 2;
    const int ecol = (lane & 3) * 2;
#pragma unroll
    for (int na = 0; na < 4; na++) {
        int col = n0 + wn + na * 8 + ecol;
        float b0 = bias[col], b1 = bias[col + 1];
#pragma unroll
        for (int ma = 0; ma < 4; ma++) {
            int row = m0 + wm + ma * 16 + erow;
            float2 v0 = make_float2((acc[ma][na][0] + b0) * scale,
                                    (acc[ma][na][1] + b1) * scale);
            float2 v1 = make_float2((acc[ma][na][2] + b0) * scale,
                                    (acc[ma][na][3] + b1) * scale);
            *(float2*)(C + (size_t)row * E_DIM + col) = v0;
            *(float2*)(C + (size_t)(row + 8) * E_DIM + col) = v1;
        }
    }
}

// ============================================================================
// Flash attention (fp32 math on packed f32x2), causal.
// Block = (head, 64-row q tile), 256 threads: tid = qg*16+sg.
// Layouts: Qs[q][d], Kts[d][s] (transposed), Vs[s][d], Ps[q][s]; pad 68.
// ============================================================================
#define BQ   64
#define BS   64
#define FPAD 68

__global__ __launch_bounds__(256) void flash_attn_kernel(
    const float* __restrict__ Q, const float* __restrict__ Kb,
    const float* __restrict__ Vb, float* __restrict__ Ob)
{
    extern __shared__ float sm[];
    float* Qs  = sm;                       // [BQ][FPAD]
    float* Kts = Qs  + BQ * FPAD;          // [D_HEAD][FPAD]
    float* Vs  = Kts + D_HEAD * FPAD;      // [BS][FPAD]
    float* Ps  = Vs  + BS * FPAD;          // [BQ][FPAD]

    const int tid = threadIdx.x;
    const int qg = tid >> 4;
    const int sg = tid & 15;
    const int qtile = blockIdx.x;
    const int n = blockIdx.y;
    const int b = n / H_DIM;
    const int h = n % H_DIM;
    const int t0 = qtile * BQ;

    {
        const int r = tid >> 2;
        const int c0 = (tid & 3) * 16;
        const float* src = Q + ((size_t)(t0 + r) * B_DIM + b) * E_DIM + h * D_HEAD + c0;
        float* dst = &Qs[r * FPAD + c0];
#pragma unroll
        for (int u = 0; u < 4; u++) *(float4*)(dst + u * 4) = *(const float4*)(src + u * 4);
    }

    float m_i[4], l_i[4];
    unsigned long long po[4][2];
#pragma unroll
    for (int i = 0; i < 4; i++) { m_i[i] = -1e30f; l_i[i] = 0.0f; po[i][0] = 0ull; po[i][1] = 0ull; }

    const int ntiles = qtile + 1;
    for (int st = 0; st < ntiles; st++) {
        const int s0 = st * BS;
        {
            const int r = tid >> 2;
            const int c0 = (tid & 3) * 16;
            const float* vsrc = Vb + ((size_t)(s0 + r) * B_DIM + b) * E_DIM + h * D_HEAD + c0;
            float* vdst = &Vs[r * FPAD + c0];
#pragma unroll
            for (int u = 0; u < 4; u++)
                *(float4*)(vdst + u * 4) = *(const float4*)(vsrc + u * 4);

            const int dg = (tid & 3) * 4;
            const float* ksrc = Kb + ((size_t)(s0 + r) * B_DIM + b) * E_DIM + h * D_HEAD;
#pragma unroll
            for (int u = 0; u < 4; u++) {
                int d0 = dg + u * 16;
                float4 kv = *(const float4*)(ksrc + d0);
                Kts[(d0 + 0) * FPAD + r] = kv.x;
                Kts[(d0 + 1) * FPAD + r] = kv.y;
                Kts[(d0 + 2) * FPAD + r] = kv.z;
                Kts[(d0 + 3) * FPAD + r] = kv.w;
            }
        }
        __syncthreads();

        unsigned long long pacc[4][2];
#pragma unroll
        for (int i = 0; i < 4; i++) { pacc[i][0] = 0ull; pacc[i][1] = 0ull; }

#pragma unroll 4
        for (int d = 0; d < D_HEAD; d++) {
            float4 kv = *(const float4*)&Kts[d * FPAD + sg * 4];
            unsigned long long k01, k23;
            PACK2(k01, kv.x, kv.y);
            PACK2(k23, kv.z, kv.w);
#pragma unroll
            for (int i = 0; i < 4; i++) {
                float q = Qs[(qg * 4 + i) * FPAD + d];
                unsigned long long qq;
                PACK2(qq, q, q);
                FMA2(pacc[i][0], qq, k01, pacc[i][0]);
                FMA2(pacc[i][1], qq, k23, pacc[i][1]);
            }
        }

        float sacc[4][4];
#pragma unroll
        for (int i = 0; i < 4; i++) {
            UNPACK2(sacc[i][0], sacc[i][1], pacc[i][0]);
            UNPACK2(sacc[i][2], sacc[i][3], pacc[i][1]);
        }

        if (st == qtile) {
#pragma unroll
            for (int i = 0; i < 4; i++) {
                int t = t0 + qg * 4 + i;
#pragma unroll
                for (int j = 0; j < 4; j++) {
                    int s = s0 + sg * 4 + j;
                    if (s > t) sacc[i][j] += -1e9f;
                }
            }
        }

        float alpha[4];
#pragma unroll
        for (int i = 0; i < 4; i++) {
            float rmax = fmaxf(fmaxf(sacc[i][0], sacc[i][1]), fmaxf(sacc[i][2], sacc[i][3]));
#pragma unroll
            for (int off = 1; off < 16; off <<= 1)
                rmax = fmaxf(rmax, __shfl_xor_sync(0xffffffffu, rmax, off));
            float mnew = fmaxf(m_i[i], rmax);
            float rsum = 0.0f;
#pragma unroll
            for (int j = 0; j < 4; j++) {
                float p = __expf(sacc[i][j] - mnew);
                sacc[i][j] = p;
                rsum += p;
            }
#pragma unroll
            for (int off = 1; off < 16; off <<= 1)
                rsum += __shfl_xor_sync(0xffffffffu, rsum, off);
            alpha[i] = __expf(m_i[i] - mnew);
            l_i[i] = l_i[i] * alpha[i] + rsum;
            m_i[i] = mnew;
        }

#pragma unroll
        for (int i = 0; i < 4; i++) {
            *(float4*)&Ps[(qg * 4 + i) * FPAD + sg * 4] =
                make_float4(sacc[i][0], sacc[i][1], sacc[i][2], sacc[i][3]);
            unsigned long long aa;
            PACK2(aa, alpha[i], alpha[i]);
            MUL2(po[i][0], po[i][0], aa);
            MUL2(po[i][1], po[i][1], aa);
        }
        __syncthreads();

#pragma unroll 4
        for (int s = 0; s < BS; s++) {
            float4 vv = *(const float4*)&Vs[s * FPAD + sg * 4];
            unsigned long long v01, v23;
            PACK2(v01, vv.x, vv.y);
            PACK2(v23, vv.z, vv.w);
#pragma unroll
            for (int i = 0; i < 4; i++) {
                float p = Ps[(qg * 4 + i) * FPAD + s];
                unsigned long long pp;
                PACK2(pp, p, p);
                FMA2(po[i][0], pp, v01, po[i][0]);
                FMA2(po[i][1], pp, v23, po[i][1]);
            }
        }
        __syncthreads();
    }

#pragma unroll
    for (int i = 0; i < 4; i++) {
        float inv = 1.0f / l_i[i];
        float o0, o1, o2, o3;
        UNPACK2(o0, o1, po[i][0]);
        UNPACK2(o2, o3, po[i][1]);
        int t = t0 + qg * 4 + i;
        float* dst = Ob + ((size_t)t * B_DIM + b) * E_DIM + h * D_HEAD + sg * 4;
        *(float4*)dst = make_float4(o0 * inv, o1 * inv, o2 * inv, o3 * inv);
    }
}

// ============================================================================
extern "C" void kernel_launch(void* const* d_in, const int* in_sizes, int n_in,
                              void* d_out, int out_size)
{
    const float* query = (const float*)d_in[0];
    const float* key   = (const float*)d_in[1];
    const float* value = (const float*)d_in[2];
    // d_in[3] = attn_mask (pure causal; applied analytically)
    const float* wq = (const float*)d_in[4];
    const float* bq = (const float*)d_in[5];
    const float* wk = (const float*)d_in[6];
    const float* bk = (const float*)d_in[7];
    const float* wv = (const float*)d_in[8];
    const float* bv = (const float*)d_in[9];
    const float* wo = (const float*)d_in[10];
    const float* bo = (const float*)d_in[11];
    float* out = (float*)d_out;

    float *qp, *kp, *vp, *ap;
    cudaGetSymbolAddress((void**)&qp, g_q);
    cudaGetSymbolAddress((void**)&kp, g_k);
    cudaGetSymbolAddress((void**)&vp, g_v);
    cudaGetSymbolAddress((void**)&ap, g_attn);

    cudaFuncSetAttribute(bf16x3_gemm_kernel,
                         cudaFuncAttributeMaxDynamicSharedMemorySize, GSMEM_BYTES);
    dim3 gGrid(E_DIM / 128, MROWS / 128);   // (8, 64)
    const float scaling = 0.125f;           // D^-0.5

    bf16x3_gemm_kernel<<<gGrid, 256, GSMEM_BYTES>>>(query, wq, bq, qp, scaling);
    bf16x3_gemm_kernel<<<gGrid, 256, GSMEM_BYTES>>>(key,   wk, bk, kp, 1.0f);
    bf16x3_gemm_kernel<<<gGrid, 256, GSMEM_BYTES>>>(value, wv, bv, vp, 1.0f);

    const int smemBytes = 4 * BQ * FPAD * (int)sizeof(float);
    cudaFuncSetAttribute(flash_attn_kernel,
                         cudaFuncAttributeMaxDynamicSharedMemorySize, smemBytes);
    dim3 fGrid(T_DIM / BQ, B_DIM * H_DIM);  // (32, 64)
    flash_attn_kernel<<<fGrid, 256, smemBytes>>>(qp, kp, vp, ap);

    bf16x3_gemm_kernel<<<gGrid, 256, GSMEM_BYTES>>>(ap, wo, bo, out, 1.0f);
}

// round 5
// speedup vs baseline: 2.7728x; 1.5510x over previous
#include <cuda_runtime.h>
#include <cuda_bf16.h>
#include <cstdint>

// Problem constants (fixed by the dataset)
#define T_DIM   2048
#define B_DIM   4
#define E_DIM   1024
#define H_DIM   16
#define D_HEAD  64
#define MROWS   (T_DIM * B_DIM)      // 8192 rows of [T*B, E] activations

// Scratch (no cudaMalloc allowed)
__device__ float g_q[MROWS * E_DIM];
__device__ float g_k[MROWS * E_DIM];
__device__ float g_v[MROWS * E_DIM];
__device__ float g_attn[MROWS * E_DIM];

// ============================================================================
// helpers
// ============================================================================
__device__ __forceinline__ uint32_t smem_u32(const void* p) {
    uint32_t a;
    asm("{ .reg .u64 t; cvta.to.shared.u64 t, %1; cvt.u32.u64 %0, t; }"
        : "=r"(a) : "l"(p));
    return a;
}

#define LDSM_X4(r0, r1, r2, r3, addr) \
    asm volatile("ldmatrix.sync.aligned.m8n8.x4.shared.b16 {%0,%1,%2,%3}, [%4];" \
                 : "=r"(r0), "=r"(r1), "=r"(r2), "=r"(r3) : "r"(addr))
#define LDSM_X2(r0, r1, addr) \
    asm volatile("ldmatrix.sync.aligned.m8n8.x2.shared.b16 {%0,%1}, [%2];" \
                 : "=r"(r0), "=r"(r1) : "r"(addr))
#define MMA_BF16(d, a, b) \
    asm volatile("mma.sync.aligned.m16n8k16.row.col.f32.bf16.bf16.f32 " \
                 "{%0,%1,%2,%3}, {%4,%5,%6,%7}, {%8,%9}, {%0,%1,%2,%3};" \
                 : "+f"((d)[0]), "+f"((d)[1]), "+f"((d)[2]), "+f"((d)[3]) \
                 : "r"((a)[0]), "r"((a)[1]), "r"((a)[2]), "r"((a)[3]), \
                   "r"((b)[0]), "r"((b)[1]))

// pack 2 floats -> hi/lo bf16 pairs (split-bf16; x in low half)
__device__ __forceinline__ void split2(float x, float y, uint32_t& hi, uint32_t& lo) {
    __nv_bfloat16 hx = __float2bfloat16(x);
    __nv_bfloat16 hy = __float2bfloat16(y);
    __nv_bfloat16 lx = __float2bfloat16(x - __bfloat162float(hx));
    __nv_bfloat16 ly = __float2bfloat16(y - __bfloat162float(hy));
    __nv_bfloat162 h2 = __halves2bfloat162(hx, hy);
    __nv_bfloat162 l2 = __halves2bfloat162(lx, ly);
    hi = *reinterpret_cast<uint32_t*>(&h2);
    lo = *reinterpret_cast<uint32_t*>(&l2);
}

// ============================================================================
// Split-bf16 GEMM: C[m,n] = (sum_k A[m,k]*W[n,k] + bias[n]) * scale
// CTA 128x128, 8 warps (2m x 4n, each 64x32), K-chunks of 32, double buffer.
// ============================================================================
#define KC   32
#define SA   40
#define MAT_ELEMS (128 * SA)
#define BUF_ELEMS (4 * MAT_ELEMS)
#define GSMEM_BYTES (2 * BUF_ELEMS * 2)   // 81920

__global__ __launch_bounds__(256) void bf16x3_gemm_kernel(
    const float* __restrict__ A, const float* __restrict__ W,
    const float* __restrict__ bias, float* __restrict__ C, float scale)
{
    extern __shared__ __nv_bfloat16 gsm[];
    const uint32_t sbase = smem_u32(gsm);

    const int tid  = threadIdx.x;
    const int wid  = tid >> 5;
    const int lane = tid & 31;
    const int m0 = blockIdx.y * 128;
    const int n0 = blockIdx.x * 128;
    const int wm = (wid >> 2) * 64;
    const int wn = (wid & 3) * 32;

    const int arow  = (lane & 7) + ((lane >> 3) & 1) * 8;
    const int akoff = (lane >> 4) * 8;
    const int brow  = lane & 7;
    const int bkoff = ((lane >> 3) & 1) * 8;

    float acc[4][4][4];
#pragma unroll
    for (int i = 0; i < 4; i++)
#pragma unroll
        for (int j = 0; j < 4; j++)
#pragma unroll
            for (int t = 0; t < 4; t++) acc[i][j][t] = 0.0f;

    const int lrow = tid >> 3;
    const int lkf  = (tid & 7) * 4;

    float4 avs[4], wvs[4];

#pragma unroll
    for (int j = 0; j < 4; j++) {
        avs[j] = *(const float4*)(A + (size_t)(m0 + lrow + j * 32) * E_DIM + lkf);
        wvs[j] = *(const float4*)(W + (size_t)(n0 + lrow + j * 32) * E_DIM + lkf);
    }
    {
        __nv_bfloat16* Ah = gsm;               __nv_bfloat16* Al = gsm + MAT_ELEMS;
        __nv_bfloat16* Wh = gsm + 2*MAT_ELEMS; __nv_bfloat16* Wl = gsm + 3*MAT_ELEMS;
#pragma unroll
        for (int j = 0; j < 4; j++) {
            int r = lrow + j * 32;
            uint32_t h0, l0, h1, l1;
            split2(avs[j].x, avs[j].y, h0, l0);
            split2(avs[j].z, avs[j].w, h1, l1);
            *(uint2*)(Ah + r * SA + lkf) = make_uint2(h0, h1);
            *(uint2*)(Al + r * SA + lkf) = make_uint2(l0, l1);
            split2(wvs[j].x, wvs[j].y, h0, l0);
            split2(wvs[j].z, wvs[j].w, h1, l1);
            *(uint2*)(Wh + r * SA + lkf) = make_uint2(h0, h1);
            *(uint2*)(Wl + r * SA + lkf) = make_uint2(l0, l1);
        }
    }
    __syncthreads();

    const int NC = E_DIM / KC;
    for (int c = 0; c < NC; c++) {
        if (c + 1 < NC) {
            const float* Ab = A + (size_t)m0 * E_DIM + (c + 1) * KC + lkf;
            const float* Wb = W + (size_t)n0 * E_DIM + (c + 1) * KC + lkf;
#pragma unroll
            for (int j = 0; j < 4; j++) {
                avs[j] = *(const float4*)(Ab + (size_t)(lrow + j * 32) * E_DIM);
                wvs[j] = *(const float4*)(Wb + (size_t)(lrow + j * 32) * E_DIM);
            }
        }
        {
            const uint32_t bufb = sbase + (uint32_t)(c & 1) * BUF_ELEMS * 2;
            const uint32_t AhB = bufb;
            const uint32_t AlB = bufb + MAT_ELEMS * 2;
            const uint32_t WhB = bufb + 2 * MAT_ELEMS * 2;
            const uint32_t WlB = bufb + 3 * MAT_ELEMS * 2;

#pragma unroll
            for (int kk = 0; kk < 2; kk++) {
                uint32_t ah[4][4], al[4][4];
#pragma unroll
                for (int ma = 0; ma < 4; ma++) {
                    uint32_t off = ((uint32_t)(wm + ma * 16 + arow) * SA
                                    + kk * 16 + akoff) * 2;
                    LDSM_X4(ah[ma][0], ah[ma][1], ah[ma][2], ah[ma][3], AhB + off);
                    LDSM_X4(al[ma][0], al[ma][1], al[ma][2], al[ma][3], AlB + off);
                }
#pragma unroll
                for (int na = 0; na < 4; na++) {
                    uint32_t off = ((uint32_t)(wn + na * 8 + brow) * SA
                                    + kk * 16 + bkoff) * 2;
                    uint32_t bh[2], bl[2];
                    LDSM_X2(bh[0], bh[1], WhB + off);
                    LDSM_X2(bl[0], bl[1], WlB + off);
#pragma unroll
                    for (int ma = 0; ma < 4; ma++) {
                        MMA_BF16(acc[ma][na], ah[ma], bh);
                        MMA_BF16(acc[ma][na], ah[ma], bl);
                        MMA_BF16(acc[ma][na], al[ma], bh);
                    }
                }
            }
        }
        __syncthreads();

        if (c + 1 < NC) {
            __nv_bfloat16* base = gsm + (size_t)((c + 1) & 1) * BUF_ELEMS;
            __nv_bfloat16* Ah = base;               __nv_bfloat16* Al = base + MAT_ELEMS;
            __nv_bfloat16* Wh = base + 2*MAT_ELEMS; __nv_bfloat16* Wl = base + 3*MAT_ELEMS;
#pragma unroll
            for (int j = 0; j < 4; j++) {
                int r = lrow + j * 32;
                uint32_t h0, l0, h1, l1;
                split2(avs[j].x, avs[j].y, h0, l0);
                split2(avs[j].z, avs[j].w, h1, l1);
                *(uint2*)(Ah + r * SA + lkf) = make_uint2(h0, h1);
                *(uint2*)(Al + r * SA + lkf) = make_uint2(l0, l1);
                split2(wvs[j].x, wvs[j].y, h0, l0);
                split2(wvs[j].z, wvs[j].w, h1, l1);
                *(uint2*)(Wh + r * SA + lkf) = make_uint2(h0, h1);
                *(uint2*)(Wl + r * SA + lkf) = make_uint2(l0, l1);
            }
            __syncthreads();
        }
    }

    const int erow = lane >> 2;
    const int ecol = (lane & 3) * 2;
#pragma unroll
    for (int na = 0; na < 4; na++) {
        int col = n0 + wn + na * 8 + ecol;
        float b0 = bias[col], b1 = bias[col + 1];
#pragma unroll
        for (int ma = 0; ma < 4; ma++) {
            int row = m0 + wm + ma * 16 + erow;
            float2 v0 = make_float2((acc[ma][na][0] + b0) * scale,
                                    (acc[ma][na][1] + b1) * scale);
            float2 v1 = make_float2((acc[ma][na][2] + b0) * scale,
                                    (acc[ma][na][3] + b1) * scale);
            *(float2*)(C + (size_t)row * E_DIM + col) = v0;
            *(float2*)(C + (size_t)(row + 8) * E_DIM + col) = v1;
        }
    }
}

// ============================================================================
// Flash attention on tensor cores (split-bf16, 3-pass), causal.
// CTA = (head, 128-q-row tile), 8 warps x 16 rows, s-tiles of 64.
// S = QhKh+QhKl+QlKh; P kept in registers (S-acc layout == A-frag layout);
// O += PhVh+PhVl+PlVh with V stored transposed [d][s].
// ============================================================================
#define FBQ 128
#define FBS 64
#define FP  72                                 // padded row length (bf16 elems)
#define FSMEM_BYTES ((2*FBQ*FP + 4*FBS*FP) * 2) // 73728

__global__ __launch_bounds__(256) void flash_mma_kernel(
    const float* __restrict__ Q, const float* __restrict__ Kb,
    const float* __restrict__ Vb, float* __restrict__ Ob)
{
    extern __shared__ __nv_bfloat16 fsm[];
    __nv_bfloat16* Qh  = fsm;
    __nv_bfloat16* Ql  = Qh  + FBQ * FP;
    __nv_bfloat16* Kh  = Ql  + FBQ * FP;
    __nv_bfloat16* Kl  = Kh  + FBS * FP;
    __nv_bfloat16* Vth = Kl  + FBS * FP;       // [d][s]
    __nv_bfloat16* Vtl = Vth + FBS * FP;

    const uint32_t sb   = smem_u32(fsm);
    const uint32_t QhB  = sb;
    const uint32_t QlB  = QhB  + FBQ * FP * 2;
    const uint32_t KhB  = QlB  + FBQ * FP * 2;
    const uint32_t KlB  = KhB  + FBS * FP * 2;
    const uint32_t VthB = KlB  + FBS * FP * 2;
    const uint32_t VtlB = VthB + FBS * FP * 2;

    const int tid  = threadIdx.x;
    const int wid  = tid >> 5;
    const int lane = tid & 31;
    const int head = blockIdx.x;                       // b*H + h
    const int qtile = (int)(gridDim.y - 1) - (int)blockIdx.y;  // heavy first
    const int b = head >> 4;
    const int h = head & 15;
    const int t0 = qtile * FBQ;

    // ---- load Q tile (128 rows x 64 d), split to bf16 hi/lo
    {
        const int r  = tid >> 1;
        const int c0 = (tid & 1) * 32;
        const float* src = Q + ((size_t)(t0 + r) * B_DIM + b) * E_DIM + h * D_HEAD + c0;
#pragma unroll
        for (int u = 0; u < 8; u++) {
            float4 v = *(const float4*)(src + u * 4);
            uint32_t h0, l0, h1, l1;
            split2(v.x, v.y, h0, l0);
            split2(v.z, v.w, h1, l1);
            *(uint2*)(Qh + r * FP + c0 + u * 4) = make_uint2(h0, h1);
            *(uint2*)(Ql + r * FP + c0 + u * 4) = make_uint2(l0, l1);
        }
    }
    __syncthreads();

    // ---- Q A-fragments (persist across all s-tiles)
    const int arow  = (lane & 7) + ((lane >> 3) & 1) * 8;
    const int akoff = (lane >> 4) * 8;
    uint32_t qah[4][4], qal[4][4];
#pragma unroll
    for (int kc = 0; kc < 4; kc++) {
        uint32_t off = ((uint32_t)(wid * 16 + arow) * FP + kc * 16 + akoff) * 2;
        LDSM_X4(qah[kc][0], qah[kc][1], qah[kc][2], qah[kc][3], QhB + off);
        LDSM_X4(qal[kc][0], qal[kc][1], qal[kc][2], qal[kc][3], QlB + off);
    }

    const int brow = lane & 7;
    const int bk   = ((lane >> 3) & 1) * 8;

    float m0 = -1e30f, m1 = -1e30f, l0 = 0.0f, l1 = 0.0f;
    float oacc[8][4];
#pragma unroll
    for (int i = 0; i < 8; i++)
#pragma unroll
        for (int t = 0; t < 4; t++) oacc[i][t] = 0.0f;

    const int wrow_min = t0 + wid * 16;        // warp's first q row
    const int wrow_max = wrow_min + 15;        // warp's last q row
    const int ntiles = 2 * qtile + 2;

    for (int st = 0; st < ntiles; st++) {
        const int s0 = st * FBS;

        // ---- load K [s][d] and V transposed [d][s], split hi/lo
        {
            const int r  = tid >> 2;
            const int c0 = (tid & 3) * 16;
            const float* ks = Kb + ((size_t)(s0 + r) * B_DIM + b) * E_DIM + h * D_HEAD + c0;
            const float* vs = Vb + ((size_t)(s0 + r) * B_DIM + b) * E_DIM + h * D_HEAD + c0;
#pragma unroll
            for (int u = 0; u < 4; u++) {
                float4 kv = *(const float4*)(ks + u * 4);
                uint32_t h0, lx0, h1, lx1;
                split2(kv.x, kv.y, h0, lx0);
                split2(kv.z, kv.w, h1, lx1);
                *(uint2*)(Kh + r * FP + c0 + u * 4) = make_uint2(h0, h1);
                *(uint2*)(Kl + r * FP + c0 + u * 4) = make_uint2(lx0, lx1);

                float4 vv = *(const float4*)(vs + u * 4);
                int db = c0 + u * 4;
                __nv_bfloat16 vh0 = __float2bfloat16(vv.x);
                __nv_bfloat16 vh1 = __float2bfloat16(vv.y);
                __nv_bfloat16 vh2 = __float2bfloat16(vv.z);
                __nv_bfloat16 vh3 = __float2bfloat16(vv.w);
                Vth[(db + 0) * FP + r] = vh0;
                Vth[(db + 1) * FP + r] = vh1;
                Vth[(db + 2) * FP + r] = vh2;
                Vth[(db + 3) * FP + r] = vh3;
                Vtl[(db + 0) * FP + r] = __float2bfloat16(vv.x - __bfloat162float(vh0));
                Vtl[(db + 1) * FP + r] = __float2bfloat16(vv.y - __bfloat162float(vh1));
                Vtl[(db + 2) * FP + r] = __float2bfloat16(vv.z - __bfloat162float(vh2));
                Vtl[(db + 3) * FP + r] = __float2bfloat16(vv.w - __bfloat162float(vh3));
            }
        }
        __syncthreads();

        if (s0 <= wrow_max) {   // warp has at least one unmasked row in this tile
            // ---- S = Q K^T (3-pass split)
            float sacc[8][4];
#pragma unroll
            for (int i = 0; i < 8; i++)
#pragma unroll
                for (int t = 0; t < 4; t++) sacc[i][t] = 0.0f;

#pragma unroll
            for (int nt = 0; nt < 8; nt++) {
#pragma unroll
                for (int kc = 0; kc < 4; kc++) {
                    uint32_t off = ((uint32_t)(nt * 8 + brow) * FP + kc * 16 + bk) * 2;
                    uint32_t bh[2], bl[2];
                    LDSM_X2(bh[0], bh[1], KhB + off);
                    LDSM_X2(bl[0], bl[1], KlB + off);
                    MMA_BF16(sacc[nt], qah[kc], bh);
                    MMA_BF16(sacc[nt], qah[kc], bl);
                    MMA_BF16(sacc[nt], qal[kc], bh);
                }
            }

            // ---- causal mask: needed whenever tile reaches past the warp's
            // FIRST row (was: last row — that gate dropped mask on straddle tiles)
            if (s0 + FBS - 1 > wrow_min) {
                int r0g = wrow_min + (lane >> 2);
                int r1g = r0g + 8;
#pragma unroll
                for (int nt = 0; nt < 8; nt++) {
                    int c0g = s0 + nt * 8 + (lane & 3) * 2;
                    if (c0g     > r0g) sacc[nt][0] = -1e9f;
                    if (c0g + 1 > r0g) sacc[nt][1] = -1e9f;
                    if (c0g     > r1g) sacc[nt][2] = -1e9f;
                    if (c0g + 1 > r1g) sacc[nt][3] = -1e9f;
                }
            }

            // ---- online softmax (rows owned by quads; reduce via xor 1,2)
            float rmax0 = -1e30f, rmax1 = -1e30f;
#pragma unroll
            for (int nt = 0; nt < 8; nt++) {
                rmax0 = fmaxf(rmax0, fmaxf(sacc[nt][0], sacc[nt][1]));
                rmax1 = fmaxf(rmax1, fmaxf(sacc[nt][2], sacc[nt][3]));
            }
            rmax0 = fmaxf(rmax0, __shfl_xor_sync(0xffffffffu, rmax0, 1));
            rmax0 = fmaxf(rmax0, __shfl_xor_sync(0xffffffffu, rmax0, 2));
            rmax1 = fmaxf(rmax1, __shfl_xor_sync(0xffffffffu, rmax1, 1));
            rmax1 = fmaxf(rmax1, __shfl_xor_sync(0xffffffffu, rmax1, 2));

            float mn0 = fmaxf(m0, rmax0);
            float mn1 = fmaxf(m1, rmax1);
            float a0 = __expf(m0 - mn0);
            float a1 = __expf(m1 - mn1);

            float rs0 = 0.0f, rs1 = 0.0f;
            uint32_t pah[4][4], pal[4][4];
#pragma unroll
            for (int nt = 0; nt < 8; nt++) {
                float p0 = __expf(sacc[nt][0] - mn0);
                float p1 = __expf(sacc[nt][1] - mn0);
                float p2 = __expf(sacc[nt][2] - mn1);
                float p3 = __expf(sacc[nt][3] - mn1);
                rs0 += p0 + p1;
                rs1 += p2 + p3;
                int kc = nt >> 1, half = nt & 1;
                uint32_t hA, lA, hB, lB;
                split2(p0, p1, hA, lA);
                split2(p2, p3, hB, lB);
                pah[kc][half * 2 + 0] = hA; pal[kc][half * 2 + 0] = lA;
                pah[kc][half * 2 + 1] = hB; pal[kc][half * 2 + 1] = lB;
            }
            rs0 += __shfl_xor_sync(0xffffffffu, rs0, 1);
            rs0 += __shfl_xor_sync(0xffffffffu, rs0, 2);
            rs1 += __shfl_xor_sync(0xffffffffu, rs1, 1);
            rs1 += __shfl_xor_sync(0xffffffffu, rs1, 2);

            l0 = l0 * a0 + rs0;
            l1 = l1 * a1 + rs1;
            m0 = mn0; m1 = mn1;

            // ---- rescale running O
#pragma unroll
            for (int dt = 0; dt < 8; dt++) {
                oacc[dt][0] *= a0; oacc[dt][1] *= a0;
                oacc[dt][2] *= a1; oacc[dt][3] *= a1;
            }

            // ---- O += P V (3-pass split, V transposed in smem)
#pragma unroll
            for (int dt = 0; dt < 8; dt++) {
#pragma unroll
                for (int kc = 0; kc < 4; kc++) {
                    uint32_t off = ((uint32_t)(dt * 8 + brow) * FP + kc * 16 + bk) * 2;
                    uint32_t vh[2], vl[2];
                    LDSM_X2(vh[0], vh[1], VthB + off);
                    LDSM_X2(vl[0], vl[1], VtlB + off);
                    MMA_BF16(oacc[dt], pah[kc], vh);
                    MMA_BF16(oacc[dt], pah[kc], vl);
                    MMA_BF16(oacc[dt], pal[kc], vh);
                }
            }
        }
        __syncthreads();
    }

    // ---- normalize + write
    float inv0 = 1.0f / l0;
    float inv1 = 1.0f / l1;
    int r0g = t0 + wid * 16 + (lane >> 2);
#pragma unroll
    for (int dt = 0; dt < 8; dt++) {
        int col = h * D_HEAD + dt * 8 + (lane & 3) * 2;
        *(float2*)(Ob + ((size_t)r0g * B_DIM + b) * E_DIM + col) =
            make_float2(oacc[dt][0] * inv0, oacc[dt][1] * inv0);
        *(float2*)(Ob + ((size_t)(r0g + 8) * B_DIM + b) * E_DIM + col) =
            make_float2(oacc[dt][2] * inv1, oacc[dt][3] * inv1);
    }
}

// ============================================================================
extern "C" void kernel_launch(void* const* d_in, const int* in_sizes, int n_in,
                              void* d_out, int out_size)
{
    const float* query = (const float*)d_in[0];
    const float* key   = (const float*)d_in[1];
    const float* value = (const float*)d_in[2];
    // d_in[3] = attn_mask (pure causal; applied analytically)
    const float* wq = (const float*)d_in[4];
    const float* bq = (const float*)d_in[5];
    const float* wk = (const float*)d_in[6];
    const float* bk = (const float*)d_in[7];
    const float* wv = (const float*)d_in[8];
    const float* bv = (const float*)d_in[9];
    const float* wo = (const float*)d_in[10];
    const float* bo = (const float*)d_in[11];
    float* out = (float*)d_out;

    float *qp, *kp, *vp, *ap;
    cudaGetSymbolAddress((void**)&qp, g_q);
    cudaGetSymbolAddress((void**)&kp, g_k);
    cudaGetSymbolAddress((void**)&vp, g_v);
    cudaGetSymbolAddress((void**)&ap, g_attn);

    cudaFuncSetAttribute(bf16x3_gemm_kernel,
                         cudaFuncAttributeMaxDynamicSharedMemorySize, GSMEM_BYTES);
    dim3 gGrid(E_DIM / 128, MROWS / 128);   // (8, 64)
    const float scaling = 0.125f;           // D^-0.5

    bf16x3_gemm_kernel<<<gGrid, 256, GSMEM_BYTES>>>(query, wq, bq, qp, scaling);
    bf16x3_gemm_kernel<<<gGrid, 256, GSMEM_BYTES>>>(key,   wk, bk, kp, 1.0f);
    bf16x3_gemm_kernel<<<gGrid, 256, GSMEM_BYTES>>>(value, wv, bv, vp, 1.0f);

    cudaFuncSetAttribute(flash_mma_kernel,
                         cudaFuncAttributeMaxDynamicSharedMemorySize, FSMEM_BYTES);
    dim3 fGrid(B_DIM * H_DIM, T_DIM / FBQ);  // (64 heads, 16 qtiles)
    flash_mma_kernel<<<fGrid, 256, FSMEM_BYTES>>>(qp, kp, vp, ap);

    bf16x3_gemm_kernel<<<gGrid, 256, GSMEM_BYTES>>>(ap, wo, bo, out, 1.0f);
}

// round 6
// speedup vs baseline: 2.9334x; 1.0579x over previous
#include <cuda_runtime.h>
#include <cuda_bf16.h>
#include <cstdint>

// Problem constants (fixed by the dataset)
#define T_DIM   2048
#define B_DIM   4
#define E_DIM   1024
#define H_DIM   16
#define D_HEAD  64
#define MROWS   (T_DIM * B_DIM)      // 8192 rows of [T*B, E] activations

// Scratch (no cudaMalloc allowed)
__device__ float g_q[MROWS * E_DIM];
__device__ float g_k[MROWS * E_DIM];
__device__ float g_v[MROWS * E_DIM];
__device__ float g_attn[MROWS * E_DIM];

// ============================================================================
// helpers
// ============================================================================
__device__ __forceinline__ uint32_t smem_u32(const void* p) {
    uint32_t a;
    asm("{ .reg .u64 t; cvta.to.shared.u64 t, %1; cvt.u32.u64 %0, t; }"
        : "=r"(a) : "l"(p));
    return a;
}

#define LDSM_X4(r0, r1, r2, r3, addr) \
    asm volatile("ldmatrix.sync.aligned.m8n8.x4.shared.b16 {%0,%1,%2,%3}, [%4];" \
                 : "=r"(r0), "=r"(r1), "=r"(r2), "=r"(r3) : "r"(addr))
#define LDSM_X4_TRANS(r0, r1, r2, r3, addr) \
    asm volatile("ldmatrix.sync.aligned.m8n8.x4.trans.shared.b16 {%0,%1,%2,%3}, [%4];" \
                 : "=r"(r0), "=r"(r1), "=r"(r2), "=r"(r3) : "r"(addr))
#define LDSM_X2(r0, r1, addr) \
    asm volatile("ldmatrix.sync.aligned.m8n8.x2.shared.b16 {%0,%1}, [%2];" \
                 : "=r"(r0), "=r"(r1) : "r"(addr))
#define MMA_BF16(d, a, b) \
    asm volatile("mma.sync.aligned.m16n8k16.row.col.f32.bf16.bf16.f32 " \
                 "{%0,%1,%2,%3}, {%4,%5,%6,%7}, {%8,%9}, {%0,%1,%2,%3};" \
                 : "+f"((d)[0]), "+f"((d)[1]), "+f"((d)[2]), "+f"((d)[3]) \
                 : "r"((a)[0]), "r"((a)[1]), "r"((a)[2]), "r"((a)[3]), \
                   "r"((b)[0]), "r"((b)[1]))
#define MMA_BF16_P(d, a, b0, b1) \
    asm volatile("mma.sync.aligned.m16n8k16.row.col.f32.bf16.bf16.f32 " \
                 "{%0,%1,%2,%3}, {%4,%5,%6,%7}, {%8,%9}, {%0,%1,%2,%3};" \
                 : "+f"((d)[0]), "+f"((d)[1]), "+f"((d)[2]), "+f"((d)[3]) \
                 : "r"((a)[0]), "r"((a)[1]), "r"((a)[2]), "r"((a)[3]), \
                   "r"(b0), "r"(b1))

// pack 2 floats -> hi/lo bf16 pairs (split-bf16; x in low half)
__device__ __forceinline__ void split2(float x, float y, uint32_t& hi, uint32_t& lo) {
    __nv_bfloat16 hx = __float2bfloat16(x);
    __nv_bfloat16 hy = __float2bfloat16(y);
    __nv_bfloat16 lx = __float2bfloat16(x - __bfloat162float(hx));
    __nv_bfloat16 ly = __float2bfloat16(y - __bfloat162float(hy));
    __nv_bfloat162 h2 = __halves2bfloat162(hx, hy);
    __nv_bfloat162 l2 = __halves2bfloat162(lx, ly);
    hi = *reinterpret_cast<uint32_t*>(&h2);
    lo = *reinterpret_cast<uint32_t*>(&l2);
}

// ============================================================================
// Split-bf16 GEMM: C[m,n] = (sum_k A[m,k]*W[n,k] + bias[n]) * scale
// CTA 128x128, 8 warps (2m x 4n, each 64x32), K-chunks of 32, double buffer.
// ============================================================================
#define KC   32
#define SA   40
#define MAT_ELEMS (128 * SA)
#define BUF_ELEMS (4 * MAT_ELEMS)
#define GSMEM_BYTES (2 * BUF_ELEMS * 2)   // 81920

__global__ __launch_bounds__(256) void bf16x3_gemm_kernel(
    const float* __restrict__ A, const float* __restrict__ W,
    const float* __restrict__ bias, float* __restrict__ C, float scale)
{
    extern __shared__ __nv_bfloat16 gsm[];
    const uint32_t sbase = smem_u32(gsm);

    const int tid  = threadIdx.x;
    const int wid  = tid >> 5;
    const int lane = tid & 31;
    const int m0 = blockIdx.y * 128;
    const int n0 = blockIdx.x * 128;
    const int wm = (wid >> 2) * 64;
    const int wn = (wid & 3) * 32;

    const int arow  = (lane & 7) + ((lane >> 3) & 1) * 8;
    const int akoff = (lane >> 4) * 8;
    const int brow  = lane & 7;
    const int bkoff = ((lane >> 3) & 1) * 8;

    float acc[4][4][4];
#pragma unroll
    for (int i = 0; i < 4; i++)
#pragma unroll
        for (int j = 0; j < 4; j++)
#pragma unroll
            for (int t = 0; t < 4; t++) acc[i][j][t] = 0.0f;

    const int lrow = tid >> 3;
    const int lkf  = (tid & 7) * 4;

    float4 avs[4], wvs[4];

#pragma unroll
    for (int j = 0; j < 4; j++) {
        avs[j] = *(const float4*)(A + (size_t)(m0 + lrow + j * 32) * E_DIM + lkf);
        wvs[j] = *(const float4*)(W + (size_t)(n0 + lrow + j * 32) * E_DIM + lkf);
    }
    {
        __nv_bfloat16* Ah = gsm;               __nv_bfloat16* Al = gsm + MAT_ELEMS;
        __nv_bfloat16* Wh = gsm + 2*MAT_ELEMS; __nv_bfloat16* Wl = gsm + 3*MAT_ELEMS;
#pragma unroll
        for (int j = 0; j < 4; j++) {
            int r = lrow + j * 32;
            uint32_t h0, l0, h1, l1;
            split2(avs[j].x, avs[j].y, h0, l0);
            split2(avs[j].z, avs[j].w, h1, l1);
            *(uint2*)(Ah + r * SA + lkf) = make_uint2(h0, h1);
            *(uint2*)(Al + r * SA + lkf) = make_uint2(l0, l1);
            split2(wvs[j].x, wvs[j].y, h0, l0);
            split2(wvs[j].z, wvs[j].w, h1, l1);
            *(uint2*)(Wh + r * SA + lkf) = make_uint2(h0, h1);
            *(uint2*)(Wl + r * SA + lkf) = make_uint2(l0, l1);
        }
    }
    __syncthreads();

    const int NC = E_DIM / KC;
    for (int c = 0; c < NC; c++) {
        if (c + 1 < NC) {
            const float* Ab = A + (size_t)m0 * E_DIM + (c + 1) * KC + lkf;
            const float* Wb = W + (size_t)n0 * E_DIM + (c + 1) * KC + lkf;
#pragma unroll
            for (int j = 0; j < 4; j++) {
                avs[j] = *(const float4*)(Ab + (size_t)(lrow + j * 32) * E_DIM);
                wvs[j] = *(const float4*)(Wb + (size_t)(lrow + j * 32) * E_DIM);
            }
        }
        {
            const uint32_t bufb = sbase + (uint32_t)(c & 1) * BUF_ELEMS * 2;
            const uint32_t AhB = bufb;
            const uint32_t AlB = bufb + MAT_ELEMS * 2;
            const uint32_t WhB = bufb + 2 * MAT_ELEMS * 2;
            const uint32_t WlB = bufb + 3 * MAT_ELEMS * 2;

#pragma unroll
            for (int kk = 0; kk < 2; kk++) {
                uint32_t ah[4][4], al[4][4];
#pragma unroll
                for (int ma = 0; ma < 4; ma++) {
                    uint32_t off = ((uint32_t)(wm + ma * 16 + arow) * SA
                                    + kk * 16 + akoff) * 2;
                    LDSM_X4(ah[ma][0], ah[ma][1], ah[ma][2], ah[ma][3], AhB + off);
                    LDSM_X4(al[ma][0], al[ma][1], al[ma][2], al[ma][3], AlB + off);
                }
#pragma unroll
                for (int na = 0; na < 4; na++) {
                    uint32_t off = ((uint32_t)(wn + na * 8 + brow) * SA
                                    + kk * 16 + bkoff) * 2;
                    uint32_t bh[2], bl[2];
                    LDSM_X2(bh[0], bh[1], WhB + off);
                    LDSM_X2(bl[0], bl[1], WlB + off);
#pragma unroll
                    for (int ma = 0; ma < 4; ma++) {
                        MMA_BF16(acc[ma][na], ah[ma], bh);
                        MMA_BF16(acc[ma][na], ah[ma], bl);
                        MMA_BF16(acc[ma][na], al[ma], bh);
                    }
                }
            }
        }
        __syncthreads();

        if (c + 1 < NC) {
            __nv_bfloat16* base = gsm + (size_t)((c + 1) & 1) * BUF_ELEMS;
            __nv_bfloat16* Ah = base;               __nv_bfloat16* Al = base + MAT_ELEMS;
            __nv_bfloat16* Wh = base + 2*MAT_ELEMS; __nv_bfloat16* Wl = base + 3*MAT_ELEMS;
#pragma unroll
            for (int j = 0; j < 4; j++) {
                int r = lrow + j * 32;
                uint32_t h0, l0, h1, l1;
                split2(avs[j].x, avs[j].y, h0, l0);
                split2(avs[j].z, avs[j].w, h1, l1);
                *(uint2*)(Ah + r * SA + lkf) = make_uint2(h0, h1);
                *(uint2*)(Al + r * SA + lkf) = make_uint2(l0, l1);
                split2(wvs[j].x, wvs[j].y, h0, l0);
                split2(wvs[j].z, wvs[j].w, h1, l1);
                *(uint2*)(Wh + r * SA + lkf) = make_uint2(h0, h1);
                *(uint2*)(Wl + r * SA + lkf) = make_uint2(l0, l1);
            }
            __syncthreads();
        }
    }

    const int erow = lane >> 2;
    const int ecol = (lane & 3) * 2;
#pragma unroll
    for (int na = 0; na < 4; na++) {
        int col = n0 + wn + na * 8 + ecol;
        float b0 = bias[col], b1 = bias[col + 1];
#pragma unroll
        for (int ma = 0; ma < 4; ma++) {
            int row = m0 + wm + ma * 16 + erow;
            float2 v0 = make_float2((acc[ma][na][0] + b0) * scale,
                                    (acc[ma][na][1] + b1) * scale);
            float2 v1 = make_float2((acc[ma][na][2] + b0) * scale,
                                    (acc[ma][na][3] + b1) * scale);
            *(float2*)(C + (size_t)row * E_DIM + col) = v0;
            *(float2*)(C + (size_t)(row + 8) * E_DIM + col) = v1;
        }
    }
}

// ============================================================================
// Flash attention on tensor cores (split-bf16, 3-pass), causal.
// CTA = (head, 128-q-row tile), 8 warps x 16 rows, s-tiles of 64.
// V stored [s][d] (vector stores); B-fragments via ldmatrix.x4.trans.
// K/V gmem loads software-pipelined (prefetch regs during compute).
// ============================================================================
#define FBQ 128
#define FBS 64
#define FP  72                                 // padded row length (bf16 elems)
// Qh,Ql [128][72] + Kh,Kl,Vh,Vl [64][72]
#define FSMEM_BYTES ((2*FBQ*FP + 4*FBS*FP) * 2) // 73728

__global__ __launch_bounds__(256) void flash_mma_kernel(
    const float* __restrict__ Q, const float* __restrict__ Kb,
    const float* __restrict__ Vb, float* __restrict__ Ob)
{
    extern __shared__ __nv_bfloat16 fsm[];
    __nv_bfloat16* Qh = fsm;
    __nv_bfloat16* Ql = Qh + FBQ * FP;
    __nv_bfloat16* Kh = Ql + FBQ * FP;
    __nv_bfloat16* Kl = Kh + FBS * FP;
    __nv_bfloat16* Vh = Kl + FBS * FP;         // [s][d]
    __nv_bfloat16* Vl = Vh + FBS * FP;

    const uint32_t sb  = smem_u32(fsm);
    const uint32_t QhB = sb;
    const uint32_t QlB = QhB + FBQ * FP * 2;
    const uint32_t KhB = QlB + FBQ * FP * 2;
    const uint32_t KlB = KhB + FBS * FP * 2;
    const uint32_t VhB = KlB + FBS * FP * 2;
    const uint32_t VlB = VhB + FBS * FP * 2;

    const int tid  = threadIdx.x;
    const int wid  = tid >> 5;
    const int lane = tid & 31;
    const int head = blockIdx.x;                       // b*H + h
    const int qtile = (int)(gridDim.y - 1) - (int)blockIdx.y;  // heavy first
    const int b = head >> 4;
    const int h = head & 15;
    const int t0 = qtile * FBQ;

    // ---- load Q tile (128 rows x 64 d), split to bf16 hi/lo
    {
        const int r  = tid >> 1;
        const int c0 = (tid & 1) * 32;
        const float* src = Q + ((size_t)(t0 + r) * B_DIM + b) * E_DIM + h * D_HEAD + c0;
#pragma unroll
        for (int u = 0; u < 8; u++) {
            float4 v = *(const float4*)(src + u * 4);
            uint32_t h0, l0, h1, l1;
            split2(v.x, v.y, h0, l0);
            split2(v.z, v.w, h1, l1);
            *(uint2*)(Qh + r * FP + c0 + u * 4) = make_uint2(h0, h1);
            *(uint2*)(Ql + r * FP + c0 + u * 4) = make_uint2(l0, l1);
        }
    }
    __syncthreads();

    // ---- Q A-fragments (persist across all s-tiles)
    const int arow  = (lane & 7) + ((lane >> 3) & 1) * 8;
    const int akoff = (lane >> 4) * 8;
    uint32_t qah[4][4], qal[4][4];
#pragma unroll
    for (int kc = 0; kc < 4; kc++) {
        uint32_t off = ((uint32_t)(wid * 16 + arow) * FP + kc * 16 + akoff) * 2;
        LDSM_X4(qah[kc][0], qah[kc][1], qah[kc][2], qah[kc][3], QhB + off);
        LDSM_X4(qal[kc][0], qal[kc][1], qal[kc][2], qal[kc][3], QlB + off);
    }

    // ldmatrix addressing for K (non-trans x4: 2 nt-tiles x 2 k-halves)
    const int krow = (lane & 7) + ((lane >> 4) & 1) * 8;   // row within nt-pair
    const int kcol = ((lane >> 3) & 1) * 8;                // k-half
    // ldmatrix addressing for V (trans x4: rows s, 2 d-halves)
    const int vrow = lane & 15;
    const int vcol = ((lane >> 4) & 1) * 8;

    float m0 = -1e30f, m1 = -1e30f, l0 = 0.0f, l1 = 0.0f;
    float oacc[8][4];
#pragma unroll
    for (int i = 0; i < 8; i++)
#pragma unroll
        for (int t = 0; t < 4; t++) oacc[i][t] = 0.0f;

    const int wrow_min = t0 + wid * 16;
    const int wrow_max = wrow_min + 15;
    const int ntiles = 2 * qtile + 2;

    // gmem load pattern: r = tid>>2 (s row), c0 = (tid&3)*16 (d base)
    const int gr  = tid >> 2;
    const int gc0 = (tid & 3) * 16;

    // ---- prologue: prefetch tile 0 into registers
    float4 kreg[4], vreg[4];
    {
        const float* ks = Kb + ((size_t)gr * B_DIM + b) * E_DIM + h * D_HEAD + gc0;
        const float* vs = Vb + ((size_t)gr * B_DIM + b) * E_DIM + h * D_HEAD + gc0;
#pragma unroll
        for (int u = 0; u < 4; u++) {
            kreg[u] = *(const float4*)(ks + u * 4);
            vreg[u] = *(const float4*)(vs + u * 4);
        }
    }

    for (int st = 0; st < ntiles; st++) {
        const int s0 = st * FBS;

        // ---- split + store prefetched K/V regs to smem (all vectorized)
#pragma unroll
        for (int u = 0; u < 4; u++) {
            uint32_t h0, lx0, h1, lx1;
            split2(kreg[u].x, kreg[u].y, h0, lx0);
            split2(kreg[u].z, kreg[u].w, h1, lx1);
            *(uint2*)(Kh + gr * FP + gc0 + u * 4) = make_uint2(h0, h1);
            *(uint2*)(Kl + gr * FP + gc0 + u * 4) = make_uint2(lx0, lx1);
            split2(vreg[u].x, vreg[u].y, h0, lx0);
            split2(vreg[u].z, vreg[u].w, h1, lx1);
            *(uint2*)(Vh + gr * FP + gc0 + u * 4) = make_uint2(h0, h1);
            *(uint2*)(Vl + gr * FP + gc0 + u * 4) = make_uint2(lx0, lx1);
        }
        __syncthreads();

        // ---- prefetch next tile (in flight during compute)
        if (st + 1 < ntiles) {
            const int sn = (st + 1) * FBS;
            const float* ks = Kb + ((size_t)(sn + gr) * B_DIM + b) * E_DIM + h * D_HEAD + gc0;
            const float* vs = Vb + ((size_t)(sn + gr) * B_DIM + b) * E_DIM + h * D_HEAD + gc0;
#pragma unroll
            for (int u = 0; u < 4; u++) {
                kreg[u] = *(const float4*)(ks + u * 4);
                vreg[u] = *(const float4*)(vs + u * 4);
            }
        }

        if (s0 <= wrow_max) {   // warp has at least one unmasked row in this tile
            // ---- S = Q K^T (3-pass split), x4 ldmatrix (2 nt per load)
            float sacc[8][4];
#pragma unroll
            for (int i = 0; i < 8; i++)
#pragma unroll
                for (int t = 0; t < 4; t++) sacc[i][t] = 0.0f;

#pragma unroll
            for (int ntp = 0; ntp < 4; ntp++) {
#pragma unroll
                for (int kc = 0; kc < 4; kc++) {
                    uint32_t off = ((uint32_t)(ntp * 16 + krow) * FP + kc * 16 + kcol) * 2;
                    uint32_t bh[4], bl[4];
                    LDSM_X4(bh[0], bh[1], bh[2], bh[3], KhB + off);
                    LDSM_X4(bl[0], bl[1], bl[2], bl[3], KlB + off);
                    MMA_BF16_P(sacc[2*ntp],   qah[kc], bh[0], bh[1]);
                    MMA_BF16_P(sacc[2*ntp],   qah[kc], bl[0], bl[1]);
                    MMA_BF16_P(sacc[2*ntp],   qal[kc], bh[0], bh[1]);
                    MMA_BF16_P(sacc[2*ntp+1], qah[kc], bh[2], bh[3]);
                    MMA_BF16_P(sacc[2*ntp+1], qah[kc], bl[2], bl[3]);
                    MMA_BF16_P(sacc[2*ntp+1], qal[kc], bh[2], bh[3]);
                }
            }

            // ---- causal mask: needed whenever tile reaches past warp's first row
            if (s0 + FBS - 1 > wrow_min) {
                int r0g = wrow_min + (lane >> 2);
                int r1g = r0g + 8;
#pragma unroll
                for (int nt = 0; nt < 8; nt++) {
                    int c0g = s0 + nt * 8 + (lane & 3) * 2;
                    if (c0g     > r0g) sacc[nt][0] = -1e9f;
                    if (c0g + 1 > r0g) sacc[nt][1] = -1e9f;
                    if (c0g     > r1g) sacc[nt][2] = -1e9f;
                    if (c0g + 1 > r1g) sacc[nt][3] = -1e9f;
                }
            }

            // ---- online softmax (rows owned by quads; reduce via xor 1,2)
            float rmax0 = -1e30f, rmax1 = -1e30f;
#pragma unroll
            for (int nt = 0; nt < 8; nt++) {
                rmax0 = fmaxf(rmax0, fmaxf(sacc[nt][0], sacc[nt][1]));
                rmax1 = fmaxf(rmax1, fmaxf(sacc[nt][2], sacc[nt][3]));
            }
            rmax0 = fmaxf(rmax0, __shfl_xor_sync(0xffffffffu, rmax0, 1));
            rmax0 = fmaxf(rmax0, __shfl_xor_sync(0xffffffffu, rmax0, 2));
            rmax1 = fmaxf(rmax1, __shfl_xor_sync(0xffffffffu, rmax1, 1));
            rmax1 = fmaxf(rmax1, __shfl_xor_sync(0xffffffffu, rmax1, 2));

            float mn0 = fmaxf(m0, rmax0);
            float mn1 = fmaxf(m1, rmax1);
            float a0 = __expf(m0 - mn0);
            float a1 = __expf(m1 - mn1);

            float rs0 = 0.0f, rs1 = 0.0f;
            uint32_t pah[4][4], pal[4][4];
#pragma unroll
            for (int nt = 0; nt < 8; nt++) {
                float p0 = __expf(sacc[nt][0] - mn0);
                float p1 = __expf(sacc[nt][1] - mn0);
                float p2 = __expf(sacc[nt][2] - mn1);
                float p3 = __expf(sacc[nt][3] - mn1);
                rs0 += p0 + p1;
                rs1 += p2 + p3;
                int kc = nt >> 1, half = nt & 1;
                uint32_t hA, lA, hB, lB;
                split2(p0, p1, hA, lA);
                split2(p2, p3, hB, lB);
                pah[kc][half * 2 + 0] = hA; pal[kc][half * 2 + 0] = lA;
                pah[kc][half * 2 + 1] = hB; pal[kc][half * 2 + 1] = lB;
            }
            rs0 += __shfl_xor_sync(0xffffffffu, rs0, 1);
            rs0 += __shfl_xor_sync(0xffffffffu, rs0, 2);
            rs1 += __shfl_xor_sync(0xffffffffu, rs1, 1);
            rs1 += __shfl_xor_sync(0xffffffffu, rs1, 2);

            l0 = l0 * a0 + rs0;
            l1 = l1 * a1 + rs1;
            m0 = mn0; m1 = mn1;

            // ---- rescale running O
#pragma unroll
            for (int dt = 0; dt < 8; dt++) {
                oacc[dt][0] *= a0; oacc[dt][1] *= a0;
                oacc[dt][2] *= a1; oacc[dt][3] *= a1;
            }

            // ---- O += P V (3-pass), V[s][d] via trans x4 ldmatrix (2 dt per load)
#pragma unroll
            for (int dtp = 0; dtp < 4; dtp++) {
#pragma unroll
                for (int kc = 0; kc < 4; kc++) {
                    uint32_t off = ((uint32_t)(kc * 16 + vrow) * FP + dtp * 16 + vcol) * 2;
                    uint32_t vh[4], vl[4];
                    LDSM_X4_TRANS(vh[0], vh[1], vh[2], vh[3], VhB + off);
                    LDSM_X4_TRANS(vl[0], vl[1], vl[2], vl[3], VlB + off);
                    MMA_BF16_P(oacc[2*dtp],   pah[kc], vh[0], vh[1]);
                    MMA_BF16_P(oacc[2*dtp],   pah[kc], vl[0], vl[1]);
                    MMA_BF16_P(oacc[2*dtp],   pal[kc], vh[0], vh[1]);
                    MMA_BF16_P(oacc[2*dtp+1], pah[kc], vh[2], vh[3]);
                    MMA_BF16_P(oacc[2*dtp+1], pah[kc], vl[2], vl[3]);
                    MMA_BF16_P(oacc[2*dtp+1], pal[kc], vh[2], vh[3]);
                }
            }
        }
        __syncthreads();
    }

    // ---- normalize + write
    float inv0 = 1.0f / l0;
    float inv1 = 1.0f / l1;
    int r0g = t0 + wid * 16 + (lane >> 2);
#pragma unroll
    for (int dt = 0; dt < 8; dt++) {
        int col = h * D_HEAD + dt * 8 + (lane & 3) * 2;
        *(float2*)(Ob + ((size_t)r0g * B_DIM + b) * E_DIM + col) =
            make_float2(oacc[dt][0] * inv0, oacc[dt][1] * inv0);
        *(float2*)(Ob + ((size_t)(r0g + 8) * B_DIM + b) * E_DIM + col) =
            make_float2(oacc[dt][2] * inv1, oacc[dt][3] * inv1);
    }
}

// ============================================================================
extern "C" void kernel_launch(void* const* d_in, const int* in_sizes, int n_in,
                              void* d_out, int out_size)
{
    const float* query = (const float*)d_in[0];
    const float* key   = (const float*)d_in[1];
    const float* value = (const float*)d_in[2];
    // d_in[3] = attn_mask (pure causal; applied analytically)
    const float* wq = (const float*)d_in[4];
    const float* bq = (const float*)d_in[5];
    const float* wk = (const float*)d_in[6];
    const float* bk = (const float*)d_in[7];
    const float* wv = (const float*)d_in[8];
    const float* bv = (const float*)d_in[9];
    const float* wo = (const float*)d_in[10];
    const float* bo = (const float*)d_in[11];
    float* out = (float*)d_out;

    float *qp, *kp, *vp, *ap;
    cudaGetSymbolAddress((void**)&qp, g_q);
    cudaGetSymbolAddress((void**)&kp, g_k);
    cudaGetSymbolAddress((void**)&vp, g_v);
    cudaGetSymbolAddress((void**)&ap, g_attn);

    cudaFuncSetAttribute(bf16x3_gemm_kernel,
                         cudaFuncAttributeMaxDynamicSharedMemorySize, GSMEM_BYTES);
    dim3 gGrid(E_DIM / 128, MROWS / 128);   // (8, 64)
    const float scaling = 0.125f;           // D^-0.5

    bf16x3_gemm_kernel<<<gGrid, 256, GSMEM_BYTES>>>(query, wq, bq, qp, scaling);
    bf16x3_gemm_kernel<<<gGrid, 256, GSMEM_BYTES>>>(key,   wk, bk, kp, 1.0f);
    bf16x3_gemm_kernel<<<gGrid, 256, GSMEM_BYTES>>>(value, wv, bv, vp, 1.0f);

    cudaFuncSetAttribute(flash_mma_kernel,
                         cudaFuncAttributeMaxDynamicSharedMemorySize, FSMEM_BYTES);
    dim3 fGrid(B_DIM * H_DIM, T_DIM / FBQ);  // (64 heads, 16 qtiles)
    flash_mma_kernel<<<fGrid, 256, FSMEM_BYTES>>>(qp, kp, vp, ap);

    bf16x3_gemm_kernel<<<gGrid, 256, GSMEM_BYTES>>>(ap, wo, bo, out, 1.0f);
}

// round 7
// speedup vs baseline: 3.2188x; 1.0973x over previous
#include <cuda_runtime.h>
#include <cuda_bf16.h>
#include <cstdint>

// Problem constants (fixed by the dataset)
#define T_DIM   2048
#define B_DIM   4
#define E_DIM   1024
#define H_DIM   16
#define D_HEAD  64
#define MROWS   (T_DIM * B_DIM)           // 8192
#define ASLOT   ((size_t)MROWS * E_DIM)   // 8M elems per activation slot
#define WSLOT   ((size_t)E_DIM * E_DIM)   // 1M elems per weight slot

// bf16 hi/lo scratch. Activation slots: 0=query/attn_out, 1=key, 2=value,
// 3=q_proj, 4=k_proj, 5=v_proj. Weight slots: 0=wq 1=wk 2=wv 3=wo.
__device__ __align__(256) __nv_bfloat16 g_bh[6 * ASLOT];
__device__ __align__(256) __nv_bfloat16 g_bl[6 * ASLOT];
__device__ __align__(256) __nv_bfloat16 g_wh[4 * WSLOT];
__device__ __align__(256) __nv_bfloat16 g_wl[4 * WSLOT];

// ============================================================================
// helpers
// ============================================================================
__device__ __forceinline__ uint32_t smem_u32(const void* p) {
    uint32_t a;
    asm("{ .reg .u64 t; cvta.to.shared.u64 t, %1; cvt.u32.u64 %0, t; }"
        : "=r"(a) : "l"(p));
    return a;
}

#define CP16(smem, gptr) \
    asm volatile("cp.async.cg.shared.global [%0], [%1], 16;" :: "r"(smem), "l"(gptr))
#define CP_COMMIT() asm volatile("cp.async.commit_group;" ::: "memory")
#define CP_WAIT0()  asm volatile("cp.async.wait_group 0;" ::: "memory")

#define LDSM_X4(r0, r1, r2, r3, addr) \
    asm volatile("ldmatrix.sync.aligned.m8n8.x4.shared.b16 {%0,%1,%2,%3}, [%4];" \
                 : "=r"(r0), "=r"(r1), "=r"(r2), "=r"(r3) : "r"(addr))
#define LDSM_X4_TRANS(r0, r1, r2, r3, addr) \
    asm volatile("ldmatrix.sync.aligned.m8n8.x4.trans.shared.b16 {%0,%1,%2,%3}, [%4];" \
                 : "=r"(r0), "=r"(r1), "=r"(r2), "=r"(r3) : "r"(addr))
#define MMA_BF16_P(d, a, b0, b1) \
    asm volatile("mma.sync.aligned.m16n8k16.row.col.f32.bf16.bf16.f32 " \
                 "{%0,%1,%2,%3}, {%4,%5,%6,%7}, {%8,%9}, {%0,%1,%2,%3};" \
                 : "+f"((d)[0]), "+f"((d)[1]), "+f"((d)[2]), "+f"((d)[3]) \
                 : "r"((a)[0]), "r"((a)[1]), "r"((a)[2]), "r"((a)[3]), \
                   "r"(b0), "r"(b1))

// pack 2 floats -> hi/lo bf16 pairs (split-bf16; x in low half)
__device__ __forceinline__ void split2(float x, float y, uint32_t& hi, uint32_t& lo) {
    __nv_bfloat16 hx = __float2bfloat16(x);
    __nv_bfloat16 hy = __float2bfloat16(y);
    __nv_bfloat16 lx = __float2bfloat16(x - __bfloat162float(hx));
    __nv_bfloat16 ly = __float2bfloat16(y - __bfloat162float(hy));
    __nv_bfloat162 h2 = __halves2bfloat162(hx, hy);
    __nv_bfloat162 l2 = __halves2bfloat162(lx, ly);
    hi = *reinterpret_cast<uint32_t*>(&h2);
    lo = *reinterpret_cast<uint32_t*>(&l2);
}

// ============================================================================
// Pre-split kernels: fp32 -> bf16 hi/lo
// ============================================================================
__global__ __launch_bounds__(256) void split_acts_kernel(
    const float* __restrict__ q, const float* __restrict__ k,
    const float* __restrict__ v,
    __nv_bfloat16* __restrict__ bh, __nv_bfloat16* __restrict__ bl)
{
    const int z = blockIdx.z;
    const float* src = (z == 0) ? q : (z == 1) ? k : v;
    size_t i = (size_t)blockIdx.x * 256 + threadIdx.x;   // float4 index
    float4 val = ((const float4*)src)[i];
    uint32_t h0, l0, h1, l1;
    split2(val.x, val.y, h0, l0);
    split2(val.z, val.w, h1, l1);
    size_t base = (size_t)z * ASLOT + i * 4;
    *(uint2*)(bh + base) = make_uint2(h0, h1);
    *(uint2*)(bl + base) = make_uint2(l0, l1);
}

__global__ __launch_bounds__(256) void split_w_kernel(
    const float* __restrict__ w0, const float* __restrict__ w1,
    const float* __restrict__ w2, const float* __restrict__ w3,
    __nv_bfloat16* __restrict__ wh, __nv_bfloat16* __restrict__ wl)
{
    const int z = blockIdx.z;
    const float* src = (z == 0) ? w0 : (z == 1) ? w1 : (z == 2) ? w2 : w3;
    size_t i = (size_t)blockIdx.x * 256 + threadIdx.x;
    float4 val = ((const float4*)src)[i];
    uint32_t h0, l0, h1, l1;
    split2(val.x, val.y, h0, l0);
    split2(val.z, val.w, h1, l1);
    size_t base = (size_t)z * WSLOT + i * 4;
    *(uint2*)(wh + base) = make_uint2(h0, h1);
    *(uint2*)(wl + base) = make_uint2(l0, l1);
}

// ============================================================================
// bf16 (pre-split) GEMM: C[m,n] = (sum_k A[m,k]*W[n,k] + bias[n]) * scale
// CTA 128x128, 8 warps (2m x 4n, each 64x32), KC=32, cp.async double buffer,
// ONE barrier per chunk. 3 mma passes: hh + hl + lh.
// ============================================================================
#define KC   32
#define SA   40
#define MATB (128 * SA * 2)          // 10240 bytes per matrix tile
#define BUF_BYTES (4 * MATB)         // 40960
#define GSMEM_BYTES (2 * BUF_BYTES)  // 81920

template <bool F32OUT>
__device__ __forceinline__ void gemm_body(
    const __nv_bfloat16* __restrict__ Ah, const __nv_bfloat16* __restrict__ Al,
    const __nv_bfloat16* __restrict__ Wh, const __nv_bfloat16* __restrict__ Wl,
    const float* __restrict__ bias, float scale,
    __nv_bfloat16* __restrict__ Ch, __nv_bfloat16* __restrict__ Cl,
    float* __restrict__ Cf)
{
    extern __shared__ __nv_bfloat16 gsm[];
    const uint32_t sbase = smem_u32(gsm);
    const int tid  = threadIdx.x;
    const int wid  = tid >> 5;
    const int lane = tid & 31;
    const int m0 = blockIdx.y * 128;
    const int n0 = blockIdx.x * 128;
    const int wm = (wid >> 2) * 64;
    const int wn = (wid & 3) * 32;

    // cp.async load mapping: row cr (0..127), segs cs, cs+1 (16B each)
    const int cr = tid >> 1;
    const int cs = (tid & 1) * 2;
    const uint32_t sOff = ((uint32_t)cr * SA + cs * 8) * 2;
    const size_t gA = (size_t)(m0 + cr) * E_DIM + cs * 8;
    const size_t gW = (size_t)(n0 + cr) * E_DIM + cs * 8;

#define GEMM_ISSUE(c, b) do {                                            \
    uint32_t sd = sbase + (uint32_t)(b) * BUF_BYTES + sOff;              \
    const __nv_bfloat16* g;                                              \
    g = Ah + gA + (c) * KC; CP16(sd,            g); CP16(sd + 16,            g + 8); \
    g = Al + gA + (c) * KC; CP16(sd + MATB,     g); CP16(sd + MATB + 16,     g + 8); \
    g = Wh + gW + (c) * KC; CP16(sd + 2 * MATB, g); CP16(sd + 2 * MATB + 16, g + 8); \
    g = Wl + gW + (c) * KC; CP16(sd + 3 * MATB, g); CP16(sd + 3 * MATB + 16, g + 8); \
    CP_COMMIT();                                                         \
} while (0)

    // fragment addressing
    const int arow  = (lane & 7) + ((lane >> 3) & 1) * 8;
    const int akoff = (lane >> 4) * 8;
    const int brow4 = (lane & 7) + ((lane >> 4) & 1) * 8;
    const int bk4   = ((lane >> 3) & 1) * 8;

    float acc[4][4][4];
#pragma unroll
    for (int i = 0; i < 4; i++)
#pragma unroll
        for (int j = 0; j < 4; j++)
#pragma unroll
            for (int t = 0; t < 4; t++) acc[i][j][t] = 0.0f;

    GEMM_ISSUE(0, 0);
    CP_WAIT0();
    __syncthreads();

    const int NC = E_DIM / KC;   // 32
    for (int c = 0; c < NC; c++) {
        if (c + 1 < NC) GEMM_ISSUE(c + 1, (c + 1) & 1);

        const uint32_t bufb = sbase + (uint32_t)(c & 1) * BUF_BYTES;
#pragma unroll
        for (int kk = 0; kk < 2; kk++) {
            uint32_t ah[4][4], al[4][4];
#pragma unroll
            for (int ma = 0; ma < 4; ma++) {
                uint32_t off = ((uint32_t)(wm + ma * 16 + arow) * SA + kk * 16 + akoff) * 2;
                LDSM_X4(ah[ma][0], ah[ma][1], ah[ma][2], ah[ma][3], bufb + off);
                LDSM_X4(al[ma][0], al[ma][1], al[ma][2], al[ma][3], bufb + MATB + off);
            }
#pragma unroll
            for (int nap = 0; nap < 2; nap++) {
                uint32_t off = ((uint32_t)(wn + nap * 16 + brow4) * SA + kk * 16 + bk4) * 2;
                uint32_t bh[4], bl[4];
                LDSM_X4(bh[0], bh[1], bh[2], bh[3], bufb + 2 * MATB + off);
                LDSM_X4(bl[0], bl[1], bl[2], bl[3], bufb + 3 * MATB + off);
#pragma unroll
                for (int ma = 0; ma < 4; ma++) {
                    MMA_BF16_P(acc[ma][2 * nap],     ah[ma], bh[0], bh[1]);
                    MMA_BF16_P(acc[ma][2 * nap],     ah[ma], bl[0], bl[1]);
                    MMA_BF16_P(acc[ma][2 * nap],     al[ma], bh[0], bh[1]);
                    MMA_BF16_P(acc[ma][2 * nap + 1], ah[ma], bh[2], bh[3]);
                    MMA_BF16_P(acc[ma][2 * nap + 1], ah[ma], bl[2], bl[3]);
                    MMA_BF16_P(acc[ma][2 * nap + 1], al[ma], bh[2], bh[3]);
                }
            }
        }
        CP_WAIT0();
        __syncthreads();
    }
#undef GEMM_ISSUE

    // epilogue
    const int erow = lane >> 2;
    const int ecol = (lane & 3) * 2;
#pragma unroll
    for (int na = 0; na < 4; na++) {
        int col = n0 + wn + na * 8 + ecol;
        float b0 = bias[col], b1 = bias[col + 1];
#pragma unroll
        for (int ma = 0; ma < 4; ma++) {
            int row = m0 + wm + ma * 16 + erow;
            float v00 = (acc[ma][na][0] + b0) * scale;
            float v01 = (acc[ma][na][1] + b1) * scale;
            float v10 = (acc[ma][na][2] + b0) * scale;
            float v11 = (acc[ma][na][3] + b1) * scale;
            if (F32OUT) {
                *(float2*)(Cf + (size_t)row * E_DIM + col) = make_float2(v00, v01);
                *(float2*)(Cf + (size_t)(row + 8) * E_DIM + col) = make_float2(v10, v11);
            } else {
                uint32_t hh, ll;
                split2(v00, v01, hh, ll);
                *(uint32_t*)(Ch + (size_t)row * E_DIM + col) = hh;
                *(uint32_t*)(Cl + (size_t)row * E_DIM + col) = ll;
                split2(v10, v11, hh, ll);
                *(uint32_t*)(Ch + (size_t)(row + 8) * E_DIM + col) = hh;
                *(uint32_t*)(Cl + (size_t)(row + 8) * E_DIM + col) = ll;
            }
        }
    }
}

// merged q/k/v projection (gridDim.z = 3), bf16 hi/lo outputs into slots 3..5
__global__ __launch_bounds__(256, 2) void qkv_gemm_kernel(
    const __nv_bfloat16* __restrict__ actH, const __nv_bfloat16* __restrict__ actL,
    const __nv_bfloat16* __restrict__ wH,   const __nv_bfloat16* __restrict__ wL,
    const float* __restrict__ bq, const float* __restrict__ bk,
    const float* __restrict__ bv,
    __nv_bfloat16* __restrict__ outH, __nv_bfloat16* __restrict__ outL)
{
    const int z = blockIdx.z;
    const float* bias = (z == 0) ? bq : (z == 1) ? bk : bv;
    const float scale = (z == 0) ? 0.125f : 1.0f;
    gemm_body<false>(actH + (size_t)z * ASLOT, actL + (size_t)z * ASLOT,
                     wH + (size_t)z * WSLOT,   wL + (size_t)z * WSLOT,
                     bias, scale,
                     outH + (size_t)(z + 3) * ASLOT,
                     outL + (size_t)(z + 3) * ASLOT, nullptr);
}

// output projection, fp32 out
__global__ __launch_bounds__(256, 2) void out_gemm_kernel(
    const __nv_bfloat16* __restrict__ Ah, const __nv_bfloat16* __restrict__ Al,
    const __nv_bfloat16* __restrict__ Wh, const __nv_bfloat16* __restrict__ Wl,
    const float* __restrict__ bias, float* __restrict__ Cf)
{
    gemm_body<true>(Ah, Al, Wh, Wl, bias, 1.0f, nullptr, nullptr, Cf);
}

// ============================================================================
// Flash attention on tensor cores (split-bf16, 3-pass), causal.
// Inputs already bf16 hi/lo. cp.async double-buffered K/V, ONE barrier/tile.
// Output written as bf16 hi/lo (consumed by out projection).
// ============================================================================
#define FBQ 128
#define FBS 64
#define FP  72
#define QMATB (FBQ * FP * 2)                    // 18432
#define KVMATB (FBS * FP * 2)                   // 9216
#define KVBUF (4 * KVMATB)                      // 36864
#define FSMEM_BYTES (2 * QMATB + 2 * KVBUF)     // 110592

__global__ __launch_bounds__(256) void flash_mma_kernel(
    const __nv_bfloat16* __restrict__ Qh_g, const __nv_bfloat16* __restrict__ Ql_g,
    const __nv_bfloat16* __restrict__ Kh_g, const __nv_bfloat16* __restrict__ Kl_g,
    const __nv_bfloat16* __restrict__ Vh_g, const __nv_bfloat16* __restrict__ Vl_g,
    __nv_bfloat16* __restrict__ Oh_g, __nv_bfloat16* __restrict__ Ol_g)
{
    extern __shared__ __nv_bfloat16 fsm[];
    const uint32_t sb  = smem_u32(fsm);
    const uint32_t QhB = sb;
    const uint32_t QlB = sb + QMATB;
    const uint32_t KV0 = sb + 2 * QMATB;         // buf b at KV0 + b*KVBUF
    // within buf: Kh, Kl, Vh, Vl each KVMATB

    const int tid  = threadIdx.x;
    const int wid  = tid >> 5;
    const int lane = tid & 31;
    const int head = blockIdx.x;                       // b*H + h
    const int qtile = (int)(gridDim.y - 1) - (int)blockIdx.y;  // heavy first
    const int b = head >> 4;
    const int h = head & 15;
    const int t0 = qtile * FBQ;

    // cp.async mappings
    const int qr = tid >> 1;              // 0..127
    const int qc = (tid & 1) * 32;        // col base (bf16)
    const int kr = tid >> 2;              // 0..63
    const int kc = (tid & 3) * 16;        // col base (bf16)

    const size_t qrow = ((size_t)(t0 + qr) * B_DIM + b) * E_DIM + h * D_HEAD + qc;
    const size_t krowbase = (size_t)B_DIM * E_DIM;   // stride per s
    const size_t kcol0 = (size_t)b * E_DIM + h * D_HEAD + kc;

#define FLASH_ISSUE_KV(s0v, bufb_) do {                                            \
    uint32_t bufb = KV0 + (uint32_t)(bufb_) * KVBUF + ((uint32_t)kr * FP + kc) * 2; \
    size_t g = (size_t)((s0v) + kr) * krowbase + kcol0;                            \
    CP16(bufb,                  Kh_g + g); CP16(bufb + 16,              Kh_g + g + 8); \
    CP16(bufb + KVMATB,         Kl_g + g); CP16(bufb + KVMATB + 16,     Kl_g + g + 8); \
    CP16(bufb + 2 * KVMATB,     Vh_g + g); CP16(bufb + 2 * KVMATB + 16, Vh_g + g + 8); \
    CP16(bufb + 3 * KVMATB,     Vl_g + g); CP16(bufb + 3 * KVMATB + 16, Vl_g + g + 8); \
    CP_COMMIT();                                                                   \
} while (0)

    // ---- prologue: Q + tile0 in flight
    {
        uint32_t sq = QhB + ((uint32_t)qr * FP + qc) * 2;
#pragma unroll
        for (int u = 0; u < 4; u++) {
            CP16(sq + u * 16,         Qh_g + qrow + u * 8);
            CP16(sq + QMATB + u * 16, Ql_g + qrow + u * 8);
        }
    }
    FLASH_ISSUE_KV(0, 0);
    CP_WAIT0();
    __syncthreads();

    // ---- Q A-fragments (persist across all s-tiles)
    const int arow  = (lane & 7) + ((lane >> 3) & 1) * 8;
    const int akoff = (lane >> 4) * 8;
    uint32_t qah[4][4], qal[4][4];
#pragma unroll
    for (int kcn = 0; kcn < 4; kcn++) {
        uint32_t off = ((uint32_t)(wid * 16 + arow) * FP + kcn * 16 + akoff) * 2;
        LDSM_X4(qah[kcn][0], qah[kcn][1], qah[kcn][2], qah[kcn][3], QhB + off);
        LDSM_X4(qal[kcn][0], qal[kcn][1], qal[kcn][2], qal[kcn][3], QlB + off);
    }

    // K (non-trans x4) / V (trans x4) fragment addressing
    const int krow4 = (lane & 7) + ((lane >> 4) & 1) * 8;
    const int kcol4 = ((lane >> 3) & 1) * 8;
    const int vrow  = lane & 15;
    const int vcol  = ((lane >> 4) & 1) * 8;

    float m0 = -1e30f, m1 = -1e30f, l0 = 0.0f, l1 = 0.0f;
    float oacc[8][4];
#pragma unroll
    for (int i = 0; i < 8; i++)
#pragma unroll
        for (int t = 0; t < 4; t++) oacc[i][t] = 0.0f;

    const int wrow_min = t0 + wid * 16;
    const int wrow_max = wrow_min + 15;
    const int ntiles = 2 * qtile + 2;

    for (int st = 0; st < ntiles; st++) {
        const int s0 = st * FBS;
        if (st + 1 < ntiles) FLASH_ISSUE_KV(s0 + FBS, (st + 1) & 1);

        if (s0 <= wrow_max) {
            const uint32_t KhB = KV0 + (uint32_t)(st & 1) * KVBUF;
            const uint32_t KlB = KhB + KVMATB;
            const uint32_t VhB = KhB + 2 * KVMATB;
            const uint32_t VlB = KhB + 3 * KVMATB;

            // ---- S = Q K^T (3-pass split)
            float sacc[8][4];
#pragma unroll
            for (int i = 0; i < 8; i++)
#pragma unroll
                for (int t = 0; t < 4; t++) sacc[i][t] = 0.0f;

#pragma unroll
            for (int ntp = 0; ntp < 4; ntp++) {
#pragma unroll
                for (int kcn = 0; kcn < 4; kcn++) {
                    uint32_t off = ((uint32_t)(ntp * 16 + krow4) * FP + kcn * 16 + kcol4) * 2;
                    uint32_t bh[4], bl[4];
                    LDSM_X4(bh[0], bh[1], bh[2], bh[3], KhB + off);
                    LDSM_X4(bl[0], bl[1], bl[2], bl[3], KlB + off);
                    MMA_BF16_P(sacc[2 * ntp],     qah[kcn], bh[0], bh[1]);
                    MMA_BF16_P(sacc[2 * ntp],     qah[kcn], bl[0], bl[1]);
                    MMA_BF16_P(sacc[2 * ntp],     qal[kcn], bh[0], bh[1]);
                    MMA_BF16_P(sacc[2 * ntp + 1], qah[kcn], bh[2], bh[3]);
                    MMA_BF16_P(sacc[2 * ntp + 1], qah[kcn], bl[2], bl[3]);
                    MMA_BF16_P(sacc[2 * ntp + 1], qal[kcn], bh[2], bh[3]);
                }
            }

            // ---- causal mask (whenever tile reaches past warp's first row)
            if (s0 + FBS - 1 > wrow_min) {
                int r0g = wrow_min + (lane >> 2);
                int r1g = r0g + 8;
#pragma unroll
                for (int nt = 0; nt < 8; nt++) {
                    int c0g = s0 + nt * 8 + (lane & 3) * 2;
                    if (c0g     > r0g) sacc[nt][0] = -1e9f;
                    if (c0g + 1 > r0g) sacc[nt][1] = -1e9f;
                    if (c0g     > r1g) sacc[nt][2] = -1e9f;
                    if (c0g + 1 > r1g) sacc[nt][3] = -1e9f;
                }
            }

            // ---- online softmax
            float rmax0 = -1e30f, rmax1 = -1e30f;
#pragma unroll
            for (int nt = 0; nt < 8; nt++) {
                rmax0 = fmaxf(rmax0, fmaxf(sacc[nt][0], sacc[nt][1]));
                rmax1 = fmaxf(rmax1, fmaxf(sacc[nt][2], sacc[nt][3]));
            }
            rmax0 = fmaxf(rmax0, __shfl_xor_sync(0xffffffffu, rmax0, 1));
            rmax0 = fmaxf(rmax0, __shfl_xor_sync(0xffffffffu, rmax0, 2));
            rmax1 = fmaxf(rmax1, __shfl_xor_sync(0xffffffffu, rmax1, 1));
            rmax1 = fmaxf(rmax1, __shfl_xor_sync(0xffffffffu, rmax1, 2));

            float mn0 = fmaxf(m0, rmax0);
            float mn1 = fmaxf(m1, rmax1);
            float a0 = __expf(m0 - mn0);
            float a1 = __expf(m1 - mn1);

            float rs0 = 0.0f, rs1 = 0.0f;
            uint32_t pah[4][4], pal[4][4];
#pragma unroll
            for (int nt = 0; nt < 8; nt++) {
                float p0 = __expf(sacc[nt][0] - mn0);
                float p1 = __expf(sacc[nt][1] - mn0);
                float p2 = __expf(sacc[nt][2] - mn1);
                float p3 = __expf(sacc[nt][3] - mn1);
                rs0 += p0 + p1;
                rs1 += p2 + p3;
                int kcn = nt >> 1, half = nt & 1;
                uint32_t hA, lA, hB, lB;
                split2(p0, p1, hA, lA);
                split2(p2, p3, hB, lB);
                pah[kcn][half * 2 + 0] = hA; pal[kcn][half * 2 + 0] = lA;
                pah[kcn][half * 2 + 1] = hB; pal[kcn][half * 2 + 1] = lB;
            }
            rs0 += __shfl_xor_sync(0xffffffffu, rs0, 1);
            rs0 += __shfl_xor_sync(0xffffffffu, rs0, 2);
            rs1 += __shfl_xor_sync(0xffffffffu, rs1, 1);
            rs1 += __shfl_xor_sync(0xffffffffu, rs1, 2);

            l0 = l0 * a0 + rs0;
            l1 = l1 * a1 + rs1;
            m0 = mn0; m1 = mn1;

#pragma unroll
            for (int dt = 0; dt < 8; dt++) {
                oacc[dt][0] *= a0; oacc[dt][1] *= a0;
                oacc[dt][2] *= a1; oacc[dt][3] *= a1;
            }

            // ---- O += P V (3-pass), V[s][d] via trans x4
#pragma unroll
            for (int dtp = 0; dtp < 4; dtp++) {
#pragma unroll
                for (int kcn = 0; kcn < 4; kcn++) {
                    uint32_t off = ((uint32_t)(kcn * 16 + vrow) * FP + dtp * 16 + vcol) * 2;
                    uint32_t vh[4], vl[4];
                    LDSM_X4_TRANS(vh[0], vh[1], vh[2], vh[3], VhB + off);
                    LDSM_X4_TRANS(vl[0], vl[1], vl[2], vl[3], VlB + off);
                    MMA_BF16_P(oacc[2 * dtp],     pah[kcn], vh[0], vh[1]);
                    MMA_BF16_P(oacc[2 * dtp],     pah[kcn], vl[0], vl[1]);
                    MMA_BF16_P(oacc[2 * dtp],     pal[kcn], vh[0], vh[1]);
                    MMA_BF16_P(oacc[2 * dtp + 1], pah[kcn], vh[2], vh[3]);
                    MMA_BF16_P(oacc[2 * dtp + 1], pah[kcn], vl[2], vl[3]);
                    MMA_BF16_P(oacc[2 * dtp + 1], pal[kcn], vh[2], vh[3]);
                }
            }
        }
        CP_WAIT0();
        __syncthreads();
    }
#undef FLASH_ISSUE_KV

    // ---- normalize + write split bf16 (consumed by out-projection GEMM)
    float inv0 = 1.0f / l0;
    float inv1 = 1.0f / l1;
    int r0g = t0 + wid * 16 + (lane >> 2);
    size_t row0 = ((size_t)r0g * B_DIM + b) * E_DIM;
    size_t row1 = ((size_t)(r0g + 8) * B_DIM + b) * E_DIM;
#pragma unroll
    for (int dt = 0; dt < 8; dt++) {
        int col = h * D_HEAD + dt * 8 + (lane & 3) * 2;
        uint32_t hh, ll;
        split2(oacc[dt][0] * inv0, oacc[dt][1] * inv0, hh, ll);
        *(uint32_t*)(Oh_g + row0 + col) = hh;
        *(uint32_t*)(Ol_g + row0 + col) = ll;
        split2(oacc[dt][2] * inv1, oacc[dt][3] * inv1, hh, ll);
        *(uint32_t*)(Oh_g + row1 + col) = hh;
        *(uint32_t*)(Ol_g + row1 + col) = ll;
    }
}

// ============================================================================
extern "C" void kernel_launch(void* const* d_in, const int* in_sizes, int n_in,
                              void* d_out, int out_size)
{
    const float* query = (const float*)d_in[0];
    const float* key   = (const float*)d_in[1];
    const float* value = (const float*)d_in[2];
    // d_in[3] = attn_mask (pure causal; applied analytically)
    const float* wq = (const float*)d_in[4];
    const float* bq = (const float*)d_in[5];
    const float* wk = (const float*)d_in[6];
    const float* bk = (const float*)d_in[7];
    const float* wv = (const float*)d_in[8];
    const float* bv = (const float*)d_in[9];
    const float* wo = (const float*)d_in[10];
    const float* bo = (const float*)d_in[11];
    float* out = (float*)d_out;

    __nv_bfloat16 *bh, *bl, *wh, *wl;
    cudaGetSymbolAddress((void**)&bh, g_bh);
    cudaGetSymbolAddress((void**)&bl, g_bl);
    cudaGetSymbolAddress((void**)&wh, g_wh);
    cudaGetSymbolAddress((void**)&wl, g_wl);

    // 1. pre-split weights + input activations to bf16 hi/lo
    split_acts_kernel<<<dim3(MROWS * E_DIM / 4 / 256, 1, 3), 256>>>(
        query, key, value, bh, bl);
    split_w_kernel<<<dim3(E_DIM * E_DIM / 4 / 256, 1, 4), 256>>>(
        wq, wk, wv, wo, wh, wl);

    // 2. merged q/k/v projections (bf16 hi/lo out, slots 3..5)
    cudaFuncSetAttribute(qkv_gemm_kernel,
                         cudaFuncAttributeMaxDynamicSharedMemorySize, GSMEM_BYTES);
    qkv_gemm_kernel<<<dim3(8, 64, 3), 256, GSMEM_BYTES>>>(
        bh, bl, wh, wl, bq, bk, bv, bh, bl);

    // 3. causal flash attention (reads slots 3..5, writes slot 0)
    cudaFuncSetAttribute(flash_mma_kernel,
                         cudaFuncAttributeMaxDynamicSharedMemorySize, FSMEM_BYTES);
    flash_mma_kernel<<<dim3(B_DIM * H_DIM, T_DIM / FBQ), 256, FSMEM_BYTES>>>(
        bh + 3 * ASLOT, bl + 3 * ASLOT,
        bh + 4 * ASLOT, bl + 4 * ASLOT,
        bh + 5 * ASLOT, bl + 5 * ASLOT,
        bh, bl);

    // 4. output projection (fp32 out)
    cudaFuncSetAttribute(out_gemm_kernel,
                         cudaFuncAttributeMaxDynamicSharedMemorySize, GSMEM_BYTES);
    out_gemm_kernel<<<dim3(8, 64), 256, GSMEM_BYTES>>>(
        bh, bl, wh + 3 * WSLOT, wl + 3 * WSLOT, bo, out);
}

// round 8
// speedup vs baseline: 3.3699x; 1.0469x over previous
#include <cuda_runtime.h>
#include <cuda_bf16.h>
#include <cstdint>

// Problem constants (fixed by the dataset)
#define T_DIM   2048
#define B_DIM   4
#define E_DIM   1024
#define H_DIM   16
#define D_HEAD  64
#define MROWS   (T_DIM * B_DIM)           // 8192
#define ASLOT   ((size_t)MROWS * E_DIM)   // 8M elems per activation slot
#define WSLOT   ((size_t)E_DIM * E_DIM)   // 1M elems per weight slot

// bf16 hi/lo scratch. Activation slots: 0=query/attn_out, 1=key, 2=value,
// 3=q_proj, 4=k_proj, 5=v_proj. Weight slots: 0=wq 1=wk 2=wv 3=wo.
__device__ __align__(256) __nv_bfloat16 g_bh[6 * ASLOT];
__device__ __align__(256) __nv_bfloat16 g_bl[6 * ASLOT];
__device__ __align__(256) __nv_bfloat16 g_wh[4 * WSLOT];
__device__ __align__(256) __nv_bfloat16 g_wl[4 * WSLOT];

// ============================================================================
// helpers
// ============================================================================
__device__ __forceinline__ uint32_t smem_u32(const void* p) {
    uint32_t a;
    asm("{ .reg .u64 t; cvta.to.shared.u64 t, %1; cvt.u32.u64 %0, t; }"
        : "=r"(a) : "l"(p));
    return a;
}

#define CP16(smem, gptr) \
    asm volatile("cp.async.cg.shared.global [%0], [%1], 16;" :: "r"(smem), "l"(gptr))
#define CP_COMMIT() asm volatile("cp.async.commit_group;" ::: "memory")
#define CP_WAIT0()  asm volatile("cp.async.wait_group 0;" ::: "memory")

#define LDSM_X4(r0, r1, r2, r3, addr) \
    asm volatile("ldmatrix.sync.aligned.m8n8.x4.shared.b16 {%0,%1,%2,%3}, [%4];" \
                 : "=r"(r0), "=r"(r1), "=r"(r2), "=r"(r3) : "r"(addr))
#define LDSM_X4_TRANS(r0, r1, r2, r3, addr) \
    asm volatile("ldmatrix.sync.aligned.m8n8.x4.trans.shared.b16 {%0,%1,%2,%3}, [%4];" \
                 : "=r"(r0), "=r"(r1), "=r"(r2), "=r"(r3) : "r"(addr))
#define MMA_BF16_P(d, a, b0, b1) \
    asm volatile("mma.sync.aligned.m16n8k16.row.col.f32.bf16.bf16.f32 " \
                 "{%0,%1,%2,%3}, {%4,%5,%6,%7}, {%8,%9}, {%0,%1,%2,%3};" \
                 : "+f"((d)[0]), "+f"((d)[1]), "+f"((d)[2]), "+f"((d)[3]) \
                 : "r"((a)[0]), "r"((a)[1]), "r"((a)[2]), "r"((a)[3]), \
                   "r"(b0), "r"(b1))

// pack 2 floats -> hi/lo bf16 pairs (split-bf16; x in low half)
__device__ __forceinline__ void split2(float x, float y, uint32_t& hi, uint32_t& lo) {
    __nv_bfloat16 hx = __float2bfloat16(x);
    __nv_bfloat16 hy = __float2bfloat16(y);
    __nv_bfloat16 lx = __float2bfloat16(x - __bfloat162float(hx));
    __nv_bfloat16 ly = __float2bfloat16(y - __bfloat162float(hy));
    __nv_bfloat162 h2 = __halves2bfloat162(hx, hy);
    __nv_bfloat162 l2 = __halves2bfloat162(lx, ly);
    hi = *reinterpret_cast<uint32_t*>(&h2);
    lo = *reinterpret_cast<uint32_t*>(&l2);
}

// ============================================================================
// Pre-split kernels: fp32 -> bf16 hi/lo
// ============================================================================
__global__ __launch_bounds__(256) void split_acts_kernel(
    const float* __restrict__ q, const float* __restrict__ k,
    const float* __restrict__ v,
    __nv_bfloat16* __restrict__ bh, __nv_bfloat16* __restrict__ bl)
{
    const int z = blockIdx.z;
    const float* src = (z == 0) ? q : (z == 1) ? k : v;
    size_t i = (size_t)blockIdx.x * 256 + threadIdx.x;   // float4 index
    float4 val = ((const float4*)src)[i];
    uint32_t h0, l0, h1, l1;
    split2(val.x, val.y, h0, l0);
    split2(val.z, val.w, h1, l1);
    size_t base = (size_t)z * ASLOT + i * 4;
    *(uint2*)(bh + base) = make_uint2(h0, h1);
    *(uint2*)(bl + base) = make_uint2(l0, l1);
}

__global__ __launch_bounds__(256) void split_w_kernel(
    const float* __restrict__ w0, const float* __restrict__ w1,
    const float* __restrict__ w2, const float* __restrict__ w3,
    __nv_bfloat16* __restrict__ wh, __nv_bfloat16* __restrict__ wl)
{
    const int z = blockIdx.z;
    const float* src = (z == 0) ? w0 : (z == 1) ? w1 : (z == 2) ? w2 : w3;
    size_t i = (size_t)blockIdx.x * 256 + threadIdx.x;
    float4 val = ((const float4*)src)[i];
    uint32_t h0, l0, h1, l1;
    split2(val.x, val.y, h0, l0);
    split2(val.z, val.w, h1, l1);
    size_t base = (size_t)z * WSLOT + i * 4;
    *(uint2*)(wh + base) = make_uint2(h0, h1);
    *(uint2*)(wl + base) = make_uint2(l0, l1);
}

// ============================================================================
// bf16 (pre-split) GEMM: C[m,n] = (sum_k A[m,k]*W[n,k] + bias[n]) * scale
// CTA 128x128, 8 warps (2m x 4n, each 64x32), KC=32, cp.async double buffer,
// ONE barrier per chunk. 3 mma passes: hh + hl + lh.
// ============================================================================
#define KC   32
#define SA   40
#define MATB (128 * SA * 2)          // 10240 bytes per matrix tile
#define BUF_BYTES (4 * MATB)         // 40960
#define GSMEM_BYTES (2 * BUF_BYTES)  // 81920

template <bool F32OUT>
__device__ __forceinline__ void gemm_body(
    const __nv_bfloat16* __restrict__ Ah, const __nv_bfloat16* __restrict__ Al,
    const __nv_bfloat16* __restrict__ Wh, const __nv_bfloat16* __restrict__ Wl,
    const float* __restrict__ bias, float scale,
    __nv_bfloat16* __restrict__ Ch, __nv_bfloat16* __restrict__ Cl,
    float* __restrict__ Cf)
{
    extern __shared__ __nv_bfloat16 gsm[];
    const uint32_t sbase = smem_u32(gsm);
    const int tid  = threadIdx.x;
    const int wid  = tid >> 5;
    const int lane = tid & 31;
    const int m0 = blockIdx.y * 128;
    const int n0 = blockIdx.x * 128;
    const int wm = (wid >> 2) * 64;
    const int wn = (wid & 3) * 32;

    // cp.async load mapping: row cr (0..127), segs cs, cs+1 (16B each)
    const int cr = tid >> 1;
    const int cs = (tid & 1) * 2;
    const uint32_t sOff = ((uint32_t)cr * SA + cs * 8) * 2;
    const size_t gA = (size_t)(m0 + cr) * E_DIM + cs * 8;
    const size_t gW = (size_t)(n0 + cr) * E_DIM + cs * 8;

#define GEMM_ISSUE(c, b) do {                                            \
    uint32_t sd = sbase + (uint32_t)(b) * BUF_BYTES + sOff;              \
    const __nv_bfloat16* g;                                              \
    g = Ah + gA + (c) * KC; CP16(sd,            g); CP16(sd + 16,            g + 8); \
    g = Al + gA + (c) * KC; CP16(sd + MATB,     g); CP16(sd + MATB + 16,     g + 8); \
    g = Wh + gW + (c) * KC; CP16(sd + 2 * MATB, g); CP16(sd + 2 * MATB + 16, g + 8); \
    g = Wl + gW + (c) * KC; CP16(sd + 3 * MATB, g); CP16(sd + 3 * MATB + 16, g + 8); \
    CP_COMMIT();                                                         \
} while (0)

    // fragment addressing
    const int arow  = (lane & 7) + ((lane >> 3) & 1) * 8;
    const int akoff = (lane >> 4) * 8;
    const int brow4 = (lane & 7) + ((lane >> 4) & 1) * 8;
    const int bk4   = ((lane >> 3) & 1) * 8;

    float acc[4][4][4];
#pragma unroll
    for (int i = 0; i < 4; i++)
#pragma unroll
        for (int j = 0; j < 4; j++)
#pragma unroll
            for (int t = 0; t < 4; t++) acc[i][j][t] = 0.0f;

    GEMM_ISSUE(0, 0);
    CP_WAIT0();
    __syncthreads();

    const int NC = E_DIM / KC;   // 32
    for (int c = 0; c < NC; c++) {
        if (c + 1 < NC) GEMM_ISSUE(c + 1, (c + 1) & 1);

        const uint32_t bufb = sbase + (uint32_t)(c & 1) * BUF_BYTES;
#pragma unroll
        for (int kk = 0; kk < 2; kk++) {
            uint32_t ah[4][4], al[4][4];
#pragma unroll
            for (int ma = 0; ma < 4; ma++) {
                uint32_t off = ((uint32_t)(wm + ma * 16 + arow) * SA + kk * 16 + akoff) * 2;
                LDSM_X4(ah[ma][0], ah[ma][1], ah[ma][2], ah[ma][3], bufb + off);
                LDSM_X4(al[ma][0], al[ma][1], al[ma][2], al[ma][3], bufb + MATB + off);
            }
#pragma unroll
            for (int nap = 0; nap < 2; nap++) {
                uint32_t off = ((uint32_t)(wn + nap * 16 + brow4) * SA + kk * 16 + bk4) * 2;
                uint32_t bh[4], bl[4];
                LDSM_X4(bh[0], bh[1], bh[2], bh[3], bufb + 2 * MATB + off);
                LDSM_X4(bl[0], bl[1], bl[2], bl[3], bufb + 3 * MATB + off);
#pragma unroll
                for (int ma = 0; ma < 4; ma++) {
                    MMA_BF16_P(acc[ma][2 * nap],     ah[ma], bh[0], bh[1]);
                    MMA_BF16_P(acc[ma][2 * nap + 1], ah[ma], bh[2], bh[3]);
                    MMA_BF16_P(acc[ma][2 * nap],     ah[ma], bl[0], bl[1]);
                    MMA_BF16_P(acc[ma][2 * nap + 1], ah[ma], bl[2], bl[3]);
                    MMA_BF16_P(acc[ma][2 * nap],     al[ma], bh[0], bh[1]);
                    MMA_BF16_P(acc[ma][2 * nap + 1], al[ma], bh[2], bh[3]);
                }
            }
        }
        CP_WAIT0();
        __syncthreads();
    }
#undef GEMM_ISSUE

    // epilogue
    const int erow = lane >> 2;
    const int ecol = (lane & 3) * 2;
#pragma unroll
    for (int na = 0; na < 4; na++) {
        int col = n0 + wn + na * 8 + ecol;
        float b0 = bias[col], b1 = bias[col + 1];
#pragma unroll
        for (int ma = 0; ma < 4; ma++) {
            int row = m0 + wm + ma * 16 + erow;
            float v00 = (acc[ma][na][0] + b0) * scale;
            float v01 = (acc[ma][na][1] + b1) * scale;
            float v10 = (acc[ma][na][2] + b0) * scale;
            float v11 = (acc[ma][na][3] + b1) * scale;
            if (F32OUT) {
                *(float2*)(Cf + (size_t)row * E_DIM + col) = make_float2(v00, v01);
                *(float2*)(Cf + (size_t)(row + 8) * E_DIM + col) = make_float2(v10, v11);
            } else {
                uint32_t hh, ll;
                split2(v00, v01, hh, ll);
                *(uint32_t*)(Ch + (size_t)row * E_DIM + col) = hh;
                *(uint32_t*)(Cl + (size_t)row * E_DIM + col) = ll;
                split2(v10, v11, hh, ll);
                *(uint32_t*)(Ch + (size_t)(row + 8) * E_DIM + col) = hh;
                *(uint32_t*)(Cl + (size_t)(row + 8) * E_DIM + col) = ll;
            }
        }
    }
}

// merged q/k/v projection (gridDim.z = 3), bf16 hi/lo outputs into slots 3..5
__global__ __launch_bounds__(256, 2) void qkv_gemm_kernel(
    const __nv_bfloat16* __restrict__ actH, const __nv_bfloat16* __restrict__ actL,
    const __nv_bfloat16* __restrict__ wH,   const __nv_bfloat16* __restrict__ wL,
    const float* __restrict__ bq, const float* __restrict__ bk,
    const float* __restrict__ bv,
    __nv_bfloat16* __restrict__ outH, __nv_bfloat16* __restrict__ outL)
{
    const int z = blockIdx.z;
    const float* bias = (z == 0) ? bq : (z == 1) ? bk : bv;
    const float scale = (z == 0) ? 0.125f : 1.0f;
    gemm_body<false>(actH + (size_t)z * ASLOT, actL + (size_t)z * ASLOT,
                     wH + (size_t)z * WSLOT,   wL + (size_t)z * WSLOT,
                     bias, scale,
                     outH + (size_t)(z + 3) * ASLOT,
                     outL + (size_t)(z + 3) * ASLOT, nullptr);
}

// output projection, fp32 out
__global__ __launch_bounds__(256, 2) void out_gemm_kernel(
    const __nv_bfloat16* __restrict__ Ah, const __nv_bfloat16* __restrict__ Al,
    const __nv_bfloat16* __restrict__ Wh, const __nv_bfloat16* __restrict__ Wl,
    const float* __restrict__ bias, float* __restrict__ Cf)
{
    gemm_body<true>(Ah, Al, Wh, Wl, bias, 1.0f, nullptr, nullptr, Cf);
}

// ============================================================================
// Flash attention on tensor cores (split-bf16, 3-pass), causal.
// Inputs already bf16 hi/lo. cp.async double-buffered K/V, ONE barrier/tile.
// KV buffer 1 ALIASES the Q smem region (dead after Q-fragment extraction),
// shrinking smem to 72KB so __launch_bounds__(256,2) yields 2 CTAs/SM.
// ============================================================================
#define FBQ 128
#define FBS 64
#define FP  72
#define QMATB (FBQ * FP * 2)                    // 18432
#define KVMATB (FBS * FP * 2)                   // 9216
#define KVBUF (4 * KVMATB)                      // 36864 (== 2*QMATB, aliasable)
#define FSMEM_BYTES (2 * QMATB + KVBUF)         // 73728

__global__ __launch_bounds__(256, 2) void flash_mma_kernel(
    const __nv_bfloat16* __restrict__ Qh_g, const __nv_bfloat16* __restrict__ Ql_g,
    const __nv_bfloat16* __restrict__ Kh_g, const __nv_bfloat16* __restrict__ Kl_g,
    const __nv_bfloat16* __restrict__ Vh_g, const __nv_bfloat16* __restrict__ Vl_g,
    __nv_bfloat16* __restrict__ Oh_g, __nv_bfloat16* __restrict__ Ol_g)
{
    extern __shared__ __nv_bfloat16 fsm[];
    const uint32_t sb  = smem_u32(fsm);
    const uint32_t QhB = sb;
    const uint32_t QlB = sb + QMATB;
    // KV buf0 after Q region; KV buf1 aliases the (dead-after-prologue) Q region
    const uint32_t kvbase0 = sb + 2 * QMATB;
    const uint32_t kvbase1 = sb;

    const int tid  = threadIdx.x;
    const int wid  = tid >> 5;
    const int lane = tid & 31;
    const int head = blockIdx.x;                       // b*H + h
    const int qtile = (int)(gridDim.y - 1) - (int)blockIdx.y;  // heavy first
    const int b = head >> 4;
    const int h = head & 15;
    const int t0 = qtile * FBQ;

    // cp.async mappings
    const int qr = tid >> 1;              // 0..127
    const int qc = (tid & 1) * 32;        // col base (bf16)
    const int kr = tid >> 2;              // 0..63
    const int kc = (tid & 3) * 16;        // col base (bf16)

    const size_t qrow = ((size_t)(t0 + qr) * B_DIM + b) * E_DIM + h * D_HEAD + qc;
    const size_t krowbase = (size_t)B_DIM * E_DIM;   // stride per s
    const size_t kcol0 = (size_t)b * E_DIM + h * D_HEAD + kc;

#define FLASH_ISSUE_KV(s0v, bufsel) do {                                           \
    uint32_t bufb = ((bufsel) ? kvbase1 : kvbase0) + ((uint32_t)kr * FP + kc) * 2; \
    size_t g = (size_t)((s0v) + kr) * krowbase + kcol0;                            \
    CP16(bufb,                  Kh_g + g); CP16(bufb + 16,              Kh_g + g + 8); \
    CP16(bufb + KVMATB,         Kl_g + g); CP16(bufb + KVMATB + 16,     Kl_g + g + 8); \
    CP16(bufb + 2 * KVMATB,     Vh_g + g); CP16(bufb + 2 * KVMATB + 16, Vh_g + g + 8); \
    CP16(bufb + 3 * KVMATB,     Vl_g + g); CP16(bufb + 3 * KVMATB + 16, Vl_g + g + 8); \
    CP_COMMIT();                                                                   \
} while (0)

    // ---- prologue: Q + tile0 in flight
    {
        uint32_t sq = QhB + ((uint32_t)qr * FP + qc) * 2;
#pragma unroll
        for (int u = 0; u < 4; u++) {
            CP16(sq + u * 16,         Qh_g + qrow + u * 8);
            CP16(sq + QMATB + u * 16, Ql_g + qrow + u * 8);
        }
    }
    FLASH_ISSUE_KV(0, 0);
    CP_WAIT0();
    __syncthreads();

    // ---- Q A-fragments (persist across all s-tiles)
    const int arow  = (lane & 7) + ((lane >> 3) & 1) * 8;
    const int akoff = (lane >> 4) * 8;
    uint32_t qah[4][4], qal[4][4];
#pragma unroll
    for (int kcn = 0; kcn < 4; kcn++) {
        uint32_t off = ((uint32_t)(wid * 16 + arow) * FP + kcn * 16 + akoff) * 2;
        LDSM_X4(qah[kcn][0], qah[kcn][1], qah[kcn][2], qah[kcn][3], QhB + off);
        LDSM_X4(qal[kcn][0], qal[kcn][1], qal[kcn][2], qal[kcn][3], QlB + off);
    }
    __syncthreads();   // Q region is now dead; buf1 cp.async may overwrite it

    // K (non-trans x4) / V (trans x4) fragment addressing
    const int krow4 = (lane & 7) + ((lane >> 4) & 1) * 8;
    const int kcol4 = ((lane >> 3) & 1) * 8;
    const int vrow  = lane & 15;
    const int vcol  = ((lane >> 4) & 1) * 8;

    float m0 = -1e30f, m1 = -1e30f, l0 = 0.0f, l1 = 0.0f;
    float oacc[8][4];
#pragma unroll
    for (int i = 0; i < 8; i++)
#pragma unroll
        for (int t = 0; t < 4; t++) oacc[i][t] = 0.0f;

    const int wrow_min = t0 + wid * 16;
    const int wrow_max = wrow_min + 15;
    const int ntiles = 2 * qtile + 2;

    for (int st = 0; st < ntiles; st++) {
        const int s0 = st * FBS;
        if (st + 1 < ntiles) FLASH_ISSUE_KV(s0 + FBS, (st + 1) & 1);

        if (s0 <= wrow_max) {
            const uint32_t KhB = (st & 1) ? kvbase1 : kvbase0;
            const uint32_t KlB = KhB + KVMATB;
            const uint32_t VhB = KhB + 2 * KVMATB;
            const uint32_t VlB = KhB + 3 * KVMATB;

            // ---- S = Q K^T (3-pass split)
            float sacc[8][4];
#pragma unroll
            for (int i = 0; i < 8; i++)
#pragma unroll
                for (int t = 0; t < 4; t++) sacc[i][t] = 0.0f;

#pragma unroll
            for (int ntp = 0; ntp < 4; ntp++) {
#pragma unroll
                for (int kcn = 0; kcn < 4; kcn++) {
                    uint32_t off = ((uint32_t)(ntp * 16 + krow4) * FP + kcn * 16 + kcol4) * 2;
                    uint32_t bh[4], bl[4];
                    LDSM_X4(bh[0], bh[1], bh[2], bh[3], KhB + off);
                    LDSM_X4(bl[0], bl[1], bl[2], bl[3], KlB + off);
                    MMA_BF16_P(sacc[2 * ntp],     qah[kcn], bh[0], bh[1]);
                    MMA_BF16_P(sacc[2 * ntp + 1], qah[kcn], bh[2], bh[3]);
                    MMA_BF16_P(sacc[2 * ntp],     qah[kcn], bl[0], bl[1]);
                    MMA_BF16_P(sacc[2 * ntp + 1], qah[kcn], bl[2], bl[3]);
                    MMA_BF16_P(sacc[2 * ntp],     qal[kcn], bh[0], bh[1]);
                    MMA_BF16_P(sacc[2 * ntp + 1], qal[kcn], bh[2], bh[3]);
                }
            }

            // ---- causal mask (whenever tile reaches past warp's first row)
            if (s0 + FBS - 1 > wrow_min) {
                int r0g = wrow_min + (lane >> 2);
                int r1g = r0g + 8;
#pragma unroll
                for (int nt = 0; nt < 8; nt++) {
                    int c0g = s0 + nt * 8 + (lane & 3) * 2;
                    if (c0g     > r0g) sacc[nt][0] = -1e9f;
                    if (c0g + 1 > r0g) sacc[nt][1] = -1e9f;
                    if (c0g     > r1g) sacc[nt][2] = -1e9f;
                    if (c0g + 1 > r1g) sacc[nt][3] = -1e9f;
                }
            }

            // ---- online softmax
            float rmax0 = -1e30f, rmax1 = -1e30f;
#pragma unroll
            for (int nt = 0; nt < 8; nt++) {
                rmax0 = fmaxf(rmax0, fmaxf(sacc[nt][0], sacc[nt][1]));
                rmax1 = fmaxf(rmax1, fmaxf(sacc[nt][2], sacc[nt][3]));
            }
            rmax0 = fmaxf(rmax0, __shfl_xor_sync(0xffffffffu, rmax0, 1));
            rmax0 = fmaxf(rmax0, __shfl_xor_sync(0xffffffffu, rmax0, 2));
            rmax1 = fmaxf(rmax1, __shfl_xor_sync(0xffffffffu, rmax1, 1));
            rmax1 = fmaxf(rmax1, __shfl_xor_sync(0xffffffffu, rmax1, 2));

            float mn0 = fmaxf(m0, rmax0);
            float mn1 = fmaxf(m1, rmax1);
            float a0 = __expf(m0 - mn0);
            float a1 = __expf(m1 - mn1);

            float rs0 = 0.0f, rs1 = 0.0f;
            uint32_t pah[4][4], pal[4][4];
#pragma unroll
            for (int nt = 0; nt < 8; nt++) {
                float p0 = __expf(sacc[nt][0] - mn0);
                float p1 = __expf(sacc[nt][1] - mn0);
                float p2 = __expf(sacc[nt][2] - mn1);
                float p3 = __expf(sacc[nt][3] - mn1);
                rs0 += p0 + p1;
                rs1 += p2 + p3;
                int kcn = nt >> 1, half = nt & 1;
                uint32_t hA, lA, hB, lB;
                split2(p0, p1, hA, lA);
                split2(p2, p3, hB, lB);
                pah[kcn][half * 2 + 0] = hA; pal[kcn][half * 2 + 0] = lA;
                pah[kcn][half * 2 + 1] = hB; pal[kcn][half * 2 + 1] = lB;
            }
            rs0 += __shfl_xor_sync(0xffffffffu, rs0, 1);
            rs0 += __shfl_xor_sync(0xffffffffu, rs0, 2);
            rs1 += __shfl_xor_sync(0xffffffffu, rs1, 1);
            rs1 += __shfl_xor_sync(0xffffffffu, rs1, 2);

            l0 = l0 * a0 + rs0;
            l1 = l1 * a1 + rs1;
            m0 = mn0; m1 = mn1;

#pragma unroll
            for (int dt = 0; dt < 8; dt++) {
                oacc[dt][0] *= a0; oacc[dt][1] *= a0;
                oacc[dt][2] *= a1; oacc[dt][3] *= a1;
            }

            // ---- O += P V (3-pass), V[s][d] via trans x4
#pragma unroll
            for (int dtp = 0; dtp < 4; dtp++) {
#pragma unroll
                for (int kcn = 0; kcn < 4; kcn++) {
                    uint32_t off = ((uint32_t)(kcn * 16 + vrow) * FP + dtp * 16 + vcol) * 2;
                    uint32_t vh[4], vl[4];
                    LDSM_X4_TRANS(vh[0], vh[1], vh[2], vh[3], VhB + off);
                    LDSM_X4_TRANS(vl[0], vl[1], vl[2], vl[3], VlB + off);
                    MMA_BF16_P(oacc[2 * dtp],     pah[kcn], vh[0], vh[1]);
                    MMA_BF16_P(oacc[2 * dtp + 1], pah[kcn], vh[2], vh[3]);
                    MMA_BF16_P(oacc[2 * dtp],     pah[kcn], vl[0], vl[1]);
                    MMA_BF16_P(oacc[2 * dtp + 1], pah[kcn], vl[2], vl[3]);
                    MMA_BF16_P(oacc[2 * dtp],     pal[kcn], vh[0], vh[1]);
                    MMA_BF16_P(oacc[2 * dtp + 1], pal[kcn], vh[2], vh[3]);
                }
            }
        }
        CP_WAIT0();
        __syncthreads();
    }
#undef FLASH_ISSUE_KV

    // ---- normalize + write split bf16 (consumed by out-projection GEMM)
    float inv0 = 1.0f / l0;
    float inv1 = 1.0f / l1;
    int r0g = t0 + wid * 16 + (lane >> 2);
    size_t row0 = ((size_t)r0g * B_DIM + b) * E_DIM;
    size_t row1 = ((size_t)(r0g + 8) * B_DIM + b) * E_DIM;
#pragma unroll
    for (int dt = 0; dt < 8; dt++) {
        int col = h * D_HEAD + dt * 8 + (lane & 3) * 2;
        uint32_t hh, ll;
        split2(oacc[dt][0] * inv0, oacc[dt][1] * inv0, hh, ll);
        *(uint32_t*)(Oh_g + row0 + col) = hh;
        *(uint32_t*)(Ol_g + row0 + col) = ll;
        split2(oacc[dt][2] * inv1, oacc[dt][3] * inv1, hh, ll);
        *(uint32_t*)(Oh_g + row1 + col) = hh;
        *(uint32_t*)(Ol_g + row1 + col) = ll;
    }
}

// ============================================================================
extern "C" void kernel_launch(void* const* d_in, const int* in_sizes, int n_in,
                              void* d_out, int out_size)
{
    const float* query = (const float*)d_in[0];
    const float* key   = (const float*)d_in[1];
    const float* value = (const float*)d_in[2];
    // d_in[3] = attn_mask (pure causal; applied analytically)
    const float* wq = (const float*)d_in[4];
    const float* bq = (const float*)d_in[5];
    const float* wk = (const float*)d_in[6];
    const float* bk = (const float*)d_in[7];
    const float* wv = (const float*)d_in[8];
    const float* bv = (const float*)d_in[9];
    const float* wo = (const float*)d_in[10];
    const float* bo = (const float*)d_in[11];
    float* out = (float*)d_out;

    __nv_bfloat16 *bh, *bl, *wh, *wl;
    cudaGetSymbolAddress((void**)&bh, g_bh);
    cudaGetSymbolAddress((void**)&bl, g_bl);
    cudaGetSymbolAddress((void**)&wh, g_wh);
    cudaGetSymbolAddress((void**)&wl, g_wl);

    // 1. pre-split weights + input activations to bf16 hi/lo
    split_acts_kernel<<<dim3(MROWS * E_DIM / 4 / 256, 1, 3), 256>>>(
        query, key, value, bh, bl);
    split_w_kernel<<<dim3(E_DIM * E_DIM / 4 / 256, 1, 4), 256>>>(
        wq, wk, wv, wo, wh, wl);

    // 2. merged q/k/v projections (bf16 hi/lo out, slots 3..5)
    cudaFuncSetAttribute(qkv_gemm_kernel,
                         cudaFuncAttributeMaxDynamicSharedMemorySize, GSMEM_BYTES);
    qkv_gemm_kernel<<<dim3(8, 64, 3), 256, GSMEM_BYTES>>>(
        bh, bl, wh, wl, bq, bk, bv, bh, bl);

    // 3. causal flash attention (reads slots 3..5, writes slot 0)
    cudaFuncSetAttribute(flash_mma_kernel,
                         cudaFuncAttributeMaxDynamicSharedMemorySize, FSMEM_BYTES);
    flash_mma_kernel<<<dim3(B_DIM * H_DIM, T_DIM / FBQ), 256, FSMEM_BYTES>>>(
        bh + 3 * ASLOT, bl + 3 * ASLOT,
        bh + 4 * ASLOT, bl + 4 * ASLOT,
        bh + 5 * ASLOT, bl + 5 * ASLOT,
        bh, bl);

    // 4. output projection (fp32 out)
    cudaFuncSetAttribute(out_gemm_kernel,
                         cudaFuncAttributeMaxDynamicSharedMemorySize, GSMEM_BYTES);
    out_gemm_kernel<<<dim3(8, 64), 256, GSMEM_BYTES>>>(
        bh, bl, wh + 3 * WSLOT, wl + 3 * WSLOT, bo, out);
}

// round 9
// speedup vs baseline: 4.7436x; 1.4076x over previous
#include <cuda_runtime.h>
#include <cuda_fp16.h>
#include <cstdint>

// Problem constants (fixed by the dataset)
#define T_DIM   2048
#define B_DIM   4
#define E_DIM   1024
#define H_DIM   16
#define D_HEAD  64
#define MROWS   (T_DIM * B_DIM)           // 8192
#define ASLOT   ((size_t)MROWS * E_DIM)   // 8M elems per activation slot
#define WSLOT   ((size_t)E_DIM * E_DIM)   // 1M elems per weight slot

// fp16 scratch. Activation slots (hi): 0=query 1=key 2=value 3=q_proj 4=k_proj
// 5=v_proj ; slot 0 reused for attn_out. Lo slots: 0..2 inputs, 3=q_proj lo,
// (4,5 unused), 0 reused for attn_out lo. Weights: hi only, slots 0..3.
__device__ __align__(256) __half g_bh[6 * ASLOT];
__device__ __align__(256) __half g_bl[6 * ASLOT];
__device__ __align__(256) __half g_wh[4 * WSLOT];

// ============================================================================
// helpers
// ============================================================================
__device__ __forceinline__ uint32_t smem_u32(const void* p) {
    uint32_t a;
    asm("{ .reg .u64 t; cvta.to.shared.u64 t, %1; cvt.u32.u64 %0, t; }"
        : "=r"(a) : "l"(p));
    return a;
}

#define CP16(smem, gptr) \
    asm volatile("cp.async.cg.shared.global [%0], [%1], 16;" :: "r"(smem), "l"(gptr))
#define CP_COMMIT() asm volatile("cp.async.commit_group;" ::: "memory")
#define CP_WAIT0()  asm volatile("cp.async.wait_group 0;" ::: "memory")

#define LDSM_X4(r0, r1, r2, r3, addr) \
    asm volatile("ldmatrix.sync.aligned.m8n8.x4.shared.b16 {%0,%1,%2,%3}, [%4];" \
                 : "=r"(r0), "=r"(r1), "=r"(r2), "=r"(r3) : "r"(addr))
#define LDSM_X4_TRANS(r0, r1, r2, r3, addr) \
    asm volatile("ldmatrix.sync.aligned.m8n8.x4.trans.shared.b16 {%0,%1,%2,%3}, [%4];" \
                 : "=r"(r0), "=r"(r1), "=r"(r2), "=r"(r3) : "r"(addr))
#define MMA_F16_P(d, a, b0, b1) \
    asm volatile("mma.sync.aligned.m16n8k16.row.col.f32.f16.f16.f32 " \
                 "{%0,%1,%2,%3}, {%4,%5,%6,%7}, {%8,%9}, {%0,%1,%2,%3};" \
                 : "+f"((d)[0]), "+f"((d)[1]), "+f"((d)[2]), "+f"((d)[3]) \
                 : "r"((a)[0]), "r"((a)[1]), "r"((a)[2]), "r"((a)[3]), \
                   "r"(b0), "r"(b1))

// pack 2 floats -> hi/lo fp16 pairs (split-fp16; x in low half)
__device__ __forceinline__ void split2h(float x, float y, uint32_t& hi, uint32_t& lo) {
    __half hx = __float2half_rn(x);
    __half hy = __float2half_rn(y);
    __half lx = __float2half_rn(x - __half2float(hx));
    __half ly = __float2half_rn(y - __half2float(hy));
    __half2 h2 = __halves2half2(hx, hy);
    __half2 l2 = __halves2half2(lx, ly);
    hi = *reinterpret_cast<uint32_t*>(&h2);
    lo = *reinterpret_cast<uint32_t*>(&l2);
}
// pack 2 floats -> single fp16 pair
__device__ __forceinline__ uint32_t pack2h(float x, float y) {
    __half2 h2 = __halves2half2(__float2half_rn(x), __float2half_rn(y));
    return *reinterpret_cast<uint32_t*>(&h2);
}

// ============================================================================
// Pre-split kernels
// ============================================================================
__global__ __launch_bounds__(256) void split_acts_kernel(
    const float* __restrict__ q, const float* __restrict__ k,
    const float* __restrict__ v,
    __half* __restrict__ bh, __half* __restrict__ bl)
{
    const int z = blockIdx.z;
    const float* src = (z == 0) ? q : (z == 1) ? k : v;
    size_t i = (size_t)blockIdx.x * 256 + threadIdx.x;   // float4 index
    float4 val = ((const float4*)src)[i];
    uint32_t h0, l0, h1, l1;
    split2h(val.x, val.y, h0, l0);
    split2h(val.z, val.w, h1, l1);
    size_t base = (size_t)z * ASLOT + i * 4;
    *(uint2*)(bh + base) = make_uint2(h0, h1);
    *(uint2*)(bl + base) = make_uint2(l0, l1);
}

__global__ __launch_bounds__(256) void split_w_kernel(
    const float* __restrict__ w0, const float* __restrict__ w1,
    const float* __restrict__ w2, const float* __restrict__ w3,
    __half* __restrict__ wh)
{
    const int z = blockIdx.z;
    const float* src = (z == 0) ? w0 : (z == 1) ? w1 : (z == 2) ? w2 : w3;
    size_t i = (size_t)blockIdx.x * 256 + threadIdx.x;
    float4 val = ((const float4*)src)[i];
    size_t base = (size_t)z * WSLOT + i * 4;
    *(uint2*)(wh + base) = make_uint2(pack2h(val.x, val.y), pack2h(val.z, val.w));
}

// ============================================================================
// split-fp16 2-pass GEMM: C[m,n] = (sum_k A[m,k]*W[n,k] + bias[n]) * scale
// A split (hi+lo), W single fp16. CTA 128x128, 8 warps (2m x 4n), KC=32,
// cp.async double buffer, one barrier per chunk. D = Ah*W + Al*W.
// ============================================================================
#define KC   32
#define SA   40
#define MATB (128 * SA * 2)          // 10240 bytes per matrix tile
#define BUF_BYTES (3 * MATB)         // 30720 (Ah, Al, Wh)
#define GSMEM_BYTES (2 * BUF_BYTES)  // 61440

template <bool F32OUT>
__device__ __forceinline__ void gemm_body(
    const __half* __restrict__ Ah, const __half* __restrict__ Al,
    const __half* __restrict__ Wh,
    const float* __restrict__ bias, float scale,
    __half* __restrict__ Ch, __half* __restrict__ Cl,
    float* __restrict__ Cf)
{
    extern __shared__ __half gsm[];
    const uint32_t sbase = smem_u32(gsm);
    const int tid  = threadIdx.x;
    const int wid  = tid >> 5;
    const int lane = tid & 31;
    const int m0 = blockIdx.y * 128;
    const int n0 = blockIdx.x * 128;
    const int wm = (wid >> 2) * 64;
    const int wn = (wid & 3) * 32;

    // cp.async load mapping
    const int cr = tid >> 1;
    const int cs = (tid & 1) * 2;
    const uint32_t sOff = ((uint32_t)cr * SA + cs * 8) * 2;
    const size_t gA = (size_t)(m0 + cr) * E_DIM + cs * 8;
    const size_t gW = (size_t)(n0 + cr) * E_DIM + cs * 8;

#define GEMM_ISSUE(c, b) do {                                            \
    uint32_t sd = sbase + (uint32_t)(b) * BUF_BYTES + sOff;              \
    const __half* g;                                                     \
    g = Ah + gA + (c) * KC; CP16(sd,            g); CP16(sd + 16,            g + 8); \
    g = Al + gA + (c) * KC; CP16(sd + MATB,     g); CP16(sd + MATB + 16,     g + 8); \
    g = Wh + gW + (c) * KC; CP16(sd + 2 * MATB, g); CP16(sd + 2 * MATB + 16, g + 8); \
    CP_COMMIT();                                                         \
} while (0)

    // fragment addressing
    const int arow  = (lane & 7) + ((lane >> 3) & 1) * 8;
    const int akoff = (lane >> 4) * 8;
    const int brow4 = (lane & 7) + ((lane >> 4) & 1) * 8;
    const int bk4   = ((lane >> 3) & 1) * 8;

    float acc[4][4][4];
#pragma unroll
    for (int i = 0; i < 4; i++)
#pragma unroll
        for (int j = 0; j < 4; j++)
#pragma unroll
            for (int t = 0; t < 4; t++) acc[i][j][t] = 0.0f;

    GEMM_ISSUE(0, 0);
    CP_WAIT0();
    __syncthreads();

    const int NC = E_DIM / KC;   // 32
    for (int c = 0; c < NC; c++) {
        if (c + 1 < NC) GEMM_ISSUE(c + 1, (c + 1) & 1);

        const uint32_t bufb = sbase + (uint32_t)(c & 1) * BUF_BYTES;
#pragma unroll
        for (int kk = 0; kk < 2; kk++) {
            uint32_t ah[4][4], al[4][4];
#pragma unroll
            for (int ma = 0; ma < 4; ma++) {
                uint32_t off = ((uint32_t)(wm + ma * 16 + arow) * SA + kk * 16 + akoff) * 2;
                LDSM_X4(ah[ma][0], ah[ma][1], ah[ma][2], ah[ma][3], bufb + off);
                LDSM_X4(al[ma][0], al[ma][1], al[ma][2], al[ma][3], bufb + MATB + off);
            }
#pragma unroll
            for (int nap = 0; nap < 2; nap++) {
                uint32_t off = ((uint32_t)(wn + nap * 16 + brow4) * SA + kk * 16 + bk4) * 2;
                uint32_t bh[4];
                LDSM_X4(bh[0], bh[1], bh[2], bh[3], bufb + 2 * MATB + off);
#pragma unroll
                for (int ma = 0; ma < 4; ma++) {
                    MMA_F16_P(acc[ma][2 * nap],     ah[ma], bh[0], bh[1]);
                    MMA_F16_P(acc[ma][2 * nap + 1], ah[ma], bh[2], bh[3]);
                    MMA_F16_P(acc[ma][2 * nap],     al[ma], bh[0], bh[1]);
                    MMA_F16_P(acc[ma][2 * nap + 1], al[ma], bh[2], bh[3]);
                }
            }
        }
        CP_WAIT0();
        __syncthreads();
    }
#undef GEMM_ISSUE

    // epilogue
    const int erow = lane >> 2;
    const int ecol = (lane & 3) * 2;
#pragma unroll
    for (int na = 0; na < 4; na++) {
        int col = n0 + wn + na * 8 + ecol;
        float b0 = bias[col], b1 = bias[col + 1];
#pragma unroll
        for (int ma = 0; ma < 4; ma++) {
            int row = m0 + wm + ma * 16 + erow;
            float v00 = (acc[ma][na][0] + b0) * scale;
            float v01 = (acc[ma][na][1] + b1) * scale;
            float v10 = (acc[ma][na][2] + b0) * scale;
            float v11 = (acc[ma][na][3] + b1) * scale;
            if (F32OUT) {
                *(float2*)(Cf + (size_t)row * E_DIM + col) = make_float2(v00, v01);
                *(float2*)(Cf + (size_t)(row + 8) * E_DIM + col) = make_float2(v10, v11);
            } else if (Cl != nullptr) {    // split output (q proj, attn in)
                uint32_t hh, ll;
                split2h(v00, v01, hh, ll);
                *(uint32_t*)(Ch + (size_t)row * E_DIM + col) = hh;
                *(uint32_t*)(Cl + (size_t)row * E_DIM + col) = ll;
                split2h(v10, v11, hh, ll);
                *(uint32_t*)(Ch + (size_t)(row + 8) * E_DIM + col) = hh;
                *(uint32_t*)(Cl + (size_t)(row + 8) * E_DIM + col) = ll;
            } else {                        // hi-only output (k, v proj)
                *(uint32_t*)(Ch + (size_t)row * E_DIM + col) = pack2h(v00, v01);
                *(uint32_t*)(Ch + (size_t)(row + 8) * E_DIM + col) = pack2h(v10, v11);
            }
        }
    }
}

// merged q/k/v projection (gridDim.z = 3)
__global__ __launch_bounds__(256, 2) void qkv_gemm_kernel(
    const __half* __restrict__ actH, const __half* __restrict__ actL,
    const __half* __restrict__ wH,
    const float* __restrict__ bq, const float* __restrict__ bk,
    const float* __restrict__ bv,
    __half* __restrict__ outH, __half* __restrict__ outL)
{
    const int z = blockIdx.z;
    const float* bias = (z == 0) ? bq : (z == 1) ? bk : bv;
    const float scale = (z == 0) ? 0.125f : 1.0f;
    __half* Cl = (z == 0) ? (outL + (size_t)3 * ASLOT) : nullptr;
    gemm_body<false>(actH + (size_t)z * ASLOT, actL + (size_t)z * ASLOT,
                     wH + (size_t)z * WSLOT,
                     bias, scale,
                     outH + (size_t)(z + 3) * ASLOT, Cl, nullptr);
}

// output projection, fp32 out
__global__ __launch_bounds__(256, 2) void out_gemm_kernel(
    const __half* __restrict__ Ah, const __half* __restrict__ Al,
    const __half* __restrict__ Wh,
    const float* __restrict__ bias, float* __restrict__ Cf)
{
    gemm_body<true>(Ah, Al, Wh, bias, 1.0f, nullptr, nullptr, Cf);
}

// ============================================================================
// Flash attention on tensor cores (split-fp16 2-pass), causal.
// S = (Qh+Ql)*Kh ; O += (Ph+Pl)*Vh. K/V single fp16 (hi), Q and P split.
// cp.async double-buffered K/V (independent buffers), one barrier per tile.
// ============================================================================
#define FBQ 128
#define FBS 64
#define FP  72
#define QMATB (FBQ * FP * 2)                    // 18432
#define KVMATB (FBS * FP * 2)                   // 9216
#define KVBUF (2 * KVMATB)                      // 18432 (Kh + Vh)
#define FSMEM_BYTES (2 * QMATB + 2 * KVBUF)     // 73728

__global__ __launch_bounds__(256, 2) void flash_mma_kernel(
    const __half* __restrict__ Qh_g, const __half* __restrict__ Ql_g,
    const __half* __restrict__ Kh_g, const __half* __restrict__ Vh_g,
    __half* __restrict__ Oh_g, __half* __restrict__ Ol_g)
{
    extern __shared__ __half fsm[];
    const uint32_t sb  = smem_u32(fsm);
    const uint32_t QhB = sb;
    const uint32_t QlB = sb + QMATB;
    const uint32_t kvbase = sb + 2 * QMATB;     // buf b at kvbase + b*KVBUF

    const int tid  = threadIdx.x;
    const int wid  = tid >> 5;
    const int lane = tid & 31;
    const int head = blockIdx.x;                       // b*H + h
    const int qtile = (int)(gridDim.y - 1) - (int)blockIdx.y;  // heavy first
    const int b = head >> 4;
    const int h = head & 15;
    const int t0 = qtile * FBQ;

    // cp.async mappings
    const int qr = tid >> 1;              // 0..127
    const int qc = (tid & 1) * 32;        // col base
    const int kr = tid >> 2;              // 0..63
    const int kc = (tid & 3) * 16;        // col base

    const size_t qrow = ((size_t)(t0 + qr) * B_DIM + b) * E_DIM + h * D_HEAD + qc;
    const size_t krowstride = (size_t)B_DIM * E_DIM;
    const size_t kcol0 = (size_t)b * E_DIM + h * D_HEAD + kc;

#define FLASH_ISSUE_KV(s0v, bufsel) do {                                           \
    uint32_t bufb = kvbase + (uint32_t)(bufsel) * KVBUF + ((uint32_t)kr * FP + kc) * 2; \
    size_t g = (size_t)((s0v) + kr) * krowstride + kcol0;                          \
    CP16(bufb,              Kh_g + g); CP16(bufb + 16,          Kh_g + g + 8);     \
    CP16(bufb + KVMATB,     Vh_g + g); CP16(bufb + KVMATB + 16, Vh_g + g + 8);     \
    CP_COMMIT();                                                                   \
} while (0)

    // ---- prologue: Q + tile0 in flight
    {
        uint32_t sq = QhB + ((uint32_t)qr * FP + qc) * 2;
#pragma unroll
        for (int u = 0; u < 4; u++) {
            CP16(sq + u * 16,         Qh_g + qrow + u * 8);
            CP16(sq + QMATB + u * 16, Ql_g + qrow + u * 8);
        }
    }
    FLASH_ISSUE_KV(0, 0);
    CP_WAIT0();
    __syncthreads();

    // ---- Q A-fragments (persist across all s-tiles)
    const int arow  = (lane & 7) + ((lane >> 3) & 1) * 8;
    const int akoff = (lane >> 4) * 8;
    uint32_t qah[4][4], qal[4][4];
#pragma unroll
    for (int kcn = 0; kcn < 4; kcn++) {
        uint32_t off = ((uint32_t)(wid * 16 + arow) * FP + kcn * 16 + akoff) * 2;
        LDSM_X4(qah[kcn][0], qah[kcn][1], qah[kcn][2], qah[kcn][3], QhB + off);
        LDSM_X4(qal[kcn][0], qal[kcn][1], qal[kcn][2], qal[kcn][3], QlB + off);
    }

    // K (non-trans x4) / V (trans x4) fragment addressing
    const int krow4 = (lane & 7) + ((lane >> 4) & 1) * 8;
    const int kcol4 = ((lane >> 3) & 1) * 8;
    const int vrow  = lane & 15;
    const int vcol  = ((lane >> 4) & 1) * 8;

    float m0 = -1e30f, m1 = -1e30f, l0 = 0.0f, l1 = 0.0f;
    float oacc[8][4];
#pragma unroll
    for (int i = 0; i < 8; i++)
#pragma unroll
        for (int t = 0; t < 4; t++) oacc[i][t] = 0.0f;

    const int wrow_min = t0 + wid * 16;
    const int wrow_max = wrow_min + 15;
    const int ntiles = 2 * qtile + 2;

    for (int st = 0; st < ntiles; st++) {
        const int s0 = st * FBS;
        if (st + 1 < ntiles) FLASH_ISSUE_KV(s0 + FBS, (st + 1) & 1);

        if (s0 <= wrow_max) {
            const uint32_t KhB = kvbase + (uint32_t)(st & 1) * KVBUF;
            const uint32_t VhB = KhB + KVMATB;

            // ---- S = Q K^T (2-pass split)
            float sacc[8][4];
#pragma unroll
            for (int i = 0; i < 8; i++)
#pragma unroll
                for (int t = 0; t < 4; t++) sacc[i][t] = 0.0f;

#pragma unroll
            for (int ntp = 0; ntp < 4; ntp++) {
#pragma unroll
                for (int kcn = 0; kcn < 4; kcn++) {
                    uint32_t off = ((uint32_t)(ntp * 16 + krow4) * FP + kcn * 16 + kcol4) * 2;
                    uint32_t bh[4];
                    LDSM_X4(bh[0], bh[1], bh[2], bh[3], KhB + off);
                    MMA_F16_P(sacc[2 * ntp],     qah[kcn], bh[0], bh[1]);
                    MMA_F16_P(sacc[2 * ntp + 1], qah[kcn], bh[2], bh[3]);
                    MMA_F16_P(sacc[2 * ntp],     qal[kcn], bh[0], bh[1]);
                    MMA_F16_P(sacc[2 * ntp + 1], qal[kcn], bh[2], bh[3]);
                }
            }

            // ---- causal mask (whenever tile reaches past warp's first row)
            if (s0 + FBS - 1 > wrow_min) {
                int r0g = wrow_min + (lane >> 2);
                int r1g = r0g + 8;
#pragma unroll
                for (int nt = 0; nt < 8; nt++) {
                    int c0g = s0 + nt * 8 + (lane & 3) * 2;
                    if (c0g     > r0g) sacc[nt][0] = -1e9f;
                    if (c0g + 1 > r0g) sacc[nt][1] = -1e9f;
                    if (c0g     > r1g) sacc[nt][2] = -1e9f;
                    if (c0g + 1 > r1g) sacc[nt][3] = -1e9f;
                }
            }

            // ---- online softmax
            float rmax0 = -1e30f, rmax1 = -1e30f;
#pragma unroll
            for (int nt = 0; nt < 8; nt++) {
                rmax0 = fmaxf(rmax0, fmaxf(sacc[nt][0], sacc[nt][1]));
                rmax1 = fmaxf(rmax1, fmaxf(sacc[nt][2], sacc[nt][3]));
            }
            rmax0 = fmaxf(rmax0, __shfl_xor_sync(0xffffffffu, rmax0, 1));
            rmax0 = fmaxf(rmax0, __shfl_xor_sync(0xffffffffu, rmax0, 2));
            rmax1 = fmaxf(rmax1, __shfl_xor_sync(0xffffffffu, rmax1, 1));
            rmax1 = fmaxf(rmax1, __shfl_xor_sync(0xffffffffu, rmax1, 2));

            float mn0 = fmaxf(m0, rmax0);
            float mn1 = fmaxf(m1, rmax1);
            float a0 = __expf(m0 - mn0);
            float a1 = __expf(m1 - mn1);

            float rs0 = 0.0f, rs1 = 0.0f;
            uint32_t pah[4][4], pal[4][4];
#pragma unroll
            for (int nt = 0; nt < 8; nt++) {
                float p0 = __expf(sacc[nt][0] - mn0);
                float p1 = __expf(sacc[nt][1] - mn0);
                float p2 = __expf(sacc[nt][2] - mn1);
                float p3 = __expf(sacc[nt][3] - mn1);
                rs0 += p0 + p1;
                rs1 += p2 + p3;
                int kcn = nt >> 1, half = nt & 1;
                uint32_t hA, lA, hB, lB;
                split2h(p0, p1, hA, lA);
                split2h(p2, p3, hB, lB);
                pah[kcn][half * 2 + 0] = hA; pal[kcn][half * 2 + 0] = lA;
                pah[kcn][half * 2 + 1] = hB; pal[kcn][half * 2 + 1] = lB;
            }
            rs0 += __shfl_xor_sync(0xffffffffu, rs0, 1);
            rs0 += __shfl_xor_sync(0xffffffffu, rs0, 2);
            rs1 += __shfl_xor_sync(0xffffffffu, rs1, 1);
            rs1 += __shfl_xor_sync(0xffffffffu, rs1, 2);

            l0 = l0 * a0 + rs0;
            l1 = l1 * a1 + rs1;
            m0 = mn0; m1 = mn1;

#pragma unroll
            for (int dt = 0; dt < 8; dt++) {
                oacc[dt][0] *= a0; oacc[dt][1] *= a0;
                oacc[dt][2] *= a1; oacc[dt][3] *= a1;
            }

            // ---- O += P V (2-pass split), V[s][d] via trans x4
#pragma unroll
            for (int dtp = 0; dtp < 4; dtp++) {
#pragma unroll
                for (int kcn = 0; kcn < 4; kcn++) {
                    uint32_t off = ((uint32_t)(kcn * 16 + vrow) * FP + dtp * 16 + vcol) * 2;
                    uint32_t vh[4];
                    LDSM_X4_TRANS(vh[0], vh[1], vh[2], vh[3], VhB + off);
                    MMA_F16_P(oacc[2 * dtp],     pah[kcn], vh[0], vh[1]);
                    MMA_F16_P(oacc[2 * dtp + 1], pah[kcn], vh[2], vh[3]);
                    MMA_F16_P(oacc[2 * dtp],     pal[kcn], vh[0], vh[1]);
                    MMA_F16_P(oacc[2 * dtp + 1], pal[kcn], vh[2], vh[3]);
                }
            }
        }
        CP_WAIT0();
        __syncthreads();
    }
#undef FLASH_ISSUE_KV

    // ---- normalize + write split fp16 (consumed by out-projection GEMM)
    float inv0 = 1.0f / l0;
    float inv1 = 1.0f / l1;
    int r0g = t0 + wid * 16 + (lane >> 2);
    size_t row0 = ((size_t)r0g * B_DIM + b) * E_DIM;
    size_t row1 = ((size_t)(r0g + 8) * B_DIM + b) * E_DIM;
#pragma unroll
    for (int dt = 0; dt < 8; dt++) {
        int col = h * D_HEAD + dt * 8 + (lane & 3) * 2;
        uint32_t hh, ll;
        split2h(oacc[dt][0] * inv0, oacc[dt][1] * inv0, hh, ll);
        *(uint32_t*)(Oh_g + row0 + col) = hh;
        *(uint32_t*)(Ol_g + row0 + col) = ll;
        split2h(oacc[dt][2] * inv1, oacc[dt][3] * inv1, hh, ll);
        *(uint32_t*)(Oh_g + row1 + col) = hh;
        *(uint32_t*)(Ol_g + row1 + col) = ll;
    }
}

// ============================================================================
extern "C" void kernel_launch(void* const* d_in, const int* in_sizes, int n_in,
                              void* d_out, int out_size)
{
    const float* query = (const float*)d_in[0];
    const float* key   = (const float*)d_in[1];
    const float* value = (const float*)d_in[2];
    // d_in[3] = attn_mask (pure causal; applied analytically)
    const float* wq = (const float*)d_in[4];
    const float* bq = (const float*)d_in[5];
    const float* wk = (const float*)d_in[6];
    const float* bk = (const float*)d_in[7];
    const float* wv = (const float*)d_in[8];
    const float* bv = (const float*)d_in[9];
    const float* wo = (const float*)d_in[10];
    const float* bo = (const float*)d_in[11];
    float* out = (float*)d_out;

    __half *bh, *bl, *wh;
    cudaGetSymbolAddress((void**)&bh, g_bh);
    cudaGetSymbolAddress((void**)&bl, g_bl);
    cudaGetSymbolAddress((void**)&wh, g_wh);

    // 1. pre-split inputs (A-side split, weights hi-only)
    split_acts_kernel<<<dim3(MROWS * E_DIM / 4 / 256, 1, 3), 256>>>(
        query, key, value, bh, bl);
    split_w_kernel<<<dim3(E_DIM * E_DIM / 4 / 256, 1, 4), 256>>>(
        wq, wk, wv, wo, wh);

    // 2. merged q/k/v projections (q split out, k/v hi-only out)
    cudaFuncSetAttribute(qkv_gemm_kernel,
                         cudaFuncAttributeMaxDynamicSharedMemorySize, GSMEM_BYTES);
    qkv_gemm_kernel<<<dim3(8, 64, 3), 256, GSMEM_BYTES>>>(
        bh, bl, wh, bq, bk, bv, bh, bl);

    // 3. causal flash attention (reads slots 3..5, writes slot 0 split)
    cudaFuncSetAttribute(flash_mma_kernel,
                         cudaFuncAttributeMaxDynamicSharedMemorySize, FSMEM_BYTES);
    flash_mma_kernel<<<dim3(B_DIM * H_DIM, T_DIM / FBQ), 256, FSMEM_BYTES>>>(
        bh + 3 * ASLOT, bl + 3 * ASLOT,
        bh + 4 * ASLOT,
        bh + 5 * ASLOT,
        bh, bl);

    // 4. output projection (fp32 out)
    cudaFuncSetAttribute(out_gemm_kernel,
                         cudaFuncAttributeMaxDynamicSharedMemorySize, GSMEM_BYTES);
    out_gemm_kernel<<<dim3(8, 64), 256, GSMEM_BYTES>>>(
        bh, bl, wh + 3 * WSLOT, bo, out);
}

// round 10
// speedup vs baseline: 7.6799x; 1.6190x over previous
#include <cuda_runtime.h>
#include <cuda_fp16.h>
#include <cstdint>

// Problem constants (fixed by the dataset)
#define T_DIM   2048
#define B_DIM   4
#define E_DIM   1024
#define H_DIM   16
#define D_HEAD  64
#define MROWS   (T_DIM * B_DIM)           // 8192
#define ASLOT   ((size_t)MROWS * E_DIM)   // 8M elems per activation slot
#define WSLOT   ((size_t)E_DIM * E_DIM)   // 1M elems per weight slot

// fp16 scratch. Activation slots: 0=query/attn_out, 1=key, 2=value,
// 3=q_proj, 4=k_proj, 5=v_proj. Weights: slots 0..3 (wq wk wv wo).
__device__ __align__(256) __half g_bh[6 * ASLOT];
__device__ __align__(256) __half g_wh[4 * WSLOT];

// ============================================================================
// helpers
// ============================================================================
__device__ __forceinline__ uint32_t smem_u32(const void* p) {
    uint32_t a;
    asm("{ .reg .u64 t; cvta.to.shared.u64 t, %1; cvt.u32.u64 %0, t; }"
        : "=r"(a) : "l"(p));
    return a;
}

#define CP16(smem, gptr) \
    asm volatile("cp.async.cg.shared.global [%0], [%1], 16;" :: "r"(smem), "l"(gptr))
#define CP_COMMIT() asm volatile("cp.async.commit_group;" ::: "memory")
#define CP_WAIT0()  asm volatile("cp.async.wait_group 0;" ::: "memory")

#define LDSM_X4(r0, r1, r2, r3, addr) \
    asm volatile("ldmatrix.sync.aligned.m8n8.x4.shared.b16 {%0,%1,%2,%3}, [%4];" \
                 : "=r"(r0), "=r"(r1), "=r"(r2), "=r"(r3) : "r"(addr))
#define LDSM_X4_TRANS(r0, r1, r2, r3, addr) \
    asm volatile("ldmatrix.sync.aligned.m8n8.x4.trans.shared.b16 {%0,%1,%2,%3}, [%4];" \
                 : "=r"(r0), "=r"(r1), "=r"(r2), "=r"(r3) : "r"(addr))
#define MMA_F16_P(d, a, b0, b1) \
    asm volatile("mma.sync.aligned.m16n8k16.row.col.f32.f16.f16.f32 " \
                 "{%0,%1,%2,%3}, {%4,%5,%6,%7}, {%8,%9}, {%0,%1,%2,%3};" \
                 : "+f"((d)[0]), "+f"((d)[1]), "+f"((d)[2]), "+f"((d)[3]) \
                 : "r"((a)[0]), "r"((a)[1]), "r"((a)[2]), "r"((a)[3]), \
                   "r"(b0), "r"(b1))

// pack 2 floats -> single fp16 pair
__device__ __forceinline__ uint32_t pack2h(float x, float y) {
    __half2 h2 = __halves2half2(__float2half_rn(x), __float2half_rn(y));
    return *reinterpret_cast<uint32_t*>(&h2);
}

// ============================================================================
// Convert kernels: fp32 -> fp16
// ============================================================================
__global__ __launch_bounds__(256) void conv_acts_kernel(
    const float* __restrict__ q, const float* __restrict__ k,
    const float* __restrict__ v, __half* __restrict__ bh)
{
    const int z = blockIdx.z;
    const float* src = (z == 0) ? q : (z == 1) ? k : v;
    size_t i = (size_t)blockIdx.x * 256 + threadIdx.x;   // float4 index
    float4 val = ((const float4*)src)[i];
    size_t base = (size_t)z * ASLOT + i * 4;
    *(uint2*)(bh + base) = make_uint2(pack2h(val.x, val.y), pack2h(val.z, val.w));
}

__global__ __launch_bounds__(256) void conv_w_kernel(
    const float* __restrict__ w0, const float* __restrict__ w1,
    const float* __restrict__ w2, const float* __restrict__ w3,
    __half* __restrict__ wh)
{
    const int z = blockIdx.z;
    const float* src = (z == 0) ? w0 : (z == 1) ? w1 : (z == 2) ? w2 : w3;
    size_t i = (size_t)blockIdx.x * 256 + threadIdx.x;
    float4 val = ((const float4*)src)[i];
    size_t base = (size_t)z * WSLOT + i * 4;
    *(uint2*)(wh + base) = make_uint2(pack2h(val.x, val.y), pack2h(val.z, val.w));
}

// ============================================================================
// fp16 GEMM (1-pass): C[m,n] = (sum_k A[m,k]*W[n,k] + bias[n]) * scale
// CTA 128x128, 8 warps (2m x 4n), KC=32, cp.async double buffer,
// one barrier per chunk.
// ============================================================================
#define KC   32
#define SA   40
#define MATB (128 * SA * 2)          // 10240 bytes per matrix tile
#define BUF_BYTES (2 * MATB)         // 20480 (A, W)
#define GSMEM_BYTES (2 * BUF_BYTES)  // 40960

template <bool F32OUT>
__device__ __forceinline__ void gemm_body(
    const __half* __restrict__ Ah, const __half* __restrict__ Wh,
    const float* __restrict__ bias, float scale,
    __half* __restrict__ Ch, float* __restrict__ Cf)
{
    extern __shared__ __half gsm[];
    const uint32_t sbase = smem_u32(gsm);
    const int tid  = threadIdx.x;
    const int wid  = tid >> 5;
    const int lane = tid & 31;
    const int m0 = blockIdx.y * 128;
    const int n0 = blockIdx.x * 128;
    const int wm = (wid >> 2) * 64;
    const int wn = (wid & 3) * 32;

    // cp.async load mapping
    const int cr = tid >> 1;
    const int cs = (tid & 1) * 2;
    const uint32_t sOff = ((uint32_t)cr * SA + cs * 8) * 2;
    const size_t gA = (size_t)(m0 + cr) * E_DIM + cs * 8;
    const size_t gW = (size_t)(n0 + cr) * E_DIM + cs * 8;

#define GEMM_ISSUE(c, b) do {                                            \
    uint32_t sd = sbase + (uint32_t)(b) * BUF_BYTES + sOff;              \
    const __half* g;                                                     \
    g = Ah + gA + (c) * KC; CP16(sd,        g); CP16(sd + 16,        g + 8); \
    g = Wh + gW + (c) * KC; CP16(sd + MATB, g); CP16(sd + MATB + 16, g + 8); \
    CP_COMMIT();                                                         \
} while (0)

    // fragment addressing
    const int arow  = (lane & 7) + ((lane >> 3) & 1) * 8;
    const int akoff = (lane >> 4) * 8;
    const int brow4 = (lane & 7) + ((lane >> 4) & 1) * 8;
    const int bk4   = ((lane >> 3) & 1) * 8;

    float acc[4][4][4];
#pragma unroll
    for (int i = 0; i < 4; i++)
#pragma unroll
        for (int j = 0; j < 4; j++)
#pragma unroll
            for (int t = 0; t < 4; t++) acc[i][j][t] = 0.0f;

    GEMM_ISSUE(0, 0);
    CP_WAIT0();
    __syncthreads();

    const int NC = E_DIM / KC;   // 32
    for (int c = 0; c < NC; c++) {
        if (c + 1 < NC) GEMM_ISSUE(c + 1, (c + 1) & 1);

        const uint32_t bufb = sbase + (uint32_t)(c & 1) * BUF_BYTES;
#pragma unroll
        for (int kk = 0; kk < 2; kk++) {
            uint32_t ah[4][4];
#pragma unroll
            for (int ma = 0; ma < 4; ma++) {
                uint32_t off = ((uint32_t)(wm + ma * 16 + arow) * SA + kk * 16 + akoff) * 2;
                LDSM_X4(ah[ma][0], ah[ma][1], ah[ma][2], ah[ma][3], bufb + off);
            }
#pragma unroll
            for (int nap = 0; nap < 2; nap++) {
                uint32_t off = ((uint32_t)(wn + nap * 16 + brow4) * SA + kk * 16 + bk4) * 2;
                uint32_t bh[4];
                LDSM_X4(bh[0], bh[1], bh[2], bh[3], bufb + MATB + off);
#pragma unroll
                for (int ma = 0; ma < 4; ma++) {
                    MMA_F16_P(acc[ma][2 * nap],     ah[ma], bh[0], bh[1]);
                    MMA_F16_P(acc[ma][2 * nap + 1], ah[ma], bh[2], bh[3]);
                }
            }
        }
        CP_WAIT0();
        __syncthreads();
    }
#undef GEMM_ISSUE

    // epilogue
    const int erow = lane >> 2;
    const int ecol = (lane & 3) * 2;
#pragma unroll
    for (int na = 0; na < 4; na++) {
        int col = n0 + wn + na * 8 + ecol;
        float b0 = bias[col], b1 = bias[col + 1];
#pragma unroll
        for (int ma = 0; ma < 4; ma++) {
            int row = m0 + wm + ma * 16 + erow;
            float v00 = (acc[ma][na][0] + b0) * scale;
            float v01 = (acc[ma][na][1] + b1) * scale;
            float v10 = (acc[ma][na][2] + b0) * scale;
            float v11 = (acc[ma][na][3] + b1) * scale;
            if (F32OUT) {
                *(float2*)(Cf + (size_t)row * E_DIM + col) = make_float2(v00, v01);
                *(float2*)(Cf + (size_t)(row + 8) * E_DIM + col) = make_float2(v10, v11);
            } else {
                *(uint32_t*)(Ch + (size_t)row * E_DIM + col) = pack2h(v00, v01);
                *(uint32_t*)(Ch + (size_t)(row + 8) * E_DIM + col) = pack2h(v10, v11);
            }
        }
    }
}

// merged q/k/v projection (gridDim.z = 3)
__global__ __launch_bounds__(256, 2) void qkv_gemm_kernel(
    const __half* __restrict__ actH, const __half* __restrict__ wH,
    const float* __restrict__ bq, const float* __restrict__ bk,
    const float* __restrict__ bv, __half* __restrict__ outH)
{
    const int z = blockIdx.z;
    const float* bias = (z == 0) ? bq : (z == 1) ? bk : bv;
    const float scale = (z == 0) ? 0.125f : 1.0f;
    gemm_body<false>(actH + (size_t)z * ASLOT, wH + (size_t)z * WSLOT,
                     bias, scale, outH + (size_t)(z + 3) * ASLOT, nullptr);
}

// output projection, fp32 out
__global__ __launch_bounds__(256, 2) void out_gemm_kernel(
    const __half* __restrict__ Ah, const __half* __restrict__ Wh,
    const float* __restrict__ bias, float* __restrict__ Cf)
{
    gemm_body<true>(Ah, Wh, bias, 1.0f, nullptr, Cf);
}

// ============================================================================
// Flash attention on tensor cores (1-pass fp16), causal.
// S = Q*K ; O += P*V, all single fp16 operands, fp32 accumulate.
// cp.async double-buffered K/V, one barrier per tile.
// ============================================================================
#define FBQ 128
#define FBS 64
#define FP  72
#define QMATB (FBQ * FP * 2)                    // 18432
#define KVMATB (FBS * FP * 2)                   // 9216
#define KVBUF (2 * KVMATB)                      // 18432 (Kh + Vh)
#define FSMEM_BYTES (QMATB + 2 * KVBUF)         // 55296

__global__ __launch_bounds__(256, 2) void flash_mma_kernel(
    const __half* __restrict__ Qh_g, const __half* __restrict__ Kh_g,
    const __half* __restrict__ Vh_g, __half* __restrict__ Oh_g)
{
    extern __shared__ __half fsm[];
    const uint32_t sb  = smem_u32(fsm);
    const uint32_t QhB = sb;
    const uint32_t kvbase = sb + QMATB;         // buf b at kvbase + b*KVBUF

    const int tid  = threadIdx.x;
    const int wid  = tid >> 5;
    const int lane = tid & 31;
    const int head = blockIdx.x;                       // b*H + h
    const int qtile = (int)(gridDim.y - 1) - (int)blockIdx.y;  // heavy first
    const int b = head >> 4;
    const int h = head & 15;
    const int t0 = qtile * FBQ;

    // cp.async mappings
    const int qr = tid >> 1;              // 0..127
    const int qc = (tid & 1) * 32;        // col base
    const int kr = tid >> 2;              // 0..63
    const int kc = (tid & 3) * 16;        // col base

    const size_t qrow = ((size_t)(t0 + qr) * B_DIM + b) * E_DIM + h * D_HEAD + qc;
    const size_t krowstride = (size_t)B_DIM * E_DIM;
    const size_t kcol0 = (size_t)b * E_DIM + h * D_HEAD + kc;

#define FLASH_ISSUE_KV(s0v, bufsel) do {                                           \
    uint32_t bufb = kvbase + (uint32_t)(bufsel) * KVBUF + ((uint32_t)kr * FP + kc) * 2; \
    size_t g = (size_t)((s0v) + kr) * krowstride + kcol0;                          \
    CP16(bufb,              Kh_g + g); CP16(bufb + 16,          Kh_g + g + 8);     \
    CP16(bufb + KVMATB,     Vh_g + g); CP16(bufb + KVMATB + 16, Vh_g + g + 8);     \
    CP_COMMIT();                                                                   \
} while (0)

    // ---- prologue: Q + tile0 in flight
    {
        uint32_t sq = QhB + ((uint32_t)qr * FP + qc) * 2;
#pragma unroll
        for (int u = 0; u < 4; u++)
            CP16(sq + u * 16, Qh_g + qrow + u * 8);
    }
    FLASH_ISSUE_KV(0, 0);
    CP_WAIT0();
    __syncthreads();

    // ---- Q A-fragments (persist across all s-tiles)
    const int arow  = (lane & 7) + ((lane >> 3) & 1) * 8;
    const int akoff = (lane >> 4) * 8;
    uint32_t qah[4][4];
#pragma unroll
    for (int kcn = 0; kcn < 4; kcn++) {
        uint32_t off = ((uint32_t)(wid * 16 + arow) * FP + kcn * 16 + akoff) * 2;
        LDSM_X4(qah[kcn][0], qah[kcn][1], qah[kcn][2], qah[kcn][3], QhB + off);
    }

    // K (non-trans x4) / V (trans x4) fragment addressing
    const int krow4 = (lane & 7) + ((lane >> 4) & 1) * 8;
    const int kcol4 = ((lane >> 3) & 1) * 8;
    const int vrow  = lane & 15;
    const int vcol  = ((lane >> 4) & 1) * 8;

    float m0 = -1e30f, m1 = -1e30f, l0 = 0.0f, l1 = 0.0f;
    float oacc[8][4];
#pragma unroll
    for (int i = 0; i < 8; i++)
#pragma unroll
        for (int t = 0; t < 4; t++) oacc[i][t] = 0.0f;

    const int wrow_min = t0 + wid * 16;
    const int wrow_max = wrow_min + 15;
    const int ntiles = 2 * qtile + 2;

    for (int st = 0; st < ntiles; st++) {
        const int s0 = st * FBS;
        if (st + 1 < ntiles) FLASH_ISSUE_KV(s0 + FBS, (st + 1) & 1);

        if (s0 <= wrow_max) {
            const uint32_t KhB = kvbase + (uint32_t)(st & 1) * KVBUF;
            const uint32_t VhB = KhB + KVMATB;

            // ---- S = Q K^T
            float sacc[8][4];
#pragma unroll
            for (int i = 0; i < 8; i++)
#pragma unroll
                for (int t = 0; t < 4; t++) sacc[i][t] = 0.0f;

#pragma unroll
            for (int ntp = 0; ntp < 4; ntp++) {
#pragma unroll
                for (int kcn = 0; kcn < 4; kcn++) {
                    uint32_t off = ((uint32_t)(ntp * 16 + krow4) * FP + kcn * 16 + kcol4) * 2;
                    uint32_t bh[4];
                    LDSM_X4(bh[0], bh[1], bh[2], bh[3], KhB + off);
                    MMA_F16_P(sacc[2 * ntp],     qah[kcn], bh[0], bh[1]);
                    MMA_F16_P(sacc[2 * ntp + 1], qah[kcn], bh[2], bh[3]);
                }
            }

            // ---- causal mask (whenever tile reaches past warp's first row)
            if (s0 + FBS - 1 > wrow_min) {
                int r0g = wrow_min + (lane >> 2);
                int r1g = r0g + 8;
#pragma unroll
                for (int nt = 0; nt < 8; nt++) {
                    int c0g = s0 + nt * 8 + (lane & 3) * 2;
                    if (c0g     > r0g) sacc[nt][0] = -1e9f;
                    if (c0g + 1 > r0g) sacc[nt][1] = -1e9f;
                    if (c0g     > r1g) sacc[nt][2] = -1e9f;
                    if (c0g + 1 > r1g) sacc[nt][3] = -1e9f;
                }
            }

            // ---- online softmax
            float rmax0 = -1e30f, rmax1 = -1e30f;
#pragma unroll
            for (int nt = 0; nt < 8; nt++) {
                rmax0 = fmaxf(rmax0, fmaxf(sacc[nt][0], sacc[nt][1]));
                rmax1 = fmaxf(rmax1, fmaxf(sacc[nt][2], sacc[nt][3]));
            }
            rmax0 = fmaxf(rmax0, __shfl_xor_sync(0xffffffffu, rmax0, 1));
            rmax0 = fmaxf(rmax0, __shfl_xor_sync(0xffffffffu, rmax0, 2));
            rmax1 = fmaxf(rmax1, __shfl_xor_sync(0xffffffffu, rmax1, 1));
            rmax1 = fmaxf(rmax1, __shfl_xor_sync(0xffffffffu, rmax1, 2));

            float mn0 = fmaxf(m0, rmax0);
            float mn1 = fmaxf(m1, rmax1);
            float a0 = __expf(m0 - mn0);
            float a1 = __expf(m1 - mn1);

            float rs0 = 0.0f, rs1 = 0.0f;
            uint32_t pah[4][4];
#pragma unroll
            for (int nt = 0; nt < 8; nt++) {
                float p0 = __expf(sacc[nt][0] - mn0);
                float p1 = __expf(sacc[nt][1] - mn0);
                float p2 = __expf(sacc[nt][2] - mn1);
                float p3 = __expf(sacc[nt][3] - mn1);
                rs0 += p0 + p1;
                rs1 += p2 + p3;
                int kcn = nt >> 1, half = nt & 1;
                pah[kcn][half * 2 + 0] = pack2h(p0, p1);
                pah[kcn][half * 2 + 1] = pack2h(p2, p3);
            }
            rs0 += __shfl_xor_sync(0xffffffffu, rs0, 1);
            rs0 += __shfl_xor_sync(0xffffffffu, rs0, 2);
            rs1 += __shfl_xor_sync(0xffffffffu, rs1, 1);
            rs1 += __shfl_xor_sync(0xffffffffu, rs1, 2);

            l0 = l0 * a0 + rs0;
            l1 = l1 * a1 + rs1;
            m0 = mn0; m1 = mn1;

#pragma unroll
            for (int dt = 0; dt < 8; dt++) {
                oacc[dt][0] *= a0; oacc[dt][1] *= a0;
                oacc[dt][2] *= a1; oacc[dt][3] *= a1;
            }

            // ---- O += P V, V[s][d] via trans x4
#pragma unroll
            for (int dtp = 0; dtp < 4; dtp++) {
#pragma unroll
                for (int kcn = 0; kcn < 4; kcn++) {
                    uint32_t off = ((uint32_t)(kcn * 16 + vrow) * FP + dtp * 16 + vcol) * 2;
                    uint32_t vh[4];
                    LDSM_X4_TRANS(vh[0], vh[1], vh[2], vh[3], VhB + off);
                    MMA_F16_P(oacc[2 * dtp],     pah[kcn], vh[0], vh[1]);
                    MMA_F16_P(oacc[2 * dtp + 1], pah[kcn], vh[2], vh[3]);
                }
            }
        }
        CP_WAIT0();
        __syncthreads();
    }
#undef FLASH_ISSUE_KV

    // ---- normalize + write fp16 (consumed by out-projection GEMM)
    float inv0 = 1.0f / l0;
    float inv1 = 1.0f / l1;
    int r0g = t0 + wid * 16 + (lane >> 2);
    size_t row0 = ((size_t)r0g * B_DIM + b) * E_DIM;
    size_t row1 = ((size_t)(r0g + 8) * B_DIM + b) * E_DIM;
#pragma unroll
    for (int dt = 0; dt < 8; dt++) {
        int col = h * D_HEAD + dt * 8 + (lane & 3) * 2;
        *(uint32_t*)(Oh_g + row0 + col) = pack2h(oacc[dt][0] * inv0, oacc[dt][1] * inv0);
        *(uint32_t*)(Oh_g + row1 + col) = pack2h(oacc[dt][2] * inv1, oacc[dt][3] * inv1);
    }
}

// ============================================================================
extern "C" void kernel_launch(void* const* d_in, const int* in_sizes, int n_in,
                              void* d_out, int out_size)
{
    const float* query = (const float*)d_in[0];
    const float* key   = (const float*)d_in[1];
    const float* value = (const float*)d_in[2];
    // d_in[3] = attn_mask (pure causal; applied analytically)
    const float* wq = (const float*)d_in[4];
    const float* bq = (const float*)d_in[5];
    const float* wk = (const float*)d_in[6];
    const float* bk = (const float*)d_in[7];
    const float* wv = (const float*)d_in[8];
    const float* bv = (const float*)d_in[9];
    const float* wo = (const float*)d_in[10];
    const float* bo = (const float*)d_in[11];
    float* out = (float*)d_out;

    __half *bh, *wh;
    cudaGetSymbolAddress((void**)&bh, g_bh);
    cudaGetSymbolAddress((void**)&wh, g_wh);

    // 1. convert inputs + weights to fp16
    conv_acts_kernel<<<dim3(MROWS * E_DIM / 4 / 256, 1, 3), 256>>>(
        query, key, value, bh);
    conv_w_kernel<<<dim3(E_DIM * E_DIM / 4 / 256, 1, 4), 256>>>(
        wq, wk, wv, wo, wh);

    // 2. merged q/k/v projections (fp16 out, slots 3..5)
    cudaFuncSetAttribute(qkv_gemm_kernel,
                         cudaFuncAttributeMaxDynamicSharedMemorySize, GSMEM_BYTES);
    qkv_gemm_kernel<<<dim3(8, 64, 3), 256, GSMEM_BYTES>>>(
        bh, wh, bq, bk, bv, bh);

    // 3. causal flash attention (reads slots 3..5, writes slot 0)
    cudaFuncSetAttribute(flash_mma_kernel,
                         cudaFuncAttributeMaxDynamicSharedMemorySize, FSMEM_BYTES);
    flash_mma_kernel<<<dim3(B_DIM * H_DIM, T_DIM / FBQ), 256, FSMEM_BYTES>>>(
        bh + 3 * ASLOT, bh + 4 * ASLOT, bh + 5 * ASLOT, bh);

    // 4. output projection (fp32 out)
    cudaFuncSetAttribute(out_gemm_kernel,
                         cudaFuncAttributeMaxDynamicSharedMemorySize, GSMEM_BYTES);
    out_gemm_kernel<<<dim3(8, 64), 256, GSMEM_BYTES>>>(
        bh, wh + 3 * WSLOT, bo, out);
}

// round 11
// speedup vs baseline: 8.0110x; 1.0431x over previous
#include <cuda_runtime.h>
#include <cuda_fp16.h>
#include <cstdint>

// Problem constants (fixed by the dataset)
#define T_DIM   2048
#define B_DIM   4
#define E_DIM   1024
#define H_DIM   16
#define D_HEAD  64
#define MROWS   (T_DIM * B_DIM)           // 8192
#define ASLOT   ((size_t)MROWS * E_DIM)   // 8M elems per activation slot
#define WSLOT   ((size_t)E_DIM * E_DIM)   // 1M elems per weight slot

// fp16 scratch. Activation slots: 0=query/attn_out, 1=key, 2=value,
// 3=q_proj, 4=k_proj, 5=v_proj. Weights: slots 0..3 (wq wk wv wo).
__device__ __align__(256) __half g_bh[6 * ASLOT];
__device__ __align__(256) __half g_wh[4 * WSLOT];

// log2(e): q-scores are computed in base-2 domain (softmax invariant)
#define LOG2E 1.4426950408889634f

// ============================================================================
// helpers
// ============================================================================
__device__ __forceinline__ uint32_t smem_u32(const void* p) {
    uint32_t a;
    asm("{ .reg .u64 t; cvta.to.shared.u64 t, %1; cvt.u32.u64 %0, t; }"
        : "=r"(a) : "l"(p));
    return a;
}

#define CP16(smem, gptr) \
    asm volatile("cp.async.cg.shared.global [%0], [%1], 16;" :: "r"(smem), "l"(gptr))
#define CP_COMMIT() asm volatile("cp.async.commit_group;" ::: "memory")
#define CP_WAIT1()  asm volatile("cp.async.wait_group 1;" ::: "memory")

#define LDSM_X4(r0, r1, r2, r3, addr) \
    asm volatile("ldmatrix.sync.aligned.m8n8.x4.shared.b16 {%0,%1,%2,%3}, [%4];" \
                 : "=r"(r0), "=r"(r1), "=r"(r2), "=r"(r3) : "r"(addr))
#define LDSM_X4_TRANS(r0, r1, r2, r3, addr) \
    asm volatile("ldmatrix.sync.aligned.m8n8.x4.trans.shared.b16 {%0,%1,%2,%3}, [%4];" \
                 : "=r"(r0), "=r"(r1), "=r"(r2), "=r"(r3) : "r"(addr))
#define MMA_F16_P(d, a, b0, b1) \
    asm volatile("mma.sync.aligned.m16n8k16.row.col.f32.f16.f16.f32 " \
                 "{%0,%1,%2,%3}, {%4,%5,%6,%7}, {%8,%9}, {%0,%1,%2,%3};" \
                 : "+f"((d)[0]), "+f"((d)[1]), "+f"((d)[2]), "+f"((d)[3]) \
                 : "r"((a)[0]), "r"((a)[1]), "r"((a)[2]), "r"((a)[3]), \
                   "r"(b0), "r"(b1))

// pack 2 floats -> single fp16 pair, one cvt.rn.f16x2.f32 (x = low half)
__device__ __forceinline__ uint32_t pack2h(float x, float y) {
    uint32_t r;
    asm("cvt.rn.f16x2.f32 %0, %1, %2;" : "=r"(r) : "f"(y), "f"(x));
    return r;
}

// ============================================================================
// Convert kernels: fp32 -> fp16
// ============================================================================
__global__ __launch_bounds__(256) void conv_acts_kernel(
    const float* __restrict__ q, const float* __restrict__ k,
    const float* __restrict__ v, __half* __restrict__ bh)
{
    const int z = blockIdx.z;
    const float* src = (z == 0) ? q : (z == 1) ? k : v;
    size_t i = (size_t)blockIdx.x * 256 + threadIdx.x;   // float4 index
    float4 val = ((const float4*)src)[i];
    size_t base = (size_t)z * ASLOT + i * 4;
    *(uint2*)(bh + base) = make_uint2(pack2h(val.x, val.y), pack2h(val.z, val.w));
}

__global__ __launch_bounds__(256) void conv_w_kernel(
    const float* __restrict__ w0, const float* __restrict__ w1,
    const float* __restrict__ w2, const float* __restrict__ w3,
    __half* __restrict__ wh)
{
    const int z = blockIdx.z;
    const float* src = (z == 0) ? w0 : (z == 1) ? w1 : (z == 2) ? w2 : w3;
    size_t i = (size_t)blockIdx.x * 256 + threadIdx.x;
    float4 val = ((const float4*)src)[i];
    size_t base = (size_t)z * WSLOT + i * 4;
    *(uint2*)(wh + base) = make_uint2(pack2h(val.x, val.y), pack2h(val.z, val.w));
}

// ============================================================================
// fp16 GEMM (1-pass): C[m,n] = (sum_k A[m,k]*W[n,k] + bias[n]) * scale
// CTA 128x128, 8 warps (2m x 4n), KC=32, cp.async TRIPLE buffer
// (wait_group 1 -> compute never waits on the in-flight prefetch).
// ============================================================================
#define KC   32
#define SA   40
#define MATB (128 * SA * 2)          // 10240 bytes per matrix tile
#define BUF_BYTES (2 * MATB)         // 20480 (A, W)
#define GSMEM_BYTES (3 * BUF_BYTES)  // 61440

template <bool F32OUT>
__device__ __forceinline__ void gemm_body(
    const __half* __restrict__ Ah, const __half* __restrict__ Wh,
    const float* __restrict__ bias, float scale,
    __half* __restrict__ Ch, float* __restrict__ Cf)
{
    extern __shared__ __half gsm[];
    const uint32_t sbase = smem_u32(gsm);
    const int tid  = threadIdx.x;
    const int wid  = tid >> 5;
    const int lane = tid & 31;
    const int m0 = blockIdx.y * 128;
    const int n0 = blockIdx.x * 128;
    const int wm = (wid >> 2) * 64;
    const int wn = (wid & 3) * 32;

    // cp.async load mapping
    const int cr = tid >> 1;
    const int cs = (tid & 1) * 2;
    const uint32_t sOff = ((uint32_t)cr * SA + cs * 8) * 2;
    const size_t gA = (size_t)(m0 + cr) * E_DIM + cs * 8;
    const size_t gW = (size_t)(n0 + cr) * E_DIM + cs * 8;

#define GEMM_ISSUE(c, b) do {                                            \
    uint32_t sd = sbase + (uint32_t)(b) * BUF_BYTES + sOff;              \
    const __half* g;                                                     \
    g = Ah + gA + (c) * KC; CP16(sd,        g); CP16(sd + 16,        g + 8); \
    g = Wh + gW + (c) * KC; CP16(sd + MATB, g); CP16(sd + MATB + 16, g + 8); \
    CP_COMMIT();                                                         \
} while (0)

    // fragment addressing
    const int arow  = (lane & 7) + ((lane >> 3) & 1) * 8;
    const int akoff = (lane >> 4) * 8;
    const int brow4 = (lane & 7) + ((lane >> 4) & 1) * 8;
    const int bk4   = ((lane >> 3) & 1) * 8;

    float acc[4][4][4];
#pragma unroll
    for (int i = 0; i < 4; i++)
#pragma unroll
        for (int j = 0; j < 4; j++)
#pragma unroll
            for (int t = 0; t < 4; t++) acc[i][j][t] = 0.0f;

    GEMM_ISSUE(0, 0);
    GEMM_ISSUE(1, 1);

    const int NC = E_DIM / KC;   // 32
    for (int c = 0; c < NC; c++) {
        CP_WAIT1();              // group c complete (c+1 may be in flight)
        __syncthreads();         // all warps done with buffer (c-1)%3
        if (c + 2 < NC) GEMM_ISSUE(c + 2, (c + 2) % 3);

        const uint32_t bufb = sbase + (uint32_t)(c % 3) * BUF_BYTES;
#pragma unroll
        for (int kk = 0; kk < 2; kk++) {
            uint32_t ah[4][4];
#pragma unroll
            for (int ma = 0; ma < 4; ma++) {
                uint32_t off = ((uint32_t)(wm + ma * 16 + arow) * SA + kk * 16 + akoff) * 2;
                LDSM_X4(ah[ma][0], ah[ma][1], ah[ma][2], ah[ma][3], bufb + off);
            }
#pragma unroll
            for (int nap = 0; nap < 2; nap++) {
                uint32_t off = ((uint32_t)(wn + nap * 16 + brow4) * SA + kk * 16 + bk4) * 2;
                uint32_t bh[4];
                LDSM_X4(bh[0], bh[1], bh[2], bh[3], bufb + MATB + off);
#pragma unroll
                for (int ma = 0; ma < 4; ma++) {
                    MMA_F16_P(acc[ma][2 * nap],     ah[ma], bh[0], bh[1]);
                    MMA_F16_P(acc[ma][2 * nap + 1], ah[ma], bh[2], bh[3]);
                }
            }
        }
    }
#undef GEMM_ISSUE

    // epilogue
    const int erow = lane >> 2;
    const int ecol = (lane & 3) * 2;
#pragma unroll
    for (int na = 0; na < 4; na++) {
        int col = n0 + wn + na * 8 + ecol;
        float b0 = bias[col], b1 = bias[col + 1];
#pragma unroll
        for (int ma = 0; ma < 4; ma++) {
            int row = m0 + wm + ma * 16 + erow;
            float v00 = (acc[ma][na][0] + b0) * scale;
            float v01 = (acc[ma][na][1] + b1) * scale;
            float v10 = (acc[ma][na][2] + b0) * scale;
            float v11 = (acc[ma][na][3] + b1) * scale;
            if (F32OUT) {
                *(float2*)(Cf + (size_t)row * E_DIM + col) = make_float2(v00, v01);
                *(float2*)(Cf + (size_t)(row + 8) * E_DIM + col) = make_float2(v10, v11);
            } else {
                *(uint32_t*)(Ch + (size_t)row * E_DIM + col) = pack2h(v00, v01);
                *(uint32_t*)(Ch + (size_t)(row + 8) * E_DIM + col) = pack2h(v10, v11);
            }
        }
    }
}

// merged q/k/v projection (gridDim.z = 3). q scores carry 0.125*log2e so the
// flash kernel can use exp2 directly.
__global__ __launch_bounds__(256, 2) void qkv_gemm_kernel(
    const __half* __restrict__ actH, const __half* __restrict__ wH,
    const float* __restrict__ bq, const float* __restrict__ bk,
    const float* __restrict__ bv, __half* __restrict__ outH)
{
    const int z = blockIdx.z;
    const float* bias = (z == 0) ? bq : (z == 1) ? bk : bv;
    const float scale = (z == 0) ? (0.125f * LOG2E) : 1.0f;
    gemm_body<false>(actH + (size_t)z * ASLOT, wH + (size_t)z * WSLOT,
                     bias, scale, outH + (size_t)(z + 3) * ASLOT, nullptr);
}

// output projection, fp32 out
__global__ __launch_bounds__(256, 2) void out_gemm_kernel(
    const __half* __restrict__ Ah, const __half* __restrict__ Wh,
    const float* __restrict__ bias, float* __restrict__ Cf)
{
    gemm_body<true>(Ah, Wh, bias, 1.0f, nullptr, Cf);
}

// ============================================================================
// Flash attention on tensor cores (1-pass fp16), causal, base-2 softmax.
// cp.async TRIPLE-buffered K/V (wait_group 1), one barrier per tile.
// ============================================================================
#define FBQ 128
#define FBS 64
#define FP  72
#define QMATB (FBQ * FP * 2)                    // 18432
#define KVMATB (FBS * FP * 2)                   // 9216
#define KVBUF (2 * KVMATB)                      // 18432 (Kh + Vh)
#define FSMEM_BYTES (QMATB + 3 * KVBUF)         // 73728

__global__ __launch_bounds__(256, 2) void flash_mma_kernel(
    const __half* __restrict__ Qh_g, const __half* __restrict__ Kh_g,
    const __half* __restrict__ Vh_g, __half* __restrict__ Oh_g)
{
    extern __shared__ __half fsm[];
    const uint32_t sb  = smem_u32(fsm);
    const uint32_t QhB = sb;
    const uint32_t kvbase = sb + QMATB;         // buf b at kvbase + b*KVBUF

    const int tid  = threadIdx.x;
    const int wid  = tid >> 5;
    const int lane = tid & 31;
    const int head = blockIdx.x;                       // b*H + h
    const int qtile = (int)(gridDim.y - 1) - (int)blockIdx.y;  // heavy first
    const int b = head >> 4;
    const int h = head & 15;
    const int t0 = qtile * FBQ;

    // cp.async mappings
    const int qr = tid >> 1;              // 0..127
    const int qc = (tid & 1) * 32;        // col base
    const int kr = tid >> 2;              // 0..63
    const int kc = (tid & 3) * 16;        // col base

    const size_t qrow = ((size_t)(t0 + qr) * B_DIM + b) * E_DIM + h * D_HEAD + qc;
    const size_t krowstride = (size_t)B_DIM * E_DIM;
    const size_t kcol0 = (size_t)b * E_DIM + h * D_HEAD + kc;

#define FLASH_ISSUE_KV(s0v, bufsel) do {                                           \
    uint32_t bufb = kvbase + (uint32_t)(bufsel) * KVBUF + ((uint32_t)kr * FP + kc) * 2; \
    size_t g = (size_t)((s0v) + kr) * krowstride + kcol0;                          \
    CP16(bufb,              Kh_g + g); CP16(bufb + 16,          Kh_g + g + 8);     \
    CP16(bufb + KVMATB,     Vh_g + g); CP16(bufb + KVMATB + 16, Vh_g + g + 8);     \
    CP_COMMIT();                                                                   \
} while (0)

    const int wrow_min = t0 + wid * 16;
    const int wrow_max = wrow_min + 15;
    const int ntiles = 2 * qtile + 2;     // always >= 2

    // ---- prologue: group0 = {Q, KV0}, group1 = {KV1}
    {
        uint32_t sq = QhB + ((uint32_t)qr * FP + qc) * 2;
#pragma unroll
        for (int u = 0; u < 4; u++)
            CP16(sq + u * 16, Qh_g + qrow + u * 8);
    }
    FLASH_ISSUE_KV(0, 0);                 // commits group 0 (includes Q)
    FLASH_ISSUE_KV(FBS, 1);               // commits group 1
    CP_WAIT1();                           // group 0 (Q + KV0) resident
    __syncthreads();

    // ---- Q A-fragments (persist across all s-tiles)
    const int arow  = (lane & 7) + ((lane >> 3) & 1) * 8;
    const int akoff = (lane >> 4) * 8;
    uint32_t qah[4][4];
#pragma unroll
    for (int kcn = 0; kcn < 4; kcn++) {
        uint32_t off = ((uint32_t)(wid * 16 + arow) * FP + kcn * 16 + akoff) * 2;
        LDSM_X4(qah[kcn][0], qah[kcn][1], qah[kcn][2], qah[kcn][3], QhB + off);
    }

    // K (non-trans x4) / V (trans x4) fragment addressing
    const int krow4 = (lane & 7) + ((lane >> 4) & 1) * 8;
    const int kcol4 = ((lane >> 3) & 1) * 8;
    const int vrow  = lane & 15;
    const int vcol  = ((lane >> 4) & 1) * 8;

    float m0 = -1e30f, m1 = -1e30f, l0 = 0.0f, l1 = 0.0f;
    float oacc[8][4];
#pragma unroll
    for (int i = 0; i < 8; i++)
#pragma unroll
        for (int t = 0; t < 4; t++) oacc[i][t] = 0.0f;

    for (int st = 0; st < ntiles; st++) {
        const int s0 = st * FBS;
        if (st + 2 < ntiles) FLASH_ISSUE_KV(s0 + 2 * FBS, (st + 2) % 3);

        if (s0 <= wrow_max) {
            const uint32_t KhB = kvbase + (uint32_t)(st % 3) * KVBUF;
            const uint32_t VhB = KhB + KVMATB;

            // ---- S = Q K^T (scores already in base-2 domain)
            float sacc[8][4];
#pragma unroll
            for (int i = 0; i < 8; i++)
#pragma unroll
                for (int t = 0; t < 4; t++) sacc[i][t] = 0.0f;

#pragma unroll
            for (int ntp = 0; ntp < 4; ntp++) {
#pragma unroll
                for (int kcn = 0; kcn < 4; kcn++) {
                    uint32_t off = ((uint32_t)(ntp * 16 + krow4) * FP + kcn * 16 + kcol4) * 2;
                    uint32_t bh[4];
                    LDSM_X4(bh[0], bh[1], bh[2], bh[3], KhB + off);
                    MMA_F16_P(sacc[2 * ntp],     qah[kcn], bh[0], bh[1]);
                    MMA_F16_P(sacc[2 * ntp + 1], qah[kcn], bh[2], bh[3]);
                }
            }

            // ---- causal mask (whenever tile reaches past warp's first row)
            if (s0 + FBS - 1 > wrow_min) {
                int r0g = wrow_min + (lane >> 2);
                int r1g = r0g + 8;
#pragma unroll
                for (int nt = 0; nt < 8; nt++) {
                    int c0g = s0 + nt * 8 + (lane & 3) * 2;
                    if (c0g     > r0g) sacc[nt][0] = -1e9f;
                    if (c0g + 1 > r0g) sacc[nt][1] = -1e9f;
                    if (c0g     > r1g) sacc[nt][2] = -1e9f;
                    if (c0g + 1 > r1g) sacc[nt][3] = -1e9f;
                }
            }

            // ---- online softmax (base-2)
            float rmax0 = -1e30f, rmax1 = -1e30f;
#pragma unroll
            for (int nt = 0; nt < 8; nt++) {
                rmax0 = fmaxf(rmax0, fmaxf(sacc[nt][0], sacc[nt][1]));
                rmax1 = fmaxf(rmax1, fmaxf(sacc[nt][2], sacc[nt][3]));
            }
            rmax0 = fmaxf(rmax0, __shfl_xor_sync(0xffffffffu, rmax0, 1));
            rmax0 = fmaxf(rmax0, __shfl_xor_sync(0xffffffffu, rmax0, 2));
            rmax1 = fmaxf(rmax1, __shfl_xor_sync(0xffffffffu, rmax1, 1));
            rmax1 = fmaxf(rmax1, __shfl_xor_sync(0xffffffffu, rmax1, 2));

            float mn0 = fmaxf(m0, rmax0);
            float mn1 = fmaxf(m1, rmax1);
            float a0 = exp2f(m0 - mn0);
            float a1 = exp2f(m1 - mn1);

            float rs0 = 0.0f, rs1 = 0.0f;
            uint32_t pah[4][4];
#pragma unroll
            for (int nt = 0; nt < 8; nt++) {
                float p0 = exp2f(sacc[nt][0] - mn0);
                float p1 = exp2f(sacc[nt][1] - mn0);
                float p2 = exp2f(sacc[nt][2] - mn1);
                float p3 = exp2f(sacc[nt][3] - mn1);
                rs0 += p0 + p1;
                rs1 += p2 + p3;
                int kcn = nt >> 1, half = nt & 1;
                pah[kcn][half * 2 + 0] = pack2h(p0, p1);
                pah[kcn][half * 2 + 1] = pack2h(p2, p3);
            }
            rs0 += __shfl_xor_sync(0xffffffffu, rs0, 1);
            rs0 += __shfl_xor_sync(0xffffffffu, rs0, 2);
            rs1 += __shfl_xor_sync(0xffffffffu, rs1, 1);
            rs1 += __shfl_xor_sync(0xffffffffu, rs1, 2);

            l0 = l0 * a0 + rs0;
            l1 = l1 * a1 + rs1;
            m0 = mn0; m1 = mn1;

#pragma unroll
            for (int dt = 0; dt < 8; dt++) {
                oacc[dt][0] *= a0; oacc[dt][1] *= a0;
                oacc[dt][2] *= a1; oacc[dt][3] *= a1;
            }

            // ---- O += P V, V[s][d] via trans x4
#pragma unroll
            for (int dtp = 0; dtp < 4; dtp++) {
#pragma unroll
                for (int kcn = 0; kcn < 4; kcn++) {
                    uint32_t off = ((uint32_t)(kcn * 16 + vrow) * FP + dtp * 16 + vcol) * 2;
                    uint32_t vh[4];
                    LDSM_X4_TRANS(vh[0], vh[1], vh[2], vh[3], VhB + off);
                    MMA_F16_P(oacc[2 * dtp],     pah[kcn], vh[0], vh[1]);
                    MMA_F16_P(oacc[2 * dtp + 1], pah[kcn], vh[2], vh[3]);
                }
            }
        }
        CP_WAIT1();              // group st+1 resident for next iteration
        __syncthreads();         // all warps done with buffer st%3
    }
#undef FLASH_ISSUE_KV

    // ---- normalize + write fp16 (consumed by out-projection GEMM)
    float inv0 = 1.0f / l0;
    float inv1 = 1.0f / l1;
    int r0g = t0 + wid * 16 + (lane >> 2);
    size_t row0 = ((size_t)r0g * B_DIM + b) * E_DIM;
    size_t row1 = ((size_t)(r0g + 8) * B_DIM + b) * E_DIM;
#pragma unroll
    for (int dt = 0; dt < 8; dt++) {
        int col = h * D_HEAD + dt * 8 + (lane & 3) * 2;
        *(uint32_t*)(Oh_g + row0 + col) = pack2h(oacc[dt][0] * inv0, oacc[dt][1] * inv0);
        *(uint32_t*)(Oh_g + row1 + col) = pack2h(oacc[dt][2] * inv1, oacc[dt][3] * inv1);
    }
}

// ============================================================================
extern "C" void kernel_launch(void* const* d_in, const int* in_sizes, int n_in,
                              void* d_out, int out_size)
{
    const float* query = (const float*)d_in[0];
    const float* key   = (const float*)d_in[1];
    const float* value = (const float*)d_in[2];
    // d_in[3] = attn_mask (pure causal; applied analytically)
    const float* wq = (const float*)d_in[4];
    const float* bq = (const float*)d_in[5];
    const float* wk = (const float*)d_in[6];
    const float* bk = (const float*)d_in[7];
    const float* wv = (const float*)d_in[8];
    const float* bv = (const float*)d_in[9];
    const float* wo = (const float*)d_in[10];
    const float* bo = (const float*)d_in[11];
    float* out = (float*)d_out;

    __half *bh, *wh;
    cudaGetSymbolAddress((void**)&bh, g_bh);
    cudaGetSymbolAddress((void**)&wh, g_wh);

    // 1. convert inputs + weights to fp16
    conv_acts_kernel<<<dim3(MROWS * E_DIM / 4 / 256, 1, 3), 256>>>(
        query, key, value, bh);
    conv_w_kernel<<<dim3(E_DIM * E_DIM / 4 / 256, 1, 4), 256>>>(
        wq, wk, wv, wo, wh);

    // 2. merged q/k/v projections (fp16 out, slots 3..5)
    cudaFuncSetAttribute(qkv_gemm_kernel,
                         cudaFuncAttributeMaxDynamicSharedMemorySize, GSMEM_BYTES);
    qkv_gemm_kernel<<<dim3(8, 64, 3), 256, GSMEM_BYTES>>>(
        bh, wh, bq, bk, bv, bh);

    // 3. causal flash attention (reads slots 3..5, writes slot 0)
    cudaFuncSetAttribute(flash_mma_kernel,
                         cudaFuncAttributeMaxDynamicSharedMemorySize, FSMEM_BYTES);
    flash_mma_kernel<<<dim3(B_DIM * H_DIM, T_DIM / FBQ), 256, FSMEM_BYTES>>>(
        bh + 3 * ASLOT, bh + 4 * ASLOT, bh + 5 * ASLOT, bh);

    // 4. output projection (fp32 out)
    cudaFuncSetAttribute(out_gemm_kernel,
                         cudaFuncAttributeMaxDynamicSharedMemorySize, GSMEM_BYTES);
    out_gemm_kernel<<<dim3(8, 64), 256, GSMEM_BYTES>>>(
        bh, wh + 3 * WSLOT, bo, out);
}

// round 12
// speedup vs baseline: 8.0478x; 1.0046x over previous
#include <cuda_runtime.h>
#include <cuda_fp16.h>
#include <cstdint>

// Problem constants (fixed by the dataset)
#define T_DIM   2048
#define B_DIM   4
#define E_DIM   1024
#define H_DIM   16
#define D_HEAD  64
#define MROWS   (T_DIM * B_DIM)           // 8192
#define ASLOT   ((size_t)MROWS * E_DIM)   // 8M elems per activation slot
#define WSLOT   ((size_t)E_DIM * E_DIM)   // 1M elems per weight slot

// fp16 scratch. Activation slots: 0=query/attn_out, 1=key, 2=value,
// 3=q_proj, 4=k_proj, 5=v_proj. Weights: slots 0..3 (wq wk wv wo).
__device__ __align__(256) __half g_bh[6 * ASLOT];
__device__ __align__(256) __half g_wh[4 * WSLOT];

// log2(e): q-scores are computed in base-2 domain (softmax invariant)
#define LOG2E 1.4426950408889634f

// ============================================================================
// helpers
// ============================================================================
__device__ __forceinline__ uint32_t smem_u32(const void* p) {
    uint32_t a;
    asm("{ .reg .u64 t; cvta.to.shared.u64 t, %1; cvt.u32.u64 %0, t; }"
        : "=r"(a) : "l"(p));
    return a;
}

#define CP16(smem, gptr) \
    asm volatile("cp.async.cg.shared.global [%0], [%1], 16;" :: "r"(smem), "l"(gptr))
#define CP_COMMIT() asm volatile("cp.async.commit_group;" ::: "memory")
#define CP_WAIT1()  asm volatile("cp.async.wait_group 1;" ::: "memory")
#define CP_WAIT2()  asm volatile("cp.async.wait_group 2;" ::: "memory")

#define LDSM_X4(r0, r1, r2, r3, addr) \
    asm volatile("ldmatrix.sync.aligned.m8n8.x4.shared.b16 {%0,%1,%2,%3}, [%4];" \
                 : "=r"(r0), "=r"(r1), "=r"(r2), "=r"(r3) : "r"(addr))
#define LDSM_X4_TRANS(r0, r1, r2, r3, addr) \
    asm volatile("ldmatrix.sync.aligned.m8n8.x4.trans.shared.b16 {%0,%1,%2,%3}, [%4];" \
                 : "=r"(r0), "=r"(r1), "=r"(r2), "=r"(r3) : "r"(addr))
#define MMA_F16_P(d, a, b0, b1) \
    asm volatile("mma.sync.aligned.m16n8k16.row.col.f32.f16.f16.f32 " \
                 "{%0,%1,%2,%3}, {%4,%5,%6,%7}, {%8,%9}, {%0,%1,%2,%3};" \
                 : "+f"((d)[0]), "+f"((d)[1]), "+f"((d)[2]), "+f"((d)[3]) \
                 : "r"((a)[0]), "r"((a)[1]), "r"((a)[2]), "r"((a)[3]), \
                   "r"(b0), "r"(b1))

// pack 2 floats -> single fp16 pair, one cvt.rn.f16x2.f32 (x = low half)
__device__ __forceinline__ uint32_t pack2h(float x, float y) {
    uint32_t r;
    asm("cvt.rn.f16x2.f32 %0, %1, %2;" : "=r"(r) : "f"(y), "f"(x));
    return r;
}
// packed fp16x2 exp2 (one MUFU op for two values)
__device__ __forceinline__ uint32_t exp2_h2(uint32_t x) {
    uint32_t r;
    asm("ex2.approx.f16x2 %0, %1;" : "=r"(r) : "r"(x));
    return r;
}
__device__ __forceinline__ uint32_t hadd2u(uint32_t a, uint32_t b) {
    uint32_t r;
    asm("add.f16x2 %0, %1, %2;" : "=r"(r) : "r"(a), "r"(b));
    return r;
}

// ============================================================================
// Convert kernels: fp32 -> fp16
// ============================================================================
__global__ __launch_bounds__(256) void conv_acts_kernel(
    const float* __restrict__ q, const float* __restrict__ k,
    const float* __restrict__ v, __half* __restrict__ bh)
{
    const int z = blockIdx.z;
    const float* src = (z == 0) ? q : (z == 1) ? k : v;
    size_t i = (size_t)blockIdx.x * 256 + threadIdx.x;   // float4 index
    float4 val = ((const float4*)src)[i];
    size_t base = (size_t)z * ASLOT + i * 4;
    *(uint2*)(bh + base) = make_uint2(pack2h(val.x, val.y), pack2h(val.z, val.w));
}

__global__ __launch_bounds__(256) void conv_w_kernel(
    const float* __restrict__ w0, const float* __restrict__ w1,
    const float* __restrict__ w2, const float* __restrict__ w3,
    __half* __restrict__ wh)
{
    const int z = blockIdx.z;
    const float* src = (z == 0) ? w0 : (z == 1) ? w1 : (z == 2) ? w2 : w3;
    size_t i = (size_t)blockIdx.x * 256 + threadIdx.x;
    float4 val = ((const float4*)src)[i];
    size_t base = (size_t)z * WSLOT + i * 4;
    *(uint2*)(wh + base) = make_uint2(pack2h(val.x, val.y), pack2h(val.z, val.w));
}

// ============================================================================
// fp16 GEMM: C[m,n] = (sum_k A[m,k]*W[n,k] + bias[n]) * scale
// CTA 128x128, 8 warps (2m x 4n), KC=32, cp.async 4-STAGE pipeline
// (wait_group 2; empty commit groups keep the cadence at the tail).
// ============================================================================
#define KC   32
#define SA   40
#define MATB (128 * SA * 2)          // 10240 bytes per matrix tile
#define BUF_BYTES (2 * MATB)         // 20480 (A, W)
#define GSMEM_BYTES (4 * BUF_BYTES)  // 81920

template <bool F32OUT>
__device__ __forceinline__ void gemm_body(
    const __half* __restrict__ Ah, const __half* __restrict__ Wh,
    const float* __restrict__ bias, float scale,
    __half* __restrict__ Ch, float* __restrict__ Cf)
{
    extern __shared__ __half gsm[];
    const uint32_t sbase = smem_u32(gsm);
    const int tid  = threadIdx.x;
    const int wid  = tid >> 5;
    const int lane = tid & 31;
    const int m0 = blockIdx.y * 128;
    const int n0 = blockIdx.x * 128;
    const int wm = (wid >> 2) * 64;
    const int wn = (wid & 3) * 32;

    // cp.async load mapping
    const int cr = tid >> 1;
    const int cs = (tid & 1) * 2;
    const uint32_t sOff = ((uint32_t)cr * SA + cs * 8) * 2;
    const size_t gA = (size_t)(m0 + cr) * E_DIM + cs * 8;
    const size_t gW = (size_t)(n0 + cr) * E_DIM + cs * 8;

    const int NC = E_DIM / KC;   // 32

// always commits (empty group when c >= NC) so wait_group counts stay aligned
#define GEMM_ISSUE(c) do {                                               \
    if ((c) < NC) {                                                      \
        uint32_t sd = sbase + (uint32_t)((c) & 3) * BUF_BYTES + sOff;    \
        const __half* g;                                                 \
        g = Ah + gA + (size_t)(c) * KC;                                  \
        CP16(sd,        g); CP16(sd + 16,        g + 8);                 \
        g = Wh + gW + (size_t)(c) * KC;                                  \
        CP16(sd + MATB, g); CP16(sd + MATB + 16, g + 8);                 \
    }                                                                    \
    CP_COMMIT();                                                         \
} while (0)

    // fragment addressing
    const int arow  = (lane & 7) + ((lane >> 3) & 1) * 8;
    const int akoff = (lane >> 4) * 8;
    const int brow4 = (lane & 7) + ((lane >> 4) & 1) * 8;
    const int bk4   = ((lane >> 3) & 1) * 8;

    float acc[4][4][4];
#pragma unroll
    for (int i = 0; i < 4; i++)
#pragma unroll
        for (int j = 0; j < 4; j++)
#pragma unroll
            for (int t = 0; t < 4; t++) acc[i][j][t] = 0.0f;

    GEMM_ISSUE(0);
    GEMM_ISSUE(1);
    GEMM_ISSUE(2);

    for (int c = 0; c < NC; c++) {
        CP_WAIT2();              // group c complete (c+1, c+2 may be in flight)
        __syncthreads();         // all warps done with buffer (c+3)&3's old data
        GEMM_ISSUE(c + 3);

        const uint32_t bufb = sbase + (uint32_t)(c & 3) * BUF_BYTES;
#pragma unroll
        for (int kk = 0; kk < 2; kk++) {
            uint32_t ah[4][4];
#pragma unroll
            for (int ma = 0; ma < 4; ma++) {
                uint32_t off = ((uint32_t)(wm + ma * 16 + arow) * SA + kk * 16 + akoff) * 2;
                LDSM_X4(ah[ma][0], ah[ma][1], ah[ma][2], ah[ma][3], bufb + off);
            }
#pragma unroll
            for (int nap = 0; nap < 2; nap++) {
                uint32_t off = ((uint32_t)(wn + nap * 16 + brow4) * SA + kk * 16 + bk4) * 2;
                uint32_t bh[4];
                LDSM_X4(bh[0], bh[1], bh[2], bh[3], bufb + MATB + off);
#pragma unroll
                for (int ma = 0; ma < 4; ma++) {
                    MMA_F16_P(acc[ma][2 * nap],     ah[ma], bh[0], bh[1]);
                    MMA_F16_P(acc[ma][2 * nap + 1], ah[ma], bh[2], bh[3]);
                }
            }
        }
    }
#undef GEMM_ISSUE

    // epilogue
    const int erow = lane >> 2;
    const int ecol = (lane & 3) * 2;
#pragma unroll
    for (int na = 0; na < 4; na++) {
        int col = n0 + wn + na * 8 + ecol;
        float b0 = bias[col], b1 = bias[col + 1];
#pragma unroll
        for (int ma = 0; ma < 4; ma++) {
            int row = m0 + wm + ma * 16 + erow;
            float v00 = (acc[ma][na][0] + b0) * scale;
            float v01 = (acc[ma][na][1] + b1) * scale;
            float v10 = (acc[ma][na][2] + b0) * scale;
            float v11 = (acc[ma][na][3] + b1) * scale;
            if (F32OUT) {
                *(float2*)(Cf + (size_t)row * E_DIM + col) = make_float2(v00, v01);
                *(float2*)(Cf + (size_t)(row + 8) * E_DIM + col) = make_float2(v10, v11);
            } else {
                *(uint32_t*)(Ch + (size_t)row * E_DIM + col) = pack2h(v00, v01);
                *(uint32_t*)(Ch + (size_t)(row + 8) * E_DIM + col) = pack2h(v10, v11);
            }
        }
    }
}

// merged q/k/v projection (gridDim.z = 3). q scores carry 0.125*log2e so the
// flash kernel can use exp2 directly.
__global__ __launch_bounds__(256, 2) void qkv_gemm_kernel(
    const __half* __restrict__ actH, const __half* __restrict__ wH,
    const float* __restrict__ bq, const float* __restrict__ bk,
    const float* __restrict__ bv, __half* __restrict__ outH)
{
    const int z = blockIdx.z;
    const float* bias = (z == 0) ? bq : (z == 1) ? bk : bv;
    const float scale = (z == 0) ? (0.125f * LOG2E) : 1.0f;
    gemm_body<false>(actH + (size_t)z * ASLOT, wH + (size_t)z * WSLOT,
                     bias, scale, outH + (size_t)(z + 3) * ASLOT, nullptr);
}

// output projection, fp32 out
__global__ __launch_bounds__(256, 2) void out_gemm_kernel(
    const __half* __restrict__ Ah, const __half* __restrict__ Wh,
    const float* __restrict__ bias, float* __restrict__ Cf)
{
    gemm_body<true>(Ah, Wh, bias, 1.0f, nullptr, Cf);
}

// ============================================================================
// Flash attention on tensor cores (1-pass fp16), causal, base-2 softmax with
// packed ex2.approx.f16x2 (halves MUFU pressure). cp.async triple buffer;
// empty commit groups keep the wait cadence correct at the tail.
// ============================================================================
#define FBQ 128
#define FBS 64
#define FP  72
#define QMATB (FBQ * FP * 2)                    // 18432
#define KVMATB (FBS * FP * 2)                   // 9216
#define KVBUF (2 * KVMATB)                      // 18432 (Kh + Vh)
#define FSMEM_BYTES (QMATB + 3 * KVBUF)         // 73728

__global__ __launch_bounds__(256, 2) void flash_mma_kernel(
    const __half* __restrict__ Qh_g, const __half* __restrict__ Kh_g,
    const __half* __restrict__ Vh_g, __half* __restrict__ Oh_g)
{
    extern __shared__ __half fsm[];
    const uint32_t sb  = smem_u32(fsm);
    const uint32_t QhB = sb;
    const uint32_t kvbase = sb + QMATB;         // buf b at kvbase + b*KVBUF

    const int tid  = threadIdx.x;
    const int wid  = tid >> 5;
    const int lane = tid & 31;
    const int head = blockIdx.x;                       // b*H + h
    const int qtile = (int)(gridDim.y - 1) - (int)blockIdx.y;  // heavy first
    const int b = head >> 4;
    const int h = head & 15;
    const int t0 = qtile * FBQ;

    // cp.async mappings
    const int qr = tid >> 1;              // 0..127
    const int qc = (tid & 1) * 32;        // col base
    const int kr = tid >> 2;              // 0..63
    const int kc = (tid & 3) * 16;        // col base

    const size_t qrow = ((size_t)(t0 + qr) * B_DIM + b) * E_DIM + h * D_HEAD + qc;
    const size_t krowstride = (size_t)B_DIM * E_DIM;
    const size_t kcol0 = (size_t)b * E_DIM + h * D_HEAD + kc;

    const int wrow_min = t0 + wid * 16;
    const int wrow_max = wrow_min + 15;
    const int ntiles = 2 * qtile + 2;     // always >= 2

// always commits (empty group past the end) to keep wait cadence aligned
#define FLASH_ISSUE_KV(stv) do {                                                   \
    if ((stv) < ntiles) {                                                          \
        uint32_t bufb = kvbase + (uint32_t)((stv) % 3) * KVBUF                     \
                      + ((uint32_t)kr * FP + kc) * 2;                              \
        size_t g = (size_t)((stv) * FBS + kr) * krowstride + kcol0;                \
        CP16(bufb,          Kh_g + g); CP16(bufb + 16,          Kh_g + g + 8);     \
        CP16(bufb + KVMATB, Vh_g + g); CP16(bufb + KVMATB + 16, Vh_g + g + 8);     \
    }                                                                              \
    CP_COMMIT();                                                                   \
} while (0)

    // ---- prologue: group0 = {Q, KV0}, group1 = {KV1}
    {
        uint32_t sq = QhB + ((uint32_t)qr * FP + qc) * 2;
#pragma unroll
        for (int u = 0; u < 4; u++)
            CP16(sq + u * 16, Qh_g + qrow + u * 8);
    }
    FLASH_ISSUE_KV(0);                    // commits group 0 (includes Q)
    FLASH_ISSUE_KV(1);                    // commits group 1
    CP_WAIT1();                           // group 0 (Q + KV0) resident
    __syncthreads();

    // ---- Q A-fragments (persist across all s-tiles)
    const int arow  = (lane & 7) + ((lane >> 3) & 1) * 8;
    const int akoff = (lane >> 4) * 8;
    uint32_t qah[4][4];
#pragma unroll
    for (int kcn = 0; kcn < 4; kcn++) {
        uint32_t off = ((uint32_t)(wid * 16 + arow) * FP + kcn * 16 + akoff) * 2;
        LDSM_X4(qah[kcn][0], qah[kcn][1], qah[kcn][2], qah[kcn][3], QhB + off);
    }

    // K (non-trans x4) / V (trans x4) fragment addressing
    const int krow4 = (lane & 7) + ((lane >> 4) & 1) * 8;
    const int kcol4 = ((lane >> 3) & 1) * 8;
    const int vrow  = lane & 15;
    const int vcol  = ((lane >> 4) & 1) * 8;

    float m0 = -1e30f, m1 = -1e30f, l0 = 0.0f, l1 = 0.0f;
    float oacc[8][4];
#pragma unroll
    for (int i = 0; i < 8; i++)
#pragma unroll
        for (int t = 0; t < 4; t++) oacc[i][t] = 0.0f;

    for (int st = 0; st < ntiles; st++) {
        const int s0 = st * FBS;
        FLASH_ISSUE_KV(st + 2);

        if (s0 <= wrow_max) {
            const uint32_t KhB = kvbase + (uint32_t)(st % 3) * KVBUF;
            const uint32_t VhB = KhB + KVMATB;

            // ---- S = Q K^T (scores already in base-2 domain)
            float sacc[8][4];
#pragma unroll
            for (int i = 0; i < 8; i++)
#pragma unroll
                for (int t = 0; t < 4; t++) sacc[i][t] = 0.0f;

#pragma unroll
            for (int ntp = 0; ntp < 4; ntp++) {
#pragma unroll
                for (int kcn = 0; kcn < 4; kcn++) {
                    uint32_t off = ((uint32_t)(ntp * 16 + krow4) * FP + kcn * 16 + kcol4) * 2;
                    uint32_t bh[4];
                    LDSM_X4(bh[0], bh[1], bh[2], bh[3], KhB + off);
                    MMA_F16_P(sacc[2 * ntp],     qah[kcn], bh[0], bh[1]);
                    MMA_F16_P(sacc[2 * ntp + 1], qah[kcn], bh[2], bh[3]);
                }
            }

            // ---- causal mask (whenever tile reaches past warp's first row)
            if (s0 + FBS - 1 > wrow_min) {
                int r0g = wrow_min + (lane >> 2);
                int r1g = r0g + 8;
#pragma unroll
                for (int nt = 0; nt < 8; nt++) {
                    int c0g = s0 + nt * 8 + (lane & 3) * 2;
                    if (c0g     > r0g) sacc[nt][0] = -1e9f;
                    if (c0g + 1 > r0g) sacc[nt][1] = -1e9f;
                    if (c0g     > r1g) sacc[nt][2] = -1e9f;
                    if (c0g + 1 > r1g) sacc[nt][3] = -1e9f;
                }
            }

            // ---- online softmax (base-2, packed fp16 exponentials)
            float rmax0 = -1e30f, rmax1 = -1e30f;
#pragma unroll
            for (int nt = 0; nt < 8; nt++) {
                rmax0 = fmaxf(rmax0, fmaxf(sacc[nt][0], sacc[nt][1]));
                rmax1 = fmaxf(rmax1, fmaxf(sacc[nt][2], sacc[nt][3]));
            }
            rmax0 = fmaxf(rmax0, __shfl_xor_sync(0xffffffffu, rmax0, 1));
            rmax0 = fmaxf(rmax0, __shfl_xor_sync(0xffffffffu, rmax0, 2));
            rmax1 = fmaxf(rmax1, __shfl_xor_sync(0xffffffffu, rmax1, 1));
            rmax1 = fmaxf(rmax1, __shfl_xor_sync(0xffffffffu, rmax1, 2));

            float mn0 = fmaxf(m0, rmax0);
            float mn1 = fmaxf(m1, rmax1);
            float a0 = exp2f(m0 - mn0);
            float a1 = exp2f(m1 - mn1);

            uint32_t pah[4][4];
            uint32_t hs0 = 0, hs1 = 0;    // fp16x2 partial sums
#pragma unroll
            for (int nt = 0; nt < 8; nt++) {
                uint32_t e01 = pack2h(sacc[nt][0] - mn0, sacc[nt][1] - mn0);
                uint32_t e23 = pack2h(sacc[nt][2] - mn1, sacc[nt][3] - mn1);
                uint32_t p01 = exp2_h2(e01);
                uint32_t p23 = exp2_h2(e23);
                int kcn = nt >> 1, half = nt & 1;
                pah[kcn][half * 2 + 0] = p01;
                pah[kcn][half * 2 + 1] = p23;
                hs0 = hadd2u(hs0, p01);
                hs1 = hadd2u(hs1, p23);
            }
            __half2 h0v = *reinterpret_cast<__half2*>(&hs0);
            __half2 h1v = *reinterpret_cast<__half2*>(&hs1);
            float rs0 = __low2float(h0v) + __high2float(h0v);
            float rs1 = __low2float(h1v) + __high2float(h1v);
            rs0 += __shfl_xor_sync(0xffffffffu, rs0, 1);
            rs0 += __shfl_xor_sync(0xffffffffu, rs0, 2);
            rs1 += __shfl_xor_sync(0xffffffffu, rs1, 1);
            rs1 += __shfl_xor_sync(0xffffffffu, rs1, 2);

            l0 = l0 * a0 + rs0;
            l1 = l1 * a1 + rs1;
            m0 = mn0; m1 = mn1;

#pragma unroll
            for (int dt = 0; dt < 8; dt++) {
                oacc[dt][0] *= a0; oacc[dt][1] *= a0;
                oacc[dt][2] *= a1; oacc[dt][3] *= a1;
            }

            // ---- O += P V, V[s][d] via trans x4
#pragma unroll
            for (int dtp = 0; dtp < 4; dtp++) {
#pragma unroll
                for (int kcn = 0; kcn < 4; kcn++) {
                    uint32_t off = ((uint32_t)(kcn * 16 + vrow) * FP + dtp * 16 + vcol) * 2;
                    uint32_t vh[4];
                    LDSM_X4_TRANS(vh[0], vh[1], vh[2], vh[3], VhB + off);
                    MMA_F16_P(oacc[2 * dtp],     pah[kcn], vh[0], vh[1]);
                    MMA_F16_P(oacc[2 * dtp + 1], pah[kcn], vh[2], vh[3]);
                }
            }
        }
        CP_WAIT1();              // group st+1 resident for next iteration
        __syncthreads();         // all warps done with buffer st%3
    }
#undef FLASH_ISSUE_KV

    // ---- normalize + write fp16 (consumed by out-projection GEMM)
    float inv0 = 1.0f / l0;
    float inv1 = 1.0f / l1;
    int r0g = t0 + wid * 16 + (lane >> 2);
    size_t row0 = ((size_t)r0g * B_DIM + b) * E_DIM;
    size_t row1 = ((size_t)(r0g + 8) * B_DIM + b) * E_DIM;
#pragma unroll
    for (int dt = 0; dt < 8; dt++) {
        int col = h * D_HEAD + dt * 8 + (lane & 3) * 2;
        *(uint32_t*)(Oh_g + row0 + col) = pack2h(oacc[dt][0] * inv0, oacc[dt][1] * inv0);
        *(uint32_t*)(Oh_g + row1 + col) = pack2h(oacc[dt][2] * inv1, oacc[dt][3] * inv1);
    }
}

// ============================================================================
extern "C" void kernel_launch(void* const* d_in, const int* in_sizes, int n_in,
                              void* d_out, int out_size)
{
    const float* query = (const float*)d_in[0];
    const float* key   = (const float*)d_in[1];
    const float* value = (const float*)d_in[2];
    // d_in[3] = attn_mask (pure causal; applied analytically)
    const float* wq = (const float*)d_in[4];
    const float* bq = (const float*)d_in[5];
    const float* wk = (const float*)d_in[6];
    const float* bk = (const float*)d_in[7];
    const float* wv = (const float*)d_in[8];
    const float* bv = (const float*)d_in[9];
    const float* wo = (const float*)d_in[10];
    const float* bo = (const float*)d_in[11];
    float* out = (float*)d_out;

    __half *bh, *wh;
    cudaGetSymbolAddress((void**)&bh, g_bh);
    cudaGetSymbolAddress((void**)&wh, g_wh);

    // 1. convert inputs + weights to fp16
    conv_acts_kernel<<<dim3(MROWS * E_DIM / 4 / 256, 1, 3), 256>>>(
        query, key, value, bh);
    conv_w_kernel<<<dim3(E_DIM * E_DIM / 4 / 256, 1, 4), 256>>>(
        wq, wk, wv, wo, wh);

    // 2. merged q/k/v projections (fp16 out, slots 3..5)
    cudaFuncSetAttribute(qkv_gemm_kernel,
                         cudaFuncAttributeMaxDynamicSharedMemorySize, GSMEM_BYTES);
    qkv_gemm_kernel<<<dim3(8, 64, 3), 256, GSMEM_BYTES>>>(
        bh, wh, bq, bk, bv, bh);

    // 3. causal flash attention (reads slots 3..5, writes slot 0)
    cudaFuncSetAttribute(flash_mma_kernel,
                         cudaFuncAttributeMaxDynamicSharedMemorySize, FSMEM_BYTES);
    flash_mma_kernel<<<dim3(B_DIM * H_DIM, T_DIM / FBQ), 256, FSMEM_BYTES>>>(
        bh + 3 * ASLOT, bh + 4 * ASLOT, bh + 5 * ASLOT, bh);

    // 4. output projection (fp32 out)
    cudaFuncSetAttribute(out_gemm_kernel,
                         cudaFuncAttributeMaxDynamicSharedMemorySize, GSMEM_BYTES);
    out_gemm_kernel<<<dim3(8, 64), 256, GSMEM_BYTES>>>(
        bh, wh + 3 * WSLOT, bo, out);
}